// round 1
// baseline (speedup 1.0000x reference)
#include <cuda_runtime.h>
#include <cuda_bf16.h>
#include <math.h>

// Problem constants
#define NTOK   8192      // B*S = 4*2048
#define HID    2048
#define INTER  8192
#define RET    128
#define NKEY   64
#define TOPK   8
#define NEXP   4096

// ---------------------------------------------------------------------------
// Scratch (device globals — no allocation allowed)
// ---------------------------------------------------------------------------
__device__ float g_q[NTOK * RET];          // queries [8192, 128]          4 MB
__device__ float g_scores[NTOK * TOPK];    // combined top-k scores        256 KB
__device__ int   g_idx[NTOK * TOPK];       // expert indices               256 KB
__device__ float g_act[(size_t)NTOK * INTER]; // gate, then silu(gate)*up  256 MB

// ---------------------------------------------------------------------------
// Generic tiled SGEMM: C[M,N] = A[M,K] @ B[K,N], row-major, fp32.
// BM=BN=128, BK=8, 256 threads, 8x8 per-thread microtile.
// EPI 0: C = v
// EPI 1: C = silu(C_old) * v        (up-proj epilogue; C holds gate pre-act)
// EPI 2: C = C_old + v              (down-proj epilogue; C holds experts)
// ---------------------------------------------------------------------------
template <int EPI>
__global__ __launch_bounds__(256) void sgemm128(
    const int M, const int N, const int K,
    const float* __restrict__ A,
    const float* __restrict__ B,
    float* __restrict__ C)
{
    constexpr int BM = 128, BN = 128, BK = 8, TM = 8, TN = 8;
    __shared__ float As[BK][BM];   // transposed A tile
    __shared__ float Bs[BK][BN];

    const int bRow = blockIdx.y;
    const int bCol = blockIdx.x;
    const int tid  = threadIdx.x;
    const int tRow = tid >> 4;        // 0..15
    const int tCol = tid & 15;        // 0..15

    const float* Ab = A + (size_t)bRow * BM * K;
    const float* Bb = B + (size_t)bCol * BN;

    float acc[TM][TN];
    #pragma unroll
    for (int i = 0; i < TM; i++)
        #pragma unroll
        for (int j = 0; j < TN; j++) acc[i][j] = 0.f;

    float regM[TM], regN[TN];

    const int aRow  = tid >> 1;          // 0..127
    const int aCol  = (tid & 1) * 4;     // 0 or 4
    const int bRowi = tid >> 5;          // 0..7
    const int bColi = (tid & 31) * 4;    // 0..124

    for (int k0 = 0; k0 < K; k0 += BK) {
        float4 a = *(const float4*)(Ab + (size_t)aRow * K + k0 + aCol);
        As[aCol + 0][aRow] = a.x;
        As[aCol + 1][aRow] = a.y;
        As[aCol + 2][aRow] = a.z;
        As[aCol + 3][aRow] = a.w;
        *(float4*)(&Bs[bRowi][bColi]) =
            *(const float4*)(Bb + (size_t)(k0 + bRowi) * N + bColi);
        __syncthreads();

        #pragma unroll
        for (int k = 0; k < BK; k++) {
            #pragma unroll
            for (int i = 0; i < TM; i++) regM[i] = As[k][tRow * TM + i];
            #pragma unroll
            for (int j = 0; j < TN; j++) regN[j] = Bs[k][tCol * TN + j];
            #pragma unroll
            for (int i = 0; i < TM; i++)
                #pragma unroll
                for (int j = 0; j < TN; j++)
                    acc[i][j] += regM[i] * regN[j];
        }
        __syncthreads();
    }

    float* Cb = C + (size_t)bRow * BM * N + (size_t)bCol * BN;
    #pragma unroll
    for (int i = 0; i < TM; i++) {
        size_t rowOff = (size_t)(tRow * TM + i) * N + tCol * TN;
        #pragma unroll
        for (int j = 0; j < TN; j += 4) {
            float4 v = make_float4(acc[i][j], acc[i][j+1], acc[i][j+2], acc[i][j+3]);
            if (EPI == 0) {
                *(float4*)(Cb + rowOff + j) = v;
            } else if (EPI == 1) {
                float4 g = *(const float4*)(Cb + rowOff + j);
                v.x = (g.x / (1.f + expf(-g.x))) * v.x;
                v.y = (g.y / (1.f + expf(-g.y))) * v.y;
                v.z = (g.z / (1.f + expf(-g.z))) * v.z;
                v.w = (g.w / (1.f + expf(-g.w))) * v.w;
                *(float4*)(Cb + rowOff + j) = v;
            } else {
                float4 o = *(const float4*)(Cb + rowOff + j);
                v.x += o.x; v.y += o.y; v.z += o.z; v.w += o.w;
                *(float4*)(Cb + rowOff + j) = v;
            }
        }
    }
}

// ---------------------------------------------------------------------------
// Product-key routing + two-level top-k.
// One block per routing row j (8192 rows), 64 threads.
// Row j of half t uses token tok = t*4096 + j/2, query cols [(j&1)*64, +64).
// ---------------------------------------------------------------------------
__global__ void routing_topk_kernel(
    const float* __restrict__ Q,       // [8192, 128]
    const float* __restrict__ keys,    // [2, 64, 64]
    float* __restrict__ out_scores,    // [8192, 8]
    int*   __restrict__ out_idx)       // [8192, 8]
{
    const int j = blockIdx.x;
    const int t = threadIdx.x;   // 0..63 == key index k
    __shared__ float q0[64], q1[64];
    __shared__ float r0[64], r1[64];
    __shared__ float cs[64];
    __shared__ int   ci[64];

    const int half = j & 1;
    const int tokA = (j >> 1);          // t = 0 half
    const int tokB = 4096 + (j >> 1);   // t = 1 half
    q0[t] = Q[tokA * RET + half * 64 + t];
    q1[t] = Q[tokB * RET + half * 64 + t];
    __syncthreads();

    float s0 = 0.f, s1 = 0.f;
    #pragma unroll
    for (int d = 0; d < 64; d++) {
        s0 += q0[d] * keys[d * 64 + t];
        s1 += q1[d] * keys[4096 + d * 64 + t];
    }
    r0[t] = s0;
    r1[t] = s1;
    __syncthreads();

    if (t == 0) {
        float v0[TOPK], v1[TOPK];
        int   i0[TOPK], i1[TOPK];
        unsigned long long u0 = 0ull, u1 = 0ull;
        for (int p = 0; p < TOPK; p++) {
            float best = -INFINITY; int bi = 0;
            for (int k = 0; k < 64; k++)
                if (!((u0 >> k) & 1ull) && r0[k] > best) { best = r0[k]; bi = k; }
            v0[p] = best; i0[p] = bi; u0 |= 1ull << bi;
            best = -INFINITY; bi = 0;
            for (int k = 0; k < 64; k++)
                if (!((u1 >> k) & 1ull) && r1[k] > best) { best = r1[k]; bi = k; }
            v1[p] = best; i1[p] = bi; u1 |= 1ull << bi;
        }
        for (int a = 0; a < TOPK; a++)
            for (int b = 0; b < TOPK; b++) {
                cs[a * TOPK + b] = v0[a] + v1[b];
                ci[a * TOPK + b] = i0[a] * NKEY + i1[b];
            }
        unsigned long long uc = 0ull;
        for (int p = 0; p < TOPK; p++) {
            float best = -INFINITY; int bi = 0;
            for (int q = 0; q < 64; q++)
                if (!((uc >> q) & 1ull) && cs[q] > best) { best = cs[q]; bi = q; }
            out_scores[j * TOPK + p] = best;
            out_idx[j * TOPK + p]    = ci[bi];
            uc |= 1ull << bi;
        }
    }
}

// ---------------------------------------------------------------------------
// Expert branch: per token, 8 gathered dot products + silu*softmax gate +
// weighted sum of up_embed rows. One block per token, 256 threads (8 warps,
// one warp per expert for the dot phase).
// ---------------------------------------------------------------------------
__global__ __launch_bounds__(256) void experts_kernel(
    const float* __restrict__ X,        // [8192, 2048]
    const float* __restrict__ down_e,   // [4096, 2048]
    const float* __restrict__ up_e,     // [4096, 2048]
    const float* __restrict__ scores,   // [8192, 8]
    const int*   __restrict__ idx,      // [8192, 8]
    float* __restrict__ out)            // [8192, 2048]
{
    const int j    = blockIdx.x;
    const int tid  = threadIdx.x;
    const int wid  = tid >> 5;
    const int lane = tid & 31;

    __shared__ float xs[HID];
    __shared__ float ew[TOPK];
    __shared__ float w[TOPK];

    // load x row (vectorized)
    for (int h4 = tid; h4 < HID / 4; h4 += 256)
        *(float4*)(&xs[h4 * 4]) = *(const float4*)(X + (size_t)j * HID + h4 * 4);
    __syncthreads();

    // one warp per expert: dot(x, down_embed[e])
    {
        const int e = idx[j * TOPK + wid];
        const float* de = down_e + (size_t)e * HID;
        float s = 0.f;
        for (int h = lane * 4; h < HID; h += 32 * 4) {
            float4 d = *(const float4*)(de + h);
            s += xs[h] * d.x + xs[h+1] * d.y + xs[h+2] * d.z + xs[h+3] * d.w;
        }
        #pragma unroll
        for (int o = 16; o; o >>= 1) s += __shfl_xor_sync(0xffffffffu, s, o);
        if (lane == 0) ew[wid] = s;
    }
    __syncthreads();

    if (tid == 0) {
        float sc[TOPK], m = -INFINITY;
        #pragma unroll
        for (int k = 0; k < TOPK; k++) { sc[k] = scores[j * TOPK + k]; m = fmaxf(m, sc[k]); }
        float den = 0.f;
        #pragma unroll
        for (int k = 0; k < TOPK; k++) { sc[k] = expf(sc[k] - m); den += sc[k]; }
        #pragma unroll
        for (int k = 0; k < TOPK; k++) {
            float e_ = ew[k];
            float silu = e_ / (1.f + expf(-e_));
            w[k] = silu * sc[k] / den;
        }
    }
    __syncthreads();

    int   eidx[TOPK];
    float wk[TOPK];
    #pragma unroll
    for (int k = 0; k < TOPK; k++) { eidx[k] = idx[j * TOPK + k]; wk[k] = w[k]; }

    for (int h = tid * 4; h < HID; h += 256 * 4) {
        float4 acc = make_float4(0.f, 0.f, 0.f, 0.f);
        #pragma unroll
        for (int k = 0; k < TOPK; k++) {
            float4 u = *(const float4*)(up_e + (size_t)eidx[k] * HID + h);
            acc.x += wk[k] * u.x; acc.y += wk[k] * u.y;
            acc.z += wk[k] * u.z; acc.w += wk[k] * u.w;
        }
        *(float4*)(out + (size_t)j * HID + h) = acc;
    }
}

// ---------------------------------------------------------------------------
// Launch
// ---------------------------------------------------------------------------
extern "C" void kernel_launch(void* const* d_in, const int* in_sizes, int n_in,
                              void* d_out, int out_size)
{
    const float* x      = (const float*)d_in[0];  // [4,2048,2048]
    const float* wq     = (const float*)d_in[1];  // [2048,128]
    const float* keys   = (const float*)d_in[2];  // [2,64,64]
    const float* down_e = (const float*)d_in[3];  // [4096,2048]
    const float* up_e   = (const float*)d_in[4];  // [4096,2048]
    const float* gate_w = (const float*)d_in[5];  // [2048,8192]
    const float* up_w   = (const float*)d_in[6];  // [2048,8192]
    const float* down_w = (const float*)d_in[7];  // [8192,2048]
    float* out = (float*)d_out;                   // [4,2048,2048]

    float *q_ptr, *scr_ptr, *act_ptr;
    int   *idx_ptr;
    cudaGetSymbolAddress((void**)&q_ptr,   g_q);
    cudaGetSymbolAddress((void**)&scr_ptr, g_scores);
    cudaGetSymbolAddress((void**)&idx_ptr, g_idx);
    cudaGetSymbolAddress((void**)&act_ptr, g_act);

    // 1) queries = X @ W_q   [8192,128]
    sgemm128<0><<<dim3(RET / 128, NTOK / 128), 256>>>(NTOK, RET, HID, x, wq, q_ptr);

    // 2) routing + two-level top-k
    routing_topk_kernel<<<NTOK, 64>>>(q_ptr, keys, scr_ptr, idx_ptr);

    // 3) expert branch -> writes experts_states into d_out
    experts_kernel<<<NTOK, 256>>>(x, down_e, up_e, scr_ptr, idx_ptr, out);

    // 4) gate = X @ gate_w -> g_act
    sgemm128<0><<<dim3(INTER / 128, NTOK / 128), 256>>>(NTOK, INTER, HID, x, gate_w, act_ptr);

    // 5) up = X @ up_w; g_act = silu(g_act) * up
    sgemm128<1><<<dim3(INTER / 128, NTOK / 128), 256>>>(NTOK, INTER, HID, x, up_w, act_ptr);

    // 6) out += g_act @ down_w
    sgemm128<2><<<dim3(HID / 128, NTOK / 128), 256>>>(NTOK, HID, INTER, act_ptr, down_w, out);
}

// round 2
// speedup vs baseline: 1.1196x; 1.1196x over previous
#include <cuda_runtime.h>
#include <cuda_bf16.h>
#include <math.h>

// Problem constants
#define NTOK   8192
#define HID    2048
#define INTER  8192
#define RET    128
#define NKEY   64
#define TOPK   8
#define NEXP   4096

// ---------------------------------------------------------------------------
// Scratch (device globals — no allocation allowed)
// ---------------------------------------------------------------------------
__device__ float g_q[NTOK * RET];
__device__ float g_scores[NTOK * TOPK];
__device__ int   g_idx[NTOK * TOPK];
__device__ float g_act[(size_t)NTOK * INTER];

// ---------------------------------------------------------------------------
// f32x2 helpers (Blackwell packed fp32)
// ---------------------------------------------------------------------------
__device__ __forceinline__ unsigned long long pack_dup(float a) {
    unsigned long long r;
    asm("mov.b64 %0, {%1, %1};" : "=l"(r) : "f"(a));
    return r;
}
__device__ __forceinline__ void ffma2(unsigned long long& d,
                                      unsigned long long a,
                                      unsigned long long b) {
    asm("fma.rn.f32x2 %0, %1, %2, %0;" : "+l"(d) : "l"(a), "l"(b));
}
__device__ __forceinline__ float2 unpack2(unsigned long long v) {
    float2 f;
    asm("mov.b64 {%0, %1}, %2;" : "=f"(f.x), "=f"(f.y) : "l"(v));
    return f;
}

// ---------------------------------------------------------------------------
// Tiled SGEMM with f32x2 inner loop + cp.async double buffering.
// C[M,N] = A[M,K] @ B[K,N], row-major fp32. BM=BN=128, BK=8, 256 thr, 8x8.
// EPI 0: C = v ; EPI 1: C = silu(C_old)*v ; EPI 2: C = C_old + v
// ---------------------------------------------------------------------------
template <int EPI>
__global__ __launch_bounds__(256, 2) void sgemm2(
    const int M, const int N, const int K,
    const float* __restrict__ A,
    const float* __restrict__ B,
    float* __restrict__ C)
{
    constexpr int BM = 128, BN = 128, BK = 8;
    __shared__ __align__(16) float As[2][BK][BM];   // transposed A tiles
    __shared__ __align__(16) float Bs[2][BK][BN];

    const int tid  = threadIdx.x;
    const int tRow = tid >> 4;          // 0..15
    const int tCol = tid & 15;          // 0..15
    const int bRow = blockIdx.y;
    const int bCol = blockIdx.x;

    const int aRow  = tid >> 1;         // 0..127
    const int aCol  = (tid & 1) * 4;    // 0 or 4
    const int bRowi = tid >> 5;         // 0..7
    const int bColi = (tid & 31) * 4;   // 0..124

    const float* Ag = A + (size_t)(bRow * BM + aRow) * K + aCol;
    const float* Bg = B + (size_t)bRowi * N + (size_t)bCol * BN + bColi;

    unsigned long long acc[8][4];
    #pragma unroll
    for (int i = 0; i < 8; i++)
        #pragma unroll
        for (int j = 0; j < 4; j++) acc[i][j] = 0ull;

    // ---- prologue: tile 0 ----
    {
        float4 a0 = *(const float4*)Ag;
        unsigned bdst = (unsigned)__cvta_generic_to_shared(&Bs[0][bRowi][bColi]);
        asm volatile("cp.async.cg.shared.global [%0], [%1], 16;\n" :: "r"(bdst), "l"(Bg));
        asm volatile("cp.async.commit_group;\n");
        As[0][aCol + 0][aRow] = a0.x;
        As[0][aCol + 1][aRow] = a0.y;
        As[0][aCol + 2][aRow] = a0.z;
        As[0][aCol + 3][aRow] = a0.w;
        asm volatile("cp.async.wait_group 0;\n");
    }
    __syncthreads();

    const int NKB = K / BK;
    for (int kb = 0; kb < NKB; kb++) {
        const int buf = kb & 1;
        float4 an;
        if (kb + 1 < NKB) {
            an = *(const float4*)(Ag + (size_t)(kb + 1) * BK);
            unsigned bdst = (unsigned)__cvta_generic_to_shared(&Bs[buf ^ 1][bRowi][bColi]);
            const float* bsrc = Bg + (size_t)(kb + 1) * BK * N;
            asm volatile("cp.async.cg.shared.global [%0], [%1], 16;\n" :: "r"(bdst), "l"(bsrc));
            asm volatile("cp.async.commit_group;\n");
        }
        #pragma unroll
        for (int k = 0; k < BK; k++) {
            ulonglong2 n01 = *(const ulonglong2*)(&Bs[buf][k][tCol * 8]);
            ulonglong2 n23 = *(const ulonglong2*)(&Bs[buf][k][tCol * 8 + 4]);
            float4 m0 = *(const float4*)(&As[buf][k][tRow * 8]);
            float4 m1 = *(const float4*)(&As[buf][k][tRow * 8 + 4]);
            float mr[8] = {m0.x, m0.y, m0.z, m0.w, m1.x, m1.y, m1.z, m1.w};
            #pragma unroll
            for (int i = 0; i < 8; i++) {
                unsigned long long mm = pack_dup(mr[i]);
                ffma2(acc[i][0], mm, n01.x);
                ffma2(acc[i][1], mm, n01.y);
                ffma2(acc[i][2], mm, n23.x);
                ffma2(acc[i][3], mm, n23.y);
            }
        }
        if (kb + 1 < NKB) {
            As[buf ^ 1][aCol + 0][aRow] = an.x;
            As[buf ^ 1][aCol + 1][aRow] = an.y;
            As[buf ^ 1][aCol + 2][aRow] = an.z;
            As[buf ^ 1][aCol + 3][aRow] = an.w;
            asm volatile("cp.async.wait_group 0;\n");
        }
        __syncthreads();
    }

    // ---- epilogue ----
    float* Cb = C + (size_t)bRow * BM * N + (size_t)bCol * BN;
    #pragma unroll
    for (int i = 0; i < 8; i++) {
        size_t rowOff = (size_t)(tRow * 8 + i) * N + tCol * 8;
        float v[8];
        #pragma unroll
        for (int j2 = 0; j2 < 4; j2++) {
            float2 p = unpack2(acc[i][j2]);
            v[2 * j2] = p.x; v[2 * j2 + 1] = p.y;
        }
        #pragma unroll
        for (int j = 0; j < 8; j += 4) {
            float4 w = make_float4(v[j], v[j+1], v[j+2], v[j+3]);
            if (EPI == 0) {
                *(float4*)(Cb + rowOff + j) = w;
            } else if (EPI == 1) {
                float4 g = *(const float4*)(Cb + rowOff + j);
                w.x = (g.x / (1.f + expf(-g.x))) * w.x;
                w.y = (g.y / (1.f + expf(-g.y))) * w.y;
                w.z = (g.z / (1.f + expf(-g.z))) * w.z;
                w.w = (g.w / (1.f + expf(-g.w))) * w.w;
                *(float4*)(Cb + rowOff + j) = w;
            } else {
                float4 o = *(const float4*)(Cb + rowOff + j);
                w.x += o.x; w.y += o.y; w.z += o.z; w.w += o.w;
                *(float4*)(Cb + rowOff + j) = w;
            }
        }
    }
}

// ---------------------------------------------------------------------------
// Product-key routing + two-level top-k (unchanged, correct & cheap)
// ---------------------------------------------------------------------------
__global__ void routing_topk_kernel(
    const float* __restrict__ Q,
    const float* __restrict__ keys,
    float* __restrict__ out_scores,
    int*   __restrict__ out_idx)
{
    const int j = blockIdx.x;
    const int t = threadIdx.x;
    __shared__ float q0[64], q1[64];
    __shared__ float r0[64], r1[64];
    __shared__ float cs[64];
    __shared__ int   ci[64];

    const int half = j & 1;
    const int tokA = (j >> 1);
    const int tokB = 4096 + (j >> 1);
    q0[t] = Q[tokA * RET + half * 64 + t];
    q1[t] = Q[tokB * RET + half * 64 + t];
    __syncthreads();

    float s0 = 0.f, s1 = 0.f;
    #pragma unroll
    for (int d = 0; d < 64; d++) {
        s0 += q0[d] * keys[d * 64 + t];
        s1 += q1[d] * keys[4096 + d * 64 + t];
    }
    r0[t] = s0;
    r1[t] = s1;
    __syncthreads();

    if (t == 0) {
        float v0[TOPK], v1[TOPK];
        int   i0[TOPK], i1[TOPK];
        unsigned long long u0 = 0ull, u1 = 0ull;
        for (int p = 0; p < TOPK; p++) {
            float best = -INFINITY; int bi = 0;
            for (int k = 0; k < 64; k++)
                if (!((u0 >> k) & 1ull) && r0[k] > best) { best = r0[k]; bi = k; }
            v0[p] = best; i0[p] = bi; u0 |= 1ull << bi;
            best = -INFINITY; bi = 0;
            for (int k = 0; k < 64; k++)
                if (!((u1 >> k) & 1ull) && r1[k] > best) { best = r1[k]; bi = k; }
            v1[p] = best; i1[p] = bi; u1 |= 1ull << bi;
        }
        for (int a = 0; a < TOPK; a++)
            for (int b = 0; b < TOPK; b++) {
                cs[a * TOPK + b] = v0[a] + v1[b];
                ci[a * TOPK + b] = i0[a] * NKEY + i1[b];
            }
        unsigned long long uc = 0ull;
        for (int p = 0; p < TOPK; p++) {
            float best = -INFINITY; int bi = 0;
            for (int q = 0; q < 64; q++)
                if (!((uc >> q) & 1ull) && cs[q] > best) { best = cs[q]; bi = q; }
            out_scores[j * TOPK + p] = best;
            out_idx[j * TOPK + p]    = ci[bi];
            uc |= 1ull << bi;
        }
    }
}

// ---------------------------------------------------------------------------
// Expert branch (unchanged)
// ---------------------------------------------------------------------------
__global__ __launch_bounds__(256) void experts_kernel(
    const float* __restrict__ X,
    const float* __restrict__ down_e,
    const float* __restrict__ up_e,
    const float* __restrict__ scores,
    const int*   __restrict__ idx,
    float* __restrict__ out)
{
    const int j    = blockIdx.x;
    const int tid  = threadIdx.x;
    const int wid  = tid >> 5;
    const int lane = tid & 31;

    __shared__ float xs[HID];
    __shared__ float ew[TOPK];
    __shared__ float w[TOPK];

    for (int h4 = tid; h4 < HID / 4; h4 += 256)
        *(float4*)(&xs[h4 * 4]) = *(const float4*)(X + (size_t)j * HID + h4 * 4);
    __syncthreads();

    {
        const int e = idx[j * TOPK + wid];
        const float* de = down_e + (size_t)e * HID;
        float s = 0.f;
        for (int h = lane * 4; h < HID; h += 32 * 4) {
            float4 d = *(const float4*)(de + h);
            s += xs[h] * d.x + xs[h+1] * d.y + xs[h+2] * d.z + xs[h+3] * d.w;
        }
        #pragma unroll
        for (int o = 16; o; o >>= 1) s += __shfl_xor_sync(0xffffffffu, s, o);
        if (lane == 0) ew[wid] = s;
    }
    __syncthreads();

    if (tid == 0) {
        float sc[TOPK], m = -INFINITY;
        #pragma unroll
        for (int k = 0; k < TOPK; k++) { sc[k] = scores[j * TOPK + k]; m = fmaxf(m, sc[k]); }
        float den = 0.f;
        #pragma unroll
        for (int k = 0; k < TOPK; k++) { sc[k] = expf(sc[k] - m); den += sc[k]; }
        #pragma unroll
        for (int k = 0; k < TOPK; k++) {
            float e_ = ew[k];
            float silu = e_ / (1.f + expf(-e_));
            w[k] = silu * sc[k] / den;
        }
    }
    __syncthreads();

    int   eidx[TOPK];
    float wk[TOPK];
    #pragma unroll
    for (int k = 0; k < TOPK; k++) { eidx[k] = idx[j * TOPK + k]; wk[k] = w[k]; }

    for (int h = tid * 4; h < HID; h += 256 * 4) {
        float4 acc = make_float4(0.f, 0.f, 0.f, 0.f);
        #pragma unroll
        for (int k = 0; k < TOPK; k++) {
            float4 u = *(const float4*)(up_e + (size_t)eidx[k] * HID + h);
            acc.x += wk[k] * u.x; acc.y += wk[k] * u.y;
            acc.z += wk[k] * u.z; acc.w += wk[k] * u.w;
        }
        *(float4*)(out + (size_t)j * HID + h) = acc;
    }
}

// ---------------------------------------------------------------------------
// Launch
// ---------------------------------------------------------------------------
extern "C" void kernel_launch(void* const* d_in, const int* in_sizes, int n_in,
                              void* d_out, int out_size)
{
    const float* x      = (const float*)d_in[0];
    const float* wq     = (const float*)d_in[1];
    const float* keys   = (const float*)d_in[2];
    const float* down_e = (const float*)d_in[3];
    const float* up_e   = (const float*)d_in[4];
    const float* gate_w = (const float*)d_in[5];
    const float* up_w   = (const float*)d_in[6];
    const float* down_w = (const float*)d_in[7];
    float* out = (float*)d_out;

    float *q_ptr, *scr_ptr, *act_ptr;
    int   *idx_ptr;
    cudaGetSymbolAddress((void**)&q_ptr,   g_q);
    cudaGetSymbolAddress((void**)&scr_ptr, g_scores);
    cudaGetSymbolAddress((void**)&idx_ptr, g_idx);
    cudaGetSymbolAddress((void**)&act_ptr, g_act);

    // 1) queries = X @ W_q
    sgemm2<0><<<dim3(RET / 128, NTOK / 128), 256>>>(NTOK, RET, HID, x, wq, q_ptr);

    // 2) routing + two-level top-k
    routing_topk_kernel<<<NTOK, 64>>>(q_ptr, keys, scr_ptr, idx_ptr);

    // 3) expert branch -> d_out
    experts_kernel<<<NTOK, 256>>>(x, down_e, up_e, scr_ptr, idx_ptr, out);

    // 4) gate = X @ gate_w
    sgemm2<0><<<dim3(INTER / 128, NTOK / 128), 256>>>(NTOK, INTER, HID, x, gate_w, act_ptr);

    // 5) up = X @ up_w; g_act = silu(gate) * up
    sgemm2<1><<<dim3(INTER / 128, NTOK / 128), 256>>>(NTOK, INTER, HID, x, up_w, act_ptr);

    // 6) out += g_act @ down_w
    sgemm2<2><<<dim3(HID / 128, NTOK / 128), 256>>>(NTOK, HID, INTER, act_ptr, down_w, out);
}

// round 5
// speedup vs baseline: 3.1216x; 2.7882x over previous
#include <cuda_runtime.h>
#include <cuda_bf16.h>
#include <math.h>
#include <stdint.h>

// Problem constants
#define NTOK   8192
#define HID    2048
#define INTER  8192
#define RET    128
#define NKEY   64
#define TOPK   8
#define NEXP   4096

// ---------------------------------------------------------------------------
// Scratch (device globals — no allocation allowed)
// ---------------------------------------------------------------------------
__device__ float g_q[NTOK * RET];
__device__ float g_scores[NTOK * TOPK];
__device__ int   g_idx[NTOK * TOPK];
__device__ float g_gate[(size_t)NTOK * INTER];              // 256 MB fp32
__device__ __nv_bfloat16 g_xh[(size_t)NTOK * HID];
__device__ __nv_bfloat16 g_xl[(size_t)NTOK * HID];
__device__ __nv_bfloat16 g_gwh[(size_t)INTER * HID];        // gate_w^T [8192,2048]
__device__ __nv_bfloat16 g_gwl[(size_t)INTER * HID];
__device__ __nv_bfloat16 g_uwh[(size_t)INTER * HID];
__device__ __nv_bfloat16 g_uwl[(size_t)INTER * HID];
__device__ __nv_bfloat16 g_dwh[(size_t)HID * INTER];        // down_w^T [2048,8192]
__device__ __nv_bfloat16 g_dwl[(size_t)HID * INTER];
__device__ __nv_bfloat16 g_acth[(size_t)NTOK * INTER];
__device__ __nv_bfloat16 g_actl[(size_t)NTOK * INTER];

// ---------------------------------------------------------------------------
// PTX helpers (base-target only: ldmatrix / mma.sync / cp.async)
// ---------------------------------------------------------------------------
__device__ __forceinline__ void cpasync16(uint32_t dst, const void* src) {
    asm volatile("cp.async.cg.shared.global [%0], [%1], 16;" :: "r"(dst), "l"(src));
}
__device__ __forceinline__ void ldsm4(uint32_t* r, uint32_t addr) {
    asm volatile("ldmatrix.sync.aligned.m8n8.x4.shared.b16 {%0,%1,%2,%3}, [%4];"
                 : "=r"(r[0]), "=r"(r[1]), "=r"(r[2]), "=r"(r[3]) : "r"(addr));
}
__device__ __forceinline__ void mma16816(float* c, const uint32_t* a, const uint32_t* b) {
    asm volatile(
        "mma.sync.aligned.m16n8k16.row.col.f32.bf16.bf16.f32 "
        "{%0,%1,%2,%3}, {%4,%5,%6,%7}, {%8,%9}, {%0,%1,%2,%3};"
        : "+f"(c[0]), "+f"(c[1]), "+f"(c[2]), "+f"(c[3])
        : "r"(a[0]), "r"(a[1]), "r"(a[2]), "r"(a[3]), "r"(b[0]), "r"(b[1]));
}

// ---------------------------------------------------------------------------
// Split-bf16 HMMA GEMM: C[M,N] = A[M,K] @ B[N,K]^T, A=Ah+Al, B=Bh+Bl.
// Terms: AhBh + AhBl + AlBh, fp32 accumulate.
// BM=BN=128, BK=64. 256 threads = 8 warps (4x2), warp tile 32x64.
// EPI 0: C = v ; EPI 1: y = silu(gate)*v -> Oh/Ol bf16 split ; EPI 2: C += v
// ---------------------------------------------------------------------------
#define STG_BYTES 65536          // 4 tiles x 128x64 bf16 (16KB each)
#define GEMM_SMEM (2 * STG_BYTES)

template <int EPI>
__global__ __launch_bounds__(256, 1) void gemm_mma(
    const int M, const int N, const int K,
    const __nv_bfloat16* __restrict__ Ah, const __nv_bfloat16* __restrict__ Al,
    const __nv_bfloat16* __restrict__ Bh, const __nv_bfloat16* __restrict__ Bl,
    float* __restrict__ C,
    const float* __restrict__ gateC,
    __nv_bfloat16* __restrict__ Oh, __nv_bfloat16* __restrict__ Ol)
{
    extern __shared__ __align__(128) char dynsmem[];
    const int tid  = threadIdx.x;
    const int lane = tid & 31;
    const int wid  = tid >> 5;
    const int wm   = wid >> 1;          // 0..3
    const int wn   = wid & 1;           // 0..1
    const int bN   = blockIdx.x;
    const int bM   = blockIdx.y;

    uint32_t sbase;
    asm("{ .reg .u64 t; cvta.to.shared.u64 t, %1; cvt.u32.u64 %0, t; }"
        : "=r"(sbase) : "l"(dynsmem));

    const int rowA = bM * 128;
    const int rowB = bN * 128;
    const int NKB  = K / 64;

    // ---- stage loader: Ah, Al, Bh, Bl tiles of [128 rows x 64 bf16] ----
    auto load_stage = [&](uint32_t db0, int kk) {
        #pragma unroll
        for (int t = 0; t < 4; t++) {
            const __nv_bfloat16* P =
                (t == 0 ? Ah : t == 1 ? Al : t == 2 ? Bh : Bl)
                + (size_t)(t < 2 ? rowA : rowB) * K + kk;
            const uint32_t db = db0 + t * 16384;
            #pragma unroll
            for (int i = 0; i < 4; i++) {
                int ch = i * 256 + tid;
                int r  = ch >> 3, c = ch & 7;
                uint32_t off = (uint32_t)(r * 128 + c * 16);
                off ^= (uint32_t)((r & 7) << 4);
                cpasync16(db + off, (const char*)(P + (size_t)r * K) + c * 16);
            }
        }
        asm volatile("cp.async.commit_group;" ::: "memory");
    };

    // ---- ldmatrix lane offsets (raw byte offset within tile + swizzle mask)
    // A-frag (m16k16): row = wm*32 + mi*16 + (lane&15), colByte = (lane>>4)*16
    uint32_t rawA[2], xA[2];
    #pragma unroll
    for (int mi = 0; mi < 2; mi++) {
        uint32_t r = (uint32_t)(wm * 32 + mi * 16 + (lane & 15));
        rawA[mi] = r * 128 + ((lane >> 4) * 16);
        xA[mi]   = (rawA[mi] >> 3) & 0x70;
    }
    // B-frag (n16k16): row = wn*64 + g*16 + (lane&7) + ((lane>>4)*8),
    //                  colByte = ((lane>>3)&1)*16
    uint32_t rawB[4], xB[4];
    #pragma unroll
    for (int g = 0; g < 4; g++) {
        uint32_t r = (uint32_t)(wn * 64 + g * 16 + (lane & 7) + ((lane >> 4) << 3));
        rawB[g] = r * 128 + (((lane >> 3) & 1) * 16);
        xB[g]   = (rawB[g] >> 3) & 0x70;
    }

    float acc[2][8][4];
    #pragma unroll
    for (int i = 0; i < 2; i++)
        #pragma unroll
        for (int j = 0; j < 8; j++)
            #pragma unroll
            for (int q = 0; q < 4; q++) acc[i][j][q] = 0.f;

    // prologue
    load_stage(sbase, 0);
    asm volatile("cp.async.wait_group 0;" ::: "memory");
    __syncthreads();

    for (int kb = 0; kb < NKB; kb++) {
        const uint32_t cur = sbase + (uint32_t)(kb & 1) * STG_BYTES;
        if (kb + 1 < NKB)
            load_stage(sbase + (uint32_t)((kb + 1) & 1) * STG_BYTES, (kb + 1) * 64);

        #pragma unroll
        for (int ks = 0; ks < 4; ks++) {
            uint32_t aH[2][4], aL[2][4], bH[4][4], bL[4][4];
            #pragma unroll
            for (int mi = 0; mi < 2; mi++) {
                uint32_t o = (rawA[mi] + ks * 32) ^ xA[mi];
                ldsm4(aH[mi], cur + o);
                ldsm4(aL[mi], cur + 16384 + o);
            }
            #pragma unroll
            for (int g = 0; g < 4; g++) {
                uint32_t o = (rawB[g] + ks * 32) ^ xB[g];
                ldsm4(bH[g], cur + 32768 + o);
                ldsm4(bL[g], cur + 49152 + o);
            }
            #pragma unroll
            for (int mi = 0; mi < 2; mi++)
                #pragma unroll
                for (int g = 0; g < 4; g++)
                    #pragma unroll
                    for (int h = 0; h < 2; h++) {
                        float* c = acc[mi][g * 2 + h];
                        mma16816(c, aH[mi], &bH[g][h * 2]);
                        mma16816(c, aH[mi], &bL[g][h * 2]);
                        mma16816(c, aL[mi], &bH[g][h * 2]);
                    }
        }
        if (kb + 1 < NKB)
            asm volatile("cp.async.wait_group 0;" ::: "memory");
        __syncthreads();
    }

    // ---- epilogue (register accumulators -> gmem) ----
    const int baseM = rowA + wm * 32;
    const int baseN = rowB + wn * 64;
    const int rOff  = lane >> 2;
    const int cOff  = (lane & 3) * 2;

    #pragma unroll
    for (int mi = 0; mi < 2; mi++) {
        #pragma unroll
        for (int nf = 0; nf < 8; nf++) {
            const int cc = baseN + nf * 8 + cOff;
            #pragma unroll
            for (int half = 0; half < 2; half++) {
                const int rr = baseM + mi * 16 + rOff + half * 8;
                const size_t pos = (size_t)rr * N + cc;
                float v0 = acc[mi][nf][half * 2 + 0];
                float v1 = acc[mi][nf][half * 2 + 1];
                if (EPI == 0) {
                    *(float2*)(C + pos) = make_float2(v0, v1);
                } else if (EPI == 1) {
                    float2 gg = *(const float2*)(gateC + pos);
                    float y0 = (gg.x / (1.f + expf(-gg.x))) * v0;
                    float y1 = (gg.y / (1.f + expf(-gg.y))) * v1;
                    __nv_bfloat16 h0 = __float2bfloat16_rn(y0);
                    __nv_bfloat16 h1 = __float2bfloat16_rn(y1);
                    __nv_bfloat16 l0 = __float2bfloat16_rn(y0 - __bfloat162float(h0));
                    __nv_bfloat16 l1 = __float2bfloat16_rn(y1 - __bfloat162float(h1));
                    *(__nv_bfloat162*)(Oh + pos) = __halves2bfloat162(h0, h1);
                    *(__nv_bfloat162*)(Ol + pos) = __halves2bfloat162(l0, l1);
                } else {
                    float2 o = *(const float2*)(C + pos);
                    o.x += v0; o.y += v1;
                    *(float2*)(C + pos) = o;
                }
            }
        }
    }
}

// ---------------------------------------------------------------------------
// Conversion: fp32 -> bf16 hi/lo (no transpose)
// ---------------------------------------------------------------------------
__global__ void conv_split(const float* __restrict__ in,
                           __nv_bfloat16* __restrict__ oh,
                           __nv_bfloat16* __restrict__ ol, size_t n4)
{
    size_t i = (size_t)blockIdx.x * blockDim.x + threadIdx.x;
    if (i >= n4) return;
    float4 v = *(const float4*)(in + i * 4);
    float f[4] = {v.x, v.y, v.z, v.w};
    __nv_bfloat16 h[4], l[4];
    #pragma unroll
    for (int q = 0; q < 4; q++) {
        h[q] = __float2bfloat16_rn(f[q]);
        l[q] = __float2bfloat16_rn(f[q] - __bfloat162float(h[q]));
    }
    *(__nv_bfloat162*)(oh + i * 4)     = __halves2bfloat162(h[0], h[1]);
    *(__nv_bfloat162*)(oh + i * 4 + 2) = __halves2bfloat162(h[2], h[3]);
    *(__nv_bfloat162*)(ol + i * 4)     = __halves2bfloat162(l[0], l[1]);
    *(__nv_bfloat162*)(ol + i * 4 + 2) = __halves2bfloat162(l[2], l[3]);
}

// ---------------------------------------------------------------------------
// Transpose + split: in fp32 [R,C] -> out bf16 [C,R] hi/lo
// ---------------------------------------------------------------------------
__global__ void tconv_split(const float* __restrict__ in,
                            __nv_bfloat16* __restrict__ oh,
                            __nv_bfloat16* __restrict__ ol, int R, int C)
{
    __shared__ float t[32][33];
    const int c0 = blockIdx.x * 32, r0 = blockIdx.y * 32;
    const int tx = threadIdx.x, ty = threadIdx.y;
    #pragma unroll
    for (int i = 0; i < 4; i++)
        t[ty + i * 8][tx] = in[(size_t)(r0 + ty + i * 8) * C + c0 + tx];
    __syncthreads();
    #pragma unroll
    for (int i = 0; i < 4; i++) {
        float v = t[tx][ty + i * 8];
        __nv_bfloat16 h = __float2bfloat16_rn(v);
        __nv_bfloat16 l = __float2bfloat16_rn(v - __bfloat162float(h));
        size_t o = (size_t)(c0 + ty + i * 8) * R + r0 + tx;
        oh[o] = h;
        ol[o] = l;
    }
}

// ---------------------------------------------------------------------------
// f32x2 helpers + fp32 SGEMM for the Q projection
// ---------------------------------------------------------------------------
__device__ __forceinline__ unsigned long long pack_dup(float a) {
    unsigned long long r;
    asm("mov.b64 %0, {%1, %1};" : "=l"(r) : "f"(a));
    return r;
}
__device__ __forceinline__ void ffma2(unsigned long long& d, unsigned long long a,
                                      unsigned long long b) {
    asm("fma.rn.f32x2 %0, %1, %2, %0;" : "+l"(d) : "l"(a), "l"(b));
}
__device__ __forceinline__ float2 unpack2(unsigned long long v) {
    float2 f;
    asm("mov.b64 {%0, %1}, %2;" : "=f"(f.x), "=f"(f.y) : "l"(v));
    return f;
}

__global__ __launch_bounds__(256, 2) void sgemm_q(
    const int M, const int N, const int K,
    const float* __restrict__ A, const float* __restrict__ B, float* __restrict__ C)
{
    constexpr int BK = 8;
    __shared__ __align__(16) float As[2][BK][128];
    __shared__ __align__(16) float Bs[2][BK][128];
    const int tid = threadIdx.x;
    const int tRow = tid >> 4, tCol = tid & 15;
    const int bRow = blockIdx.y, bCol = blockIdx.x;
    const int aRow = tid >> 1, aCol = (tid & 1) * 4;
    const int bRowi = tid >> 5, bColi = (tid & 31) * 4;

    const float* Ag = A + (size_t)(bRow * 128 + aRow) * K + aCol;
    const float* Bg = B + (size_t)bRowi * N + (size_t)bCol * 128 + bColi;

    unsigned long long acc[8][4];
    #pragma unroll
    for (int i = 0; i < 8; i++)
        #pragma unroll
        for (int j = 0; j < 4; j++) acc[i][j] = 0ull;

    {
        float4 a0 = *(const float4*)Ag;
        unsigned bdst = (unsigned)__cvta_generic_to_shared(&Bs[0][bRowi][bColi]);
        asm volatile("cp.async.cg.shared.global [%0], [%1], 16;" :: "r"(bdst), "l"(Bg));
        asm volatile("cp.async.commit_group;");
        As[0][aCol + 0][aRow] = a0.x; As[0][aCol + 1][aRow] = a0.y;
        As[0][aCol + 2][aRow] = a0.z; As[0][aCol + 3][aRow] = a0.w;
        asm volatile("cp.async.wait_group 0;");
    }
    __syncthreads();

    const int NKB = K / BK;
    for (int kb = 0; kb < NKB; kb++) {
        const int buf = kb & 1;
        float4 an;
        if (kb + 1 < NKB) {
            an = *(const float4*)(Ag + (size_t)(kb + 1) * BK);
            unsigned bdst = (unsigned)__cvta_generic_to_shared(&Bs[buf ^ 1][bRowi][bColi]);
            asm volatile("cp.async.cg.shared.global [%0], [%1], 16;"
                         :: "r"(bdst), "l"(Bg + (size_t)(kb + 1) * BK * N));
            asm volatile("cp.async.commit_group;");
        }
        #pragma unroll
        for (int k = 0; k < BK; k++) {
            ulonglong2 n01 = *(const ulonglong2*)(&Bs[buf][k][tCol * 8]);
            ulonglong2 n23 = *(const ulonglong2*)(&Bs[buf][k][tCol * 8 + 4]);
            float4 m0 = *(const float4*)(&As[buf][k][tRow * 8]);
            float4 m1 = *(const float4*)(&As[buf][k][tRow * 8 + 4]);
            float mr[8] = {m0.x, m0.y, m0.z, m0.w, m1.x, m1.y, m1.z, m1.w};
            #pragma unroll
            for (int i = 0; i < 8; i++) {
                unsigned long long mm = pack_dup(mr[i]);
                ffma2(acc[i][0], mm, n01.x);
                ffma2(acc[i][1], mm, n01.y);
                ffma2(acc[i][2], mm, n23.x);
                ffma2(acc[i][3], mm, n23.y);
            }
        }
        if (kb + 1 < NKB) {
            As[buf ^ 1][aCol + 0][aRow] = an.x; As[buf ^ 1][aCol + 1][aRow] = an.y;
            As[buf ^ 1][aCol + 2][aRow] = an.z; As[buf ^ 1][aCol + 3][aRow] = an.w;
            asm volatile("cp.async.wait_group 0;");
        }
        __syncthreads();
    }

    float* Cb = C + (size_t)bRow * 128 * N + (size_t)bCol * 128;
    #pragma unroll
    for (int i = 0; i < 8; i++) {
        size_t rowOff = (size_t)(tRow * 8 + i) * N + tCol * 8;
        #pragma unroll
        for (int j2 = 0; j2 < 4; j2++) {
            float2 p = unpack2(acc[i][j2]);
            *(float2*)(Cb + rowOff + 2 * j2) = p;
        }
    }
}

// ---------------------------------------------------------------------------
// Product-key routing + two-level top-k
// ---------------------------------------------------------------------------
__global__ void routing_topk_kernel(
    const float* __restrict__ Q, const float* __restrict__ keys,
    float* __restrict__ out_scores, int* __restrict__ out_idx)
{
    const int j = blockIdx.x;
    const int t = threadIdx.x;
    __shared__ float q0[64], q1[64];
    __shared__ float r0[64], r1[64];
    __shared__ float cs[64];
    __shared__ int   ci[64];

    const int half = j & 1;
    const int tokA = (j >> 1);
    const int tokB = 4096 + (j >> 1);
    q0[t] = Q[tokA * RET + half * 64 + t];
    q1[t] = Q[tokB * RET + half * 64 + t];
    __syncthreads();

    float s0 = 0.f, s1 = 0.f;
    #pragma unroll
    for (int d = 0; d < 64; d++) {
        s0 += q0[d] * keys[d * 64 + t];
        s1 += q1[d] * keys[4096 + d * 64 + t];
    }
    r0[t] = s0;
    r1[t] = s1;
    __syncthreads();

    if (t == 0) {
        float v0[TOPK], v1[TOPK];
        int   i0[TOPK], i1[TOPK];
        unsigned long long u0 = 0ull, u1 = 0ull;
        for (int p = 0; p < TOPK; p++) {
            float best = -INFINITY; int bi = 0;
            for (int k = 0; k < 64; k++)
                if (!((u0 >> k) & 1ull) && r0[k] > best) { best = r0[k]; bi = k; }
            v0[p] = best; i0[p] = bi; u0 |= 1ull << bi;
            best = -INFINITY; bi = 0;
            for (int k = 0; k < 64; k++)
                if (!((u1 >> k) & 1ull) && r1[k] > best) { best = r1[k]; bi = k; }
            v1[p] = best; i1[p] = bi; u1 |= 1ull << bi;
        }
        for (int a = 0; a < TOPK; a++)
            for (int b = 0; b < TOPK; b++) {
                cs[a * TOPK + b] = v0[a] + v1[b];
                ci[a * TOPK + b] = i0[a] * NKEY + i1[b];
            }
        unsigned long long uc = 0ull;
        for (int p = 0; p < TOPK; p++) {
            float best = -INFINITY; int bi = 0;
            for (int q = 0; q < 64; q++)
                if (!((uc >> q) & 1ull) && cs[q] > best) { best = cs[q]; bi = q; }
            out_scores[j * TOPK + p] = best;
            out_idx[j * TOPK + p]    = ci[bi];
            uc |= 1ull << bi;
        }
    }
}

// ---------------------------------------------------------------------------
// Expert branch
// ---------------------------------------------------------------------------
__global__ __launch_bounds__(256) void experts_kernel(
    const float* __restrict__ X, const float* __restrict__ down_e,
    const float* __restrict__ up_e, const float* __restrict__ scores,
    const int* __restrict__ idx, float* __restrict__ out)
{
    const int j = blockIdx.x;
    const int tid = threadIdx.x;
    const int wid = tid >> 5;
    const int lane = tid & 31;

    __shared__ float xs[HID];
    __shared__ float ew[TOPK];
    __shared__ float w[TOPK];

    for (int h4 = tid; h4 < HID / 4; h4 += 256)
        *(float4*)(&xs[h4 * 4]) = *(const float4*)(X + (size_t)j * HID + h4 * 4);
    __syncthreads();

    {
        const int e = idx[j * TOPK + wid];
        const float* de = down_e + (size_t)e * HID;
        float s = 0.f;
        for (int h = lane * 4; h < HID; h += 32 * 4) {
            float4 d = *(const float4*)(de + h);
            s += xs[h] * d.x + xs[h+1] * d.y + xs[h+2] * d.z + xs[h+3] * d.w;
        }
        #pragma unroll
        for (int o = 16; o; o >>= 1) s += __shfl_xor_sync(0xffffffffu, s, o);
        if (lane == 0) ew[wid] = s;
    }
    __syncthreads();

    if (tid == 0) {
        float sc[TOPK], m = -INFINITY;
        #pragma unroll
        for (int k = 0; k < TOPK; k++) { sc[k] = scores[j * TOPK + k]; m = fmaxf(m, sc[k]); }
        float den = 0.f;
        #pragma unroll
        for (int k = 0; k < TOPK; k++) { sc[k] = expf(sc[k] - m); den += sc[k]; }
        #pragma unroll
        for (int k = 0; k < TOPK; k++) {
            float e_ = ew[k];
            w[k] = (e_ / (1.f + expf(-e_))) * sc[k] / den;
        }
    }
    __syncthreads();

    int   eidx[TOPK];
    float wk[TOPK];
    #pragma unroll
    for (int k = 0; k < TOPK; k++) { eidx[k] = idx[j * TOPK + k]; wk[k] = w[k]; }

    for (int h = tid * 4; h < HID; h += 256 * 4) {
        float4 acc = make_float4(0.f, 0.f, 0.f, 0.f);
        #pragma unroll
        for (int k = 0; k < TOPK; k++) {
            float4 u = *(const float4*)(up_e + (size_t)eidx[k] * HID + h);
            acc.x += wk[k] * u.x; acc.y += wk[k] * u.y;
            acc.z += wk[k] * u.z; acc.w += wk[k] * u.w;
        }
        *(float4*)(out + (size_t)j * HID + h) = acc;
    }
}

// ---------------------------------------------------------------------------
// Launch
// ---------------------------------------------------------------------------
extern "C" void kernel_launch(void* const* d_in, const int* in_sizes, int n_in,
                              void* d_out, int out_size)
{
    const float* x      = (const float*)d_in[0];
    const float* wq     = (const float*)d_in[1];
    const float* keys   = (const float*)d_in[2];
    const float* down_e = (const float*)d_in[3];
    const float* up_e   = (const float*)d_in[4];
    const float* gate_w = (const float*)d_in[5];
    const float* up_w   = (const float*)d_in[6];
    const float* down_w = (const float*)d_in[7];
    float* out = (float*)d_out;

    float *q_ptr, *scr_ptr, *gate_ptr;
    int   *idx_ptr;
    __nv_bfloat16 *xh, *xl, *gwh, *gwl, *uwh, *uwl, *dwh, *dwl, *acth, *actl;
    cudaGetSymbolAddress((void**)&q_ptr,    g_q);
    cudaGetSymbolAddress((void**)&scr_ptr,  g_scores);
    cudaGetSymbolAddress((void**)&idx_ptr,  g_idx);
    cudaGetSymbolAddress((void**)&gate_ptr, g_gate);
    cudaGetSymbolAddress((void**)&xh,   g_xh);
    cudaGetSymbolAddress((void**)&xl,   g_xl);
    cudaGetSymbolAddress((void**)&gwh,  g_gwh);
    cudaGetSymbolAddress((void**)&gwl,  g_gwl);
    cudaGetSymbolAddress((void**)&uwh,  g_uwh);
    cudaGetSymbolAddress((void**)&uwl,  g_uwl);
    cudaGetSymbolAddress((void**)&dwh,  g_dwh);
    cudaGetSymbolAddress((void**)&dwl,  g_dwl);
    cudaGetSymbolAddress((void**)&acth, g_acth);
    cudaGetSymbolAddress((void**)&actl, g_actl);

    cudaFuncSetAttribute(gemm_mma<0>, cudaFuncAttributeMaxDynamicSharedMemorySize, GEMM_SMEM);
    cudaFuncSetAttribute(gemm_mma<1>, cudaFuncAttributeMaxDynamicSharedMemorySize, GEMM_SMEM);
    cudaFuncSetAttribute(gemm_mma<2>, cudaFuncAttributeMaxDynamicSharedMemorySize, GEMM_SMEM);

    // conversions
    conv_split<<<(NTOK * HID / 4 + 255) / 256, 256>>>(x, xh, xl, (size_t)NTOK * HID / 4);
    tconv_split<<<dim3(INTER / 32, HID / 32), dim3(32, 8)>>>(gate_w, gwh, gwl, HID, INTER);
    tconv_split<<<dim3(INTER / 32, HID / 32), dim3(32, 8)>>>(up_w,   uwh, uwl, HID, INTER);
    tconv_split<<<dim3(HID / 32, INTER / 32), dim3(32, 8)>>>(down_w, dwh, dwl, INTER, HID);

    // routing branch
    sgemm_q<<<dim3(RET / 128, NTOK / 128), 256>>>(NTOK, RET, HID, x, wq, q_ptr);
    routing_topk_kernel<<<NTOK, 64>>>(q_ptr, keys, scr_ptr, idx_ptr);
    experts_kernel<<<NTOK, 256>>>(x, down_e, up_e, scr_ptr, idx_ptr, out);

    // dense MLP on tensor cores (HMMA via mma.sync)
    gemm_mma<0><<<dim3(INTER / 128, NTOK / 128), 256, GEMM_SMEM>>>(
        NTOK, INTER, HID, xh, xl, gwh, gwl, gate_ptr, nullptr, nullptr, nullptr);
    gemm_mma<1><<<dim3(INTER / 128, NTOK / 128), 256, GEMM_SMEM>>>(
        NTOK, INTER, HID, xh, xl, uwh, uwl, nullptr, gate_ptr, acth, actl);
    gemm_mma<2><<<dim3(HID / 128, NTOK / 128), 256, GEMM_SMEM>>>(
        NTOK, HID, INTER, acth, actl, dwh, dwl, out, nullptr, nullptr, nullptr);
}

// round 6
// speedup vs baseline: 4.5972x; 1.4727x over previous
#include <cuda_runtime.h>
#include <cuda_fp16.h>
#include <math.h>
#include <stdint.h>

// Problem constants
#define NTOK   8192
#define HID    2048
#define INTER  8192
#define RET    128
#define NKEY   64
#define TOPK   8
#define NEXP   4096

// ---------------------------------------------------------------------------
// Scratch (device globals — no allocation allowed)
// ---------------------------------------------------------------------------
__device__ float g_q[NTOK * RET];
__device__ float g_scores[NTOK * TOPK];
__device__ int   g_idx[NTOK * TOPK];
__device__ __half g_xh[(size_t)NTOK * HID];        // X fp16 hi
__device__ __half g_xl[(size_t)NTOK * HID];        // X fp16 lo
__device__ __half g_gw[(size_t)INTER * HID];       // gate_w^T fp16 [8192,2048]
__device__ __half g_uw[(size_t)INTER * HID];       // up_w^T   fp16 [8192,2048]
__device__ __half g_dw[(size_t)HID * INTER];       // down_w^T fp16 [2048,8192]
__device__ __half g_acth[(size_t)NTOK * INTER];    // act fp16 hi
__device__ __half g_actl[(size_t)NTOK * INTER];    // act fp16 lo

// ---------------------------------------------------------------------------
// PTX helpers (base-target: ldmatrix / mma.sync / cp.async)
// ---------------------------------------------------------------------------
__device__ __forceinline__ void cpasync16(uint32_t dst, const void* src) {
    asm volatile("cp.async.cg.shared.global [%0], [%1], 16;" :: "r"(dst), "l"(src));
}
__device__ __forceinline__ void ldsm4(uint32_t* r, uint32_t addr) {
    asm volatile("ldmatrix.sync.aligned.m8n8.x4.shared.b16 {%0,%1,%2,%3}, [%4];"
                 : "=r"(r[0]), "=r"(r[1]), "=r"(r[2]), "=r"(r[3]) : "r"(addr));
}
__device__ __forceinline__ void mma16816(float* c, const uint32_t* a, const uint32_t* b) {
    asm volatile(
        "mma.sync.aligned.m16n8k16.row.col.f32.f16.f16.f32 "
        "{%0,%1,%2,%3}, {%4,%5,%6,%7}, {%8,%9}, {%0,%1,%2,%3};"
        : "+f"(c[0]), "+f"(c[1]), "+f"(c[2]), "+f"(c[3])
        : "r"(a[0]), "r"(a[1]), "r"(a[2]), "r"(a[3]), "r"(b[0]), "r"(b[1]));
}
__device__ __forceinline__ uint32_t smem_addr(const void* p) {
    uint32_t a;
    asm("{ .reg .u64 t; cvta.to.shared.u64 t, %1; cvt.u32.u64 %0, t; }" : "=r"(a) : "l"(p));
    return a;
}

#define STAGE 65536

// ---------------------------------------------------------------------------
// Fused gate+up GEMM (fp16, A-split 2-term):
//   gate = X @ gate_w, up = X @ up_w, act = silu(gate)*up -> fp16 hi/lo
// A = Xh + Xl (fp16 exact split), B single fp16. C tile 128x128 per GEMM.
// 512 threads = 16 warps (4m x 4n), warp tile 32x32 per GEMM. BK=64.
// Tiles/stage: Ah(16K), Al(16K), Bg(16K), Bu(16K) = 64KB; double buffered.
// ---------------------------------------------------------------------------
__global__ __launch_bounds__(512, 1) void gemm_gu(
    const __half* __restrict__ Ah, const __half* __restrict__ Al,
    const __half* __restrict__ Bg, const __half* __restrict__ Bu,
    __half* __restrict__ Oh, __half* __restrict__ Ol)
{
    extern __shared__ __align__(128) char dynsmem[];
    const int K  = HID;
    const int NN = INTER;
    const int tid = threadIdx.x, lane = tid & 31, wid = tid >> 5;
    const int wm = wid & 3, wn = wid >> 2;
    const int rowA = blockIdx.y * 128, rowB = blockIdx.x * 128;
    const uint32_t sbase = smem_addr(dynsmem);

    auto load_stage = [&](uint32_t db0, int kk) {
        #pragma unroll
        for (int i = 0; i < 8; i++) {
            int ch = i * 512 + tid;
            int t = ch >> 10, local = ch & 1023;
            int r = local >> 3, c = local & 7;
            const __half* P = (t == 0 ? Ah : t == 1 ? Al : t == 2 ? Bg : Bu)
                              + (size_t)((t < 2 ? rowA : rowB) + r) * K + kk;
            uint32_t off = ((uint32_t)(r * 128 + c * 16)) ^ (uint32_t)((r & 7) << 4);
            cpasync16(db0 + t * 16384 + off, (const char*)P + c * 16);
        }
        asm volatile("cp.async.commit_group;" ::: "memory");
    };

    uint32_t rawA[2], xA[2];
    #pragma unroll
    for (int mi = 0; mi < 2; mi++) {
        uint32_t r = (uint32_t)(wm * 32 + mi * 16 + (lane & 15));
        rawA[mi] = r * 128 + ((lane >> 4) * 16);
        xA[mi]   = (rawA[mi] >> 3) & 0x70;
    }
    uint32_t rawB[2], xB[2];
    #pragma unroll
    for (int g = 0; g < 2; g++) {
        uint32_t r = (uint32_t)(wn * 32 + g * 16 + (lane & 7) + ((lane >> 4) << 3));
        rawB[g] = r * 128 + (((lane >> 3) & 1) * 16);
        xB[g]   = (rawB[g] >> 3) & 0x70;
    }

    float ag[2][4][4], au[2][4][4];
    #pragma unroll
    for (int i = 0; i < 2; i++)
        #pragma unroll
        for (int j = 0; j < 4; j++)
            #pragma unroll
            for (int q = 0; q < 4; q++) { ag[i][j][q] = 0.f; au[i][j][q] = 0.f; }

    load_stage(sbase, 0);
    asm volatile("cp.async.wait_group 0;" ::: "memory");
    __syncthreads();

    const int NKB = K / 64;
    for (int kb = 0; kb < NKB; kb++) {
        const uint32_t cur = sbase + (uint32_t)(kb & 1) * STAGE;
        if (kb + 1 < NKB)
            load_stage(sbase + (uint32_t)((kb + 1) & 1) * STAGE, (kb + 1) * 64);

        #pragma unroll
        for (int ks = 0; ks < 4; ks++) {
            uint32_t aH[2][4], aL[2][4], bG[2][4], bU[2][4];
            #pragma unroll
            for (int mi = 0; mi < 2; mi++) {
                uint32_t o = (rawA[mi] + ks * 32) ^ xA[mi];
                ldsm4(aH[mi], cur + o);
                ldsm4(aL[mi], cur + 16384 + o);
            }
            #pragma unroll
            for (int g = 0; g < 2; g++) {
                uint32_t o = (rawB[g] + ks * 32) ^ xB[g];
                ldsm4(bG[g], cur + 32768 + o);
                ldsm4(bU[g], cur + 49152 + o);
            }
            #pragma unroll
            for (int mi = 0; mi < 2; mi++)
                #pragma unroll
                for (int g = 0; g < 2; g++)
                    #pragma unroll
                    for (int hh = 0; hh < 2; hh++) {
                        mma16816(ag[mi][g * 2 + hh], aH[mi], &bG[g][hh * 2]);
                        mma16816(ag[mi][g * 2 + hh], aL[mi], &bG[g][hh * 2]);
                        mma16816(au[mi][g * 2 + hh], aH[mi], &bU[g][hh * 2]);
                        mma16816(au[mi][g * 2 + hh], aL[mi], &bU[g][hh * 2]);
                    }
        }
        if (kb + 1 < NKB)
            asm volatile("cp.async.wait_group 0;" ::: "memory");
        __syncthreads();
    }

    // epilogue: act = silu(gate)*up -> fp16 hi/lo
    const int rOff = lane >> 2, cOff = (lane & 3) * 2;
    #pragma unroll
    for (int mi = 0; mi < 2; mi++)
        #pragma unroll
        for (int nf = 0; nf < 4; nf++)
            #pragma unroll
            for (int hh = 0; hh < 2; hh++) {
                const int rr = rowA + wm * 32 + mi * 16 + rOff + hh * 8;
                const int cc = rowB + wn * 32 + nf * 8 + cOff;
                const size_t pos = (size_t)rr * NN + cc;
                float g0 = ag[mi][nf][hh * 2 + 0], g1 = ag[mi][nf][hh * 2 + 1];
                float u0 = au[mi][nf][hh * 2 + 0], u1 = au[mi][nf][hh * 2 + 1];
                float y0 = (g0 / (1.f + expf(-g0))) * u0;
                float y1 = (g1 / (1.f + expf(-g1))) * u1;
                __half h0 = __float2half_rn(y0);
                __half h1 = __float2half_rn(y1);
                __half l0 = __float2half_rn(y0 - __half2float(h0));
                __half l1 = __float2half_rn(y1 - __half2float(h1));
                *(__half2*)(Oh + pos) = __halves2half2(h0, h1);
                *(__half2*)(Ol + pos) = __halves2half2(l0, l1);
            }
}

// ---------------------------------------------------------------------------
// Down GEMM (fp16, A-split 2-term): out += act @ down_w
// CTA tile 128(M) x 256(N), BK=64. 512 threads = 16 warps (4m x 4n),
// warp tile 32x64. Tiles/stage: Ah(16K), Al(16K), B(32K) = 64KB.
// ---------------------------------------------------------------------------
__global__ __launch_bounds__(512, 1) void gemm_dn(
    const __half* __restrict__ Ah, const __half* __restrict__ Al,
    const __half* __restrict__ B, float* __restrict__ C)
{
    extern __shared__ __align__(128) char dynsmem[];
    const int K  = INTER;
    const int NN = HID;
    const int tid = threadIdx.x, lane = tid & 31, wid = tid >> 5;
    const int wm = wid & 3, wn = wid >> 2;
    const int rowA = blockIdx.y * 128, rowB = blockIdx.x * 256;
    const uint32_t sbase = smem_addr(dynsmem);

    auto load_stage = [&](uint32_t db0, int kk) {
        #pragma unroll
        for (int i = 0; i < 8; i++) {
            int ch = i * 512 + tid;
            const __half* P;
            uint32_t dst;
            int r, c;
            if (ch < 2048) {
                int t = ch >> 10, local = ch & 1023;
                r = local >> 3; c = local & 7;
                P = (t == 0 ? Ah : Al) + (size_t)(rowA + r) * K + kk;
                uint32_t off = ((uint32_t)(r * 128 + c * 16)) ^ (uint32_t)((r & 7) << 4);
                dst = db0 + t * 16384 + off;
            } else {
                int local = ch - 2048;
                r = local >> 3; c = local & 7;
                P = B + (size_t)(rowB + r) * K + kk;
                uint32_t off = ((uint32_t)(r * 128 + c * 16)) ^ (uint32_t)((r & 7) << 4);
                dst = db0 + 32768 + off;
            }
            cpasync16(dst, (const char*)P + c * 16);
        }
        asm volatile("cp.async.commit_group;" ::: "memory");
    };

    uint32_t rawA[2], xA[2];
    #pragma unroll
    for (int mi = 0; mi < 2; mi++) {
        uint32_t r = (uint32_t)(wm * 32 + mi * 16 + (lane & 15));
        rawA[mi] = r * 128 + ((lane >> 4) * 16);
        xA[mi]   = (rawA[mi] >> 3) & 0x70;
    }
    uint32_t rawB[4], xB[4];
    #pragma unroll
    for (int g = 0; g < 4; g++) {
        uint32_t r = (uint32_t)(wn * 64 + g * 16 + (lane & 7) + ((lane >> 4) << 3));
        rawB[g] = r * 128 + (((lane >> 3) & 1) * 16);
        xB[g]   = (rawB[g] >> 3) & 0x70;
    }

    float acc[2][8][4];
    #pragma unroll
    for (int i = 0; i < 2; i++)
        #pragma unroll
        for (int j = 0; j < 8; j++)
            #pragma unroll
            for (int q = 0; q < 4; q++) acc[i][j][q] = 0.f;

    load_stage(sbase, 0);
    asm volatile("cp.async.wait_group 0;" ::: "memory");
    __syncthreads();

    const int NKB = K / 64;
    for (int kb = 0; kb < NKB; kb++) {
        const uint32_t cur = sbase + (uint32_t)(kb & 1) * STAGE;
        if (kb + 1 < NKB)
            load_stage(sbase + (uint32_t)((kb + 1) & 1) * STAGE, (kb + 1) * 64);

        #pragma unroll
        for (int ks = 0; ks < 4; ks++) {
            uint32_t aH[2][4], aL[2][4], bR[4][4];
            #pragma unroll
            for (int mi = 0; mi < 2; mi++) {
                uint32_t o = (rawA[mi] + ks * 32) ^ xA[mi];
                ldsm4(aH[mi], cur + o);
                ldsm4(aL[mi], cur + 16384 + o);
            }
            #pragma unroll
            for (int g = 0; g < 4; g++) {
                uint32_t o = (rawB[g] + ks * 32) ^ xB[g];
                ldsm4(bR[g], cur + 32768 + o);
            }
            #pragma unroll
            for (int mi = 0; mi < 2; mi++)
                #pragma unroll
                for (int g = 0; g < 4; g++)
                    #pragma unroll
                    for (int hh = 0; hh < 2; hh++) {
                        float* c = acc[mi][g * 2 + hh];
                        mma16816(c, aH[mi], &bR[g][hh * 2]);
                        mma16816(c, aL[mi], &bR[g][hh * 2]);
                    }
        }
        if (kb + 1 < NKB)
            asm volatile("cp.async.wait_group 0;" ::: "memory");
        __syncthreads();
    }

    // epilogue: out += v
    const int rOff = lane >> 2, cOff = (lane & 3) * 2;
    #pragma unroll
    for (int mi = 0; mi < 2; mi++)
        #pragma unroll
        for (int nf = 0; nf < 8; nf++)
            #pragma unroll
            for (int hh = 0; hh < 2; hh++) {
                const int rr = rowA + wm * 32 + mi * 16 + rOff + hh * 8;
                const int cc = rowB + wn * 64 + nf * 8 + cOff;
                const size_t pos = (size_t)rr * NN + cc;
                float2 o = *(const float2*)(C + pos);
                o.x += acc[mi][nf][hh * 2 + 0];
                o.y += acc[mi][nf][hh * 2 + 1];
                *(float2*)(C + pos) = o;
            }
}

// ---------------------------------------------------------------------------
// Conversions
// ---------------------------------------------------------------------------
__global__ void conv_xh(const float* __restrict__ in,
                        __half* __restrict__ oh, __half* __restrict__ ol, size_t n4)
{
    size_t i = (size_t)blockIdx.x * blockDim.x + threadIdx.x;
    if (i >= n4) return;
    float4 v = *(const float4*)(in + i * 4);
    float f[4] = {v.x, v.y, v.z, v.w};
    __half h[4], l[4];
    #pragma unroll
    for (int q = 0; q < 4; q++) {
        h[q] = __float2half_rn(f[q]);
        l[q] = __float2half_rn(f[q] - __half2float(h[q]));
    }
    *(__half2*)(oh + i * 4)     = __halves2half2(h[0], h[1]);
    *(__half2*)(oh + i * 4 + 2) = __halves2half2(h[2], h[3]);
    *(__half2*)(ol + i * 4)     = __halves2half2(l[0], l[1]);
    *(__half2*)(ol + i * 4 + 2) = __halves2half2(l[2], l[3]);
}

__global__ void tconv_h(const float* __restrict__ in, __half* __restrict__ o,
                        int R, int C)
{
    __shared__ float t[32][33];
    const int c0 = blockIdx.x * 32, r0 = blockIdx.y * 32;
    const int tx = threadIdx.x, ty = threadIdx.y;
    #pragma unroll
    for (int i = 0; i < 4; i++)
        t[ty + i * 8][tx] = in[(size_t)(r0 + ty + i * 8) * C + c0 + tx];
    __syncthreads();
    #pragma unroll
    for (int i = 0; i < 4; i++)
        o[(size_t)(c0 + ty + i * 8) * R + r0 + tx] = __float2half_rn(t[tx][ty + i * 8]);
}

// ---------------------------------------------------------------------------
// f32x2 SGEMM for the Q projection (fp32 exact, routing is bit-sensitive)
// ---------------------------------------------------------------------------
__device__ __forceinline__ unsigned long long pack_dup(float a) {
    unsigned long long r;
    asm("mov.b64 %0, {%1, %1};" : "=l"(r) : "f"(a));
    return r;
}
__device__ __forceinline__ void ffma2(unsigned long long& d, unsigned long long a,
                                      unsigned long long b) {
    asm("fma.rn.f32x2 %0, %1, %2, %0;" : "+l"(d) : "l"(a), "l"(b));
}
__device__ __forceinline__ float2 unpack2(unsigned long long v) {
    float2 f;
    asm("mov.b64 {%0, %1}, %2;" : "=f"(f.x), "=f"(f.y) : "l"(v));
    return f;
}

__global__ __launch_bounds__(256, 2) void sgemm_q(
    const int M, const int N, const int K,
    const float* __restrict__ A, const float* __restrict__ B, float* __restrict__ C)
{
    constexpr int BK = 8;
    __shared__ __align__(16) float As[2][BK][128];
    __shared__ __align__(16) float Bs[2][BK][128];
    const int tid = threadIdx.x;
    const int tRow = tid >> 4, tCol = tid & 15;
    const int bRow = blockIdx.y, bCol = blockIdx.x;
    const int aRow = tid >> 1, aCol = (tid & 1) * 4;
    const int bRowi = tid >> 5, bColi = (tid & 31) * 4;

    const float* Ag = A + (size_t)(bRow * 128 + aRow) * K + aCol;
    const float* Bg = B + (size_t)bRowi * N + (size_t)bCol * 128 + bColi;

    unsigned long long acc[8][4];
    #pragma unroll
    for (int i = 0; i < 8; i++)
        #pragma unroll
        for (int j = 0; j < 4; j++) acc[i][j] = 0ull;

    {
        float4 a0 = *(const float4*)Ag;
        unsigned bdst = (unsigned)__cvta_generic_to_shared(&Bs[0][bRowi][bColi]);
        asm volatile("cp.async.cg.shared.global [%0], [%1], 16;" :: "r"(bdst), "l"(Bg));
        asm volatile("cp.async.commit_group;");
        As[0][aCol + 0][aRow] = a0.x; As[0][aCol + 1][aRow] = a0.y;
        As[0][aCol + 2][aRow] = a0.z; As[0][aCol + 3][aRow] = a0.w;
        asm volatile("cp.async.wait_group 0;");
    }
    __syncthreads();

    const int NKB = K / BK;
    for (int kb = 0; kb < NKB; kb++) {
        const int buf = kb & 1;
        float4 an;
        if (kb + 1 < NKB) {
            an = *(const float4*)(Ag + (size_t)(kb + 1) * BK);
            unsigned bdst = (unsigned)__cvta_generic_to_shared(&Bs[buf ^ 1][bRowi][bColi]);
            asm volatile("cp.async.cg.shared.global [%0], [%1], 16;"
                         :: "r"(bdst), "l"(Bg + (size_t)(kb + 1) * BK * N));
            asm volatile("cp.async.commit_group;");
        }
        #pragma unroll
        for (int k = 0; k < BK; k++) {
            ulonglong2 n01 = *(const ulonglong2*)(&Bs[buf][k][tCol * 8]);
            ulonglong2 n23 = *(const ulonglong2*)(&Bs[buf][k][tCol * 8 + 4]);
            float4 m0 = *(const float4*)(&As[buf][k][tRow * 8]);
            float4 m1 = *(const float4*)(&As[buf][k][tRow * 8 + 4]);
            float mr[8] = {m0.x, m0.y, m0.z, m0.w, m1.x, m1.y, m1.z, m1.w};
            #pragma unroll
            for (int i = 0; i < 8; i++) {
                unsigned long long mm = pack_dup(mr[i]);
                ffma2(acc[i][0], mm, n01.x);
                ffma2(acc[i][1], mm, n01.y);
                ffma2(acc[i][2], mm, n23.x);
                ffma2(acc[i][3], mm, n23.y);
            }
        }
        if (kb + 1 < NKB) {
            As[buf ^ 1][aCol + 0][aRow] = an.x; As[buf ^ 1][aCol + 1][aRow] = an.y;
            As[buf ^ 1][aCol + 2][aRow] = an.z; As[buf ^ 1][aCol + 3][aRow] = an.w;
            asm volatile("cp.async.wait_group 0;");
        }
        __syncthreads();
    }

    float* Cb = C + (size_t)bRow * 128 * N + (size_t)bCol * 128;
    #pragma unroll
    for (int i = 0; i < 8; i++) {
        size_t rowOff = (size_t)(tRow * 8 + i) * N + tCol * 8;
        #pragma unroll
        for (int j2 = 0; j2 < 4; j2++) {
            float2 p = unpack2(acc[i][j2]);
            *(float2*)(Cb + rowOff + 2 * j2) = p;
        }
    }
}

// ---------------------------------------------------------------------------
// Product-key routing + two-level top-k
// ---------------------------------------------------------------------------
__global__ void routing_topk_kernel(
    const float* __restrict__ Q, const float* __restrict__ keys,
    float* __restrict__ out_scores, int* __restrict__ out_idx)
{
    const int j = blockIdx.x;
    const int t = threadIdx.x;
    __shared__ float q0[64], q1[64];
    __shared__ float r0[64], r1[64];
    __shared__ float cs[64];
    __shared__ int   ci[64];

    const int half = j & 1;
    const int tokA = (j >> 1);
    const int tokB = 4096 + (j >> 1);
    q0[t] = Q[tokA * RET + half * 64 + t];
    q1[t] = Q[tokB * RET + half * 64 + t];
    __syncthreads();

    float s0 = 0.f, s1 = 0.f;
    #pragma unroll
    for (int d = 0; d < 64; d++) {
        s0 += q0[d] * keys[d * 64 + t];
        s1 += q1[d] * keys[4096 + d * 64 + t];
    }
    r0[t] = s0;
    r1[t] = s1;
    __syncthreads();

    if (t == 0) {
        float v0[TOPK], v1[TOPK];
        int   i0[TOPK], i1[TOPK];
        unsigned long long u0 = 0ull, u1 = 0ull;
        for (int p = 0; p < TOPK; p++) {
            float best = -INFINITY; int bi = 0;
            for (int k = 0; k < 64; k++)
                if (!((u0 >> k) & 1ull) && r0[k] > best) { best = r0[k]; bi = k; }
            v0[p] = best; i0[p] = bi; u0 |= 1ull << bi;
            best = -INFINITY; bi = 0;
            for (int k = 0; k < 64; k++)
                if (!((u1 >> k) & 1ull) && r1[k] > best) { best = r1[k]; bi = k; }
            v1[p] = best; i1[p] = bi; u1 |= 1ull << bi;
        }
        for (int a = 0; a < TOPK; a++)
            for (int b = 0; b < TOPK; b++) {
                cs[a * TOPK + b] = v0[a] + v1[b];
                ci[a * TOPK + b] = i0[a] * NKEY + i1[b];
            }
        unsigned long long uc = 0ull;
        for (int p = 0; p < TOPK; p++) {
            float best = -INFINITY; int bi = 0;
            for (int q = 0; q < 64; q++)
                if (!((uc >> q) & 1ull) && cs[q] > best) { best = cs[q]; bi = q; }
            out_scores[j * TOPK + p] = best;
            out_idx[j * TOPK + p]    = ci[bi];
            uc |= 1ull << bi;
        }
    }
}

// ---------------------------------------------------------------------------
// Expert branch
// ---------------------------------------------------------------------------
__global__ __launch_bounds__(256) void experts_kernel(
    const float* __restrict__ X, const float* __restrict__ down_e,
    const float* __restrict__ up_e, const float* __restrict__ scores,
    const int* __restrict__ idx, float* __restrict__ out)
{
    const int j = blockIdx.x;
    const int tid = threadIdx.x;
    const int wid = tid >> 5;
    const int lane = tid & 31;

    __shared__ float xs[HID];
    __shared__ float ew[TOPK];
    __shared__ float w[TOPK];

    for (int h4 = tid; h4 < HID / 4; h4 += 256)
        *(float4*)(&xs[h4 * 4]) = *(const float4*)(X + (size_t)j * HID + h4 * 4);
    __syncthreads();

    {
        const int e = idx[j * TOPK + wid];
        const float* de = down_e + (size_t)e * HID;
        float s = 0.f;
        for (int h = lane * 4; h < HID; h += 32 * 4) {
            float4 d = *(const float4*)(de + h);
            s += xs[h] * d.x + xs[h+1] * d.y + xs[h+2] * d.z + xs[h+3] * d.w;
        }
        #pragma unroll
        for (int o = 16; o; o >>= 1) s += __shfl_xor_sync(0xffffffffu, s, o);
        if (lane == 0) ew[wid] = s;
    }
    __syncthreads();

    if (tid == 0) {
        float sc[TOPK], m = -INFINITY;
        #pragma unroll
        for (int k = 0; k < TOPK; k++) { sc[k] = scores[j * TOPK + k]; m = fmaxf(m, sc[k]); }
        float den = 0.f;
        #pragma unroll
        for (int k = 0; k < TOPK; k++) { sc[k] = expf(sc[k] - m); den += sc[k]; }
        #pragma unroll
        for (int k = 0; k < TOPK; k++) {
            float e_ = ew[k];
            w[k] = (e_ / (1.f + expf(-e_))) * sc[k] / den;
        }
    }
    __syncthreads();

    int   eidx[TOPK];
    float wk[TOPK];
    #pragma unroll
    for (int k = 0; k < TOPK; k++) { eidx[k] = idx[j * TOPK + k]; wk[k] = w[k]; }

    for (int h = tid * 4; h < HID; h += 256 * 4) {
        float4 acc = make_float4(0.f, 0.f, 0.f, 0.f);
        #pragma unroll
        for (int k = 0; k < TOPK; k++) {
            float4 u = *(const float4*)(up_e + (size_t)eidx[k] * HID + h);
            acc.x += wk[k] * u.x; acc.y += wk[k] * u.y;
            acc.z += wk[k] * u.z; acc.w += wk[k] * u.w;
        }
        *(float4*)(out + (size_t)j * HID + h) = acc;
    }
}

// ---------------------------------------------------------------------------
// Launch
// ---------------------------------------------------------------------------
extern "C" void kernel_launch(void* const* d_in, const int* in_sizes, int n_in,
                              void* d_out, int out_size)
{
    const float* x      = (const float*)d_in[0];
    const float* wq     = (const float*)d_in[1];
    const float* keys   = (const float*)d_in[2];
    const float* down_e = (const float*)d_in[3];
    const float* up_e   = (const float*)d_in[4];
    const float* gate_w = (const float*)d_in[5];
    const float* up_w   = (const float*)d_in[6];
    const float* down_w = (const float*)d_in[7];
    float* out = (float*)d_out;

    float *q_ptr, *scr_ptr;
    int   *idx_ptr;
    __half *xh, *xl, *gw, *uw, *dw, *acth, *actl;
    cudaGetSymbolAddress((void**)&q_ptr,   g_q);
    cudaGetSymbolAddress((void**)&scr_ptr, g_scores);
    cudaGetSymbolAddress((void**)&idx_ptr, g_idx);
    cudaGetSymbolAddress((void**)&xh,   g_xh);
    cudaGetSymbolAddress((void**)&xl,   g_xl);
    cudaGetSymbolAddress((void**)&gw,   g_gw);
    cudaGetSymbolAddress((void**)&uw,   g_uw);
    cudaGetSymbolAddress((void**)&dw,   g_dw);
    cudaGetSymbolAddress((void**)&acth, g_acth);
    cudaGetSymbolAddress((void**)&actl, g_actl);

    cudaFuncSetAttribute(gemm_gu, cudaFuncAttributeMaxDynamicSharedMemorySize, 2 * STAGE);
    cudaFuncSetAttribute(gemm_dn, cudaFuncAttributeMaxDynamicSharedMemorySize, 2 * STAGE);

    // conversions
    conv_xh<<<(NTOK * HID / 4 + 255) / 256, 256>>>(x, xh, xl, (size_t)NTOK * HID / 4);
    tconv_h<<<dim3(INTER / 32, HID / 32), dim3(32, 8)>>>(gate_w, gw, HID, INTER);
    tconv_h<<<dim3(INTER / 32, HID / 32), dim3(32, 8)>>>(up_w,   uw, HID, INTER);
    tconv_h<<<dim3(HID / 32, INTER / 32), dim3(32, 8)>>>(down_w, dw, INTER, HID);

    // routing branch (fp32 exact)
    sgemm_q<<<dim3(RET / 128, NTOK / 128), 256>>>(NTOK, RET, HID, x, wq, q_ptr);
    routing_topk_kernel<<<NTOK, 64>>>(q_ptr, keys, scr_ptr, idx_ptr);
    experts_kernel<<<NTOK, 256>>>(x, down_e, up_e, scr_ptr, idx_ptr, out);

    // dense MLP: fused gate+up, then down (accumulates onto experts output)
    gemm_gu<<<dim3(INTER / 128, NTOK / 128), 512, 2 * STAGE>>>(
        xh, xl, gw, uw, acth, actl);
    gemm_dn<<<dim3(HID / 256, NTOK / 128), 512, 2 * STAGE>>>(
        acth, actl, dw, out);
}

// round 7
// speedup vs baseline: 5.3413x; 1.1619x over previous
#include <cuda_runtime.h>
#include <cuda_fp16.h>
#include <math.h>
#include <stdint.h>

// Problem constants
#define NTOK   8192
#define HID    2048
#define INTER  8192
#define RET    128
#define NKEY   64
#define TOPK   8
#define NEXP   4096

// ---------------------------------------------------------------------------
// Scratch (device globals — no allocation allowed)
// ---------------------------------------------------------------------------
__device__ float g_q[NTOK * RET];
__device__ float g_scores[NTOK * TOPK];
__device__ int   g_idx[NTOK * TOPK];
__device__ __half g_xh[(size_t)NTOK * HID];        // X fp16 hi
__device__ __half g_xl[(size_t)NTOK * HID];        // X fp16 lo
__device__ __half g_gw[(size_t)INTER * HID];       // gate_w^T fp16 [8192,2048]
__device__ __half g_uw[(size_t)INTER * HID];       // up_w^T   fp16 [8192,2048]
__device__ __half g_dw[(size_t)HID * INTER];       // down_w^T fp16 [2048,8192]
__device__ __half g_act[(size_t)NTOK * INTER];     // act fp16 (single)

// ---------------------------------------------------------------------------
// PTX helpers
// ---------------------------------------------------------------------------
__device__ __forceinline__ void cpasync16(uint32_t dst, const void* src) {
    asm volatile("cp.async.cg.shared.global [%0], [%1], 16;" :: "r"(dst), "l"(src));
}
__device__ __forceinline__ void ldsm4(uint32_t* r, uint32_t addr) {
    asm volatile("ldmatrix.sync.aligned.m8n8.x4.shared.b16 {%0,%1,%2,%3}, [%4];"
                 : "=r"(r[0]), "=r"(r[1]), "=r"(r[2]), "=r"(r[3]) : "r"(addr));
}
__device__ __forceinline__ void mma16816(float* c, const uint32_t* a, const uint32_t* b) {
    asm volatile(
        "mma.sync.aligned.m16n8k16.row.col.f32.f16.f16.f32 "
        "{%0,%1,%2,%3}, {%4,%5,%6,%7}, {%8,%9}, {%0,%1,%2,%3};"
        : "+f"(c[0]), "+f"(c[1]), "+f"(c[2]), "+f"(c[3])
        : "r"(a[0]), "r"(a[1]), "r"(a[2]), "r"(a[3]), "r"(b[0]), "r"(b[1]));
}
__device__ __forceinline__ uint32_t smem_addr(const void* p) {
    uint32_t a;
    asm("{ .reg .u64 t; cvta.to.shared.u64 t, %1; cvt.u32.u64 %0, t; }" : "=r"(a) : "l"(p));
    return a;
}

#define STAGE_GU 65536    // Ah, Al, Bg, Bu x 16KB
#define STAGE_DN 49152    // Ah 16KB + B 32KB

// ---------------------------------------------------------------------------
// Fused gate+up GEMM (fp16, A-split 2-term):
//   act = silu(X@gate_w) * (X@up_w) -> single fp16
// 512 threads = 16 warps (4m x 4n), warp tile 32x32 per GEMM. BK=64.
// ---------------------------------------------------------------------------
__global__ __launch_bounds__(512, 1) void gemm_gu(
    const __half* __restrict__ Ah, const __half* __restrict__ Al,
    const __half* __restrict__ Bg, const __half* __restrict__ Bu,
    __half* __restrict__ O)
{
    extern __shared__ __align__(128) char dynsmem[];
    const int K  = HID;
    const int NN = INTER;
    const int tid = threadIdx.x, lane = tid & 31, wid = tid >> 5;
    const int wm = wid & 3, wn = wid >> 2;
    const int rowA = blockIdx.y * 128, rowB = blockIdx.x * 128;
    const uint32_t sbase = smem_addr(dynsmem);

    auto load_stage = [&](uint32_t db0, int kk) {
        #pragma unroll
        for (int i = 0; i < 8; i++) {
            int ch = i * 512 + tid;
            int t = ch >> 10, local = ch & 1023;
            int r = local >> 3, c = local & 7;
            const __half* P = (t == 0 ? Ah : t == 1 ? Al : t == 2 ? Bg : Bu)
                              + (size_t)((t < 2 ? rowA : rowB) + r) * K + kk;
            uint32_t off = ((uint32_t)(r * 128 + c * 16)) ^ (uint32_t)((r & 7) << 4);
            cpasync16(db0 + t * 16384 + off, (const char*)P + c * 16);
        }
        asm volatile("cp.async.commit_group;" ::: "memory");
    };

    uint32_t rawA[2], xA[2];
    #pragma unroll
    for (int mi = 0; mi < 2; mi++) {
        uint32_t r = (uint32_t)(wm * 32 + mi * 16 + (lane & 15));
        rawA[mi] = r * 128 + ((lane >> 4) * 16);
        xA[mi]   = (rawA[mi] >> 3) & 0x70;
    }
    uint32_t rawB[2], xB[2];
    #pragma unroll
    for (int g = 0; g < 2; g++) {
        uint32_t r = (uint32_t)(wn * 32 + g * 16 + (lane & 7) + ((lane >> 4) << 3));
        rawB[g] = r * 128 + (((lane >> 3) & 1) * 16);
        xB[g]   = (rawB[g] >> 3) & 0x70;
    }

    float ag[2][4][4], au[2][4][4];
    #pragma unroll
    for (int i = 0; i < 2; i++)
        #pragma unroll
        for (int j = 0; j < 4; j++)
            #pragma unroll
            for (int q = 0; q < 4; q++) { ag[i][j][q] = 0.f; au[i][j][q] = 0.f; }

    load_stage(sbase, 0);
    asm volatile("cp.async.wait_group 0;" ::: "memory");
    __syncthreads();

    const int NKB = K / 64;
    for (int kb = 0; kb < NKB; kb++) {
        const uint32_t cur = sbase + (uint32_t)(kb & 1) * STAGE_GU;
        if (kb + 1 < NKB)
            load_stage(sbase + (uint32_t)((kb + 1) & 1) * STAGE_GU, (kb + 1) * 64);

        #pragma unroll
        for (int ks = 0; ks < 4; ks++) {
            uint32_t aH[2][4], aL[2][4], bG[2][4], bU[2][4];
            #pragma unroll
            for (int mi = 0; mi < 2; mi++) {
                uint32_t o = (rawA[mi] + ks * 32) ^ xA[mi];
                ldsm4(aH[mi], cur + o);
                ldsm4(aL[mi], cur + 16384 + o);
            }
            #pragma unroll
            for (int g = 0; g < 2; g++) {
                uint32_t o = (rawB[g] + ks * 32) ^ xB[g];
                ldsm4(bG[g], cur + 32768 + o);
                ldsm4(bU[g], cur + 49152 + o);
            }
            #pragma unroll
            for (int mi = 0; mi < 2; mi++)
                #pragma unroll
                for (int g = 0; g < 2; g++)
                    #pragma unroll
                    for (int hh = 0; hh < 2; hh++) {
                        mma16816(ag[mi][g * 2 + hh], aH[mi], &bG[g][hh * 2]);
                        mma16816(ag[mi][g * 2 + hh], aL[mi], &bG[g][hh * 2]);
                        mma16816(au[mi][g * 2 + hh], aH[mi], &bU[g][hh * 2]);
                        mma16816(au[mi][g * 2 + hh], aL[mi], &bU[g][hh * 2]);
                    }
        }
        if (kb + 1 < NKB)
            asm volatile("cp.async.wait_group 0;" ::: "memory");
        __syncthreads();
    }

    // epilogue: act = silu(gate)*up -> fp16
    const int rOff = lane >> 2, cOff = (lane & 3) * 2;
    #pragma unroll
    for (int mi = 0; mi < 2; mi++)
        #pragma unroll
        for (int nf = 0; nf < 4; nf++)
            #pragma unroll
            for (int hh = 0; hh < 2; hh++) {
                const int rr = rowA + wm * 32 + mi * 16 + rOff + hh * 8;
                const int cc = rowB + wn * 32 + nf * 8 + cOff;
                const size_t pos = (size_t)rr * NN + cc;
                float g0 = ag[mi][nf][hh * 2 + 0], g1 = ag[mi][nf][hh * 2 + 1];
                float u0 = au[mi][nf][hh * 2 + 0], u1 = au[mi][nf][hh * 2 + 1];
                float y0 = (g0 / (1.f + expf(-g0))) * u0;
                float y1 = (g1 / (1.f + expf(-g1))) * u1;
                *(__half2*)(O + pos) =
                    __halves2half2(__float2half_rn(y0), __float2half_rn(y1));
            }
}

// ---------------------------------------------------------------------------
// Down GEMM (fp16 single-term): out += act @ down_w
// CTA tile 128(M) x 256(N), BK=64. 512 threads = 16 warps (4m x 4n),
// warp tile 32x64. Tiles/stage: A(16K) + B(32K) = 48KB.
// ---------------------------------------------------------------------------
__global__ __launch_bounds__(512, 1) void gemm_dn(
    const __half* __restrict__ A,
    const __half* __restrict__ B, float* __restrict__ C)
{
    extern __shared__ __align__(128) char dynsmem[];
    const int K  = INTER;
    const int NN = HID;
    const int tid = threadIdx.x, lane = tid & 31, wid = tid >> 5;
    const int wm = wid & 3, wn = wid >> 2;
    const int rowA = blockIdx.y * 128, rowB = blockIdx.x * 256;
    const uint32_t sbase = smem_addr(dynsmem);

    auto load_stage = [&](uint32_t db0, int kk) {
        #pragma unroll
        for (int i = 0; i < 6; i++) {
            int ch = i * 512 + tid;
            const __half* P;
            uint32_t dst;
            if (ch < 1024) {
                int r = ch >> 3, c = ch & 7;
                P = A + (size_t)(rowA + r) * K + kk + c * 8;
                uint32_t off = ((uint32_t)(r * 128 + c * 16)) ^ (uint32_t)((r & 7) << 4);
                dst = db0 + off;
            } else {
                int local = ch - 1024;
                int r = local >> 3, c = local & 7;
                P = B + (size_t)(rowB + r) * K + kk + c * 8;
                uint32_t off = ((uint32_t)(r * 128 + c * 16)) ^ (uint32_t)((r & 7) << 4);
                dst = db0 + 16384 + off;
            }
            cpasync16(dst, P);
        }
        asm volatile("cp.async.commit_group;" ::: "memory");
    };

    uint32_t rawA[2], xA[2];
    #pragma unroll
    for (int mi = 0; mi < 2; mi++) {
        uint32_t r = (uint32_t)(wm * 32 + mi * 16 + (lane & 15));
        rawA[mi] = r * 128 + ((lane >> 4) * 16);
        xA[mi]   = (rawA[mi] >> 3) & 0x70;
    }
    uint32_t rawB[4], xB[4];
    #pragma unroll
    for (int g = 0; g < 4; g++) {
        uint32_t r = (uint32_t)(wn * 64 + g * 16 + (lane & 7) + ((lane >> 4) << 3));
        rawB[g] = r * 128 + (((lane >> 3) & 1) * 16);
        xB[g]   = (rawB[g] >> 3) & 0x70;
    }

    float acc[2][8][4];
    #pragma unroll
    for (int i = 0; i < 2; i++)
        #pragma unroll
        for (int j = 0; j < 8; j++)
            #pragma unroll
            for (int q = 0; q < 4; q++) acc[i][j][q] = 0.f;

    load_stage(sbase, 0);
    asm volatile("cp.async.wait_group 0;" ::: "memory");
    __syncthreads();

    const int NKB = K / 64;
    for (int kb = 0; kb < NKB; kb++) {
        const uint32_t cur = sbase + (uint32_t)(kb & 1) * STAGE_DN;
        if (kb + 1 < NKB)
            load_stage(sbase + (uint32_t)((kb + 1) & 1) * STAGE_DN, (kb + 1) * 64);

        #pragma unroll
        for (int ks = 0; ks < 4; ks++) {
            uint32_t aH[2][4], bR[4][4];
            #pragma unroll
            for (int mi = 0; mi < 2; mi++)
                ldsm4(aH[mi], cur + ((rawA[mi] + ks * 32) ^ xA[mi]));
            #pragma unroll
            for (int g = 0; g < 4; g++)
                ldsm4(bR[g], cur + 16384 + ((rawB[g] + ks * 32) ^ xB[g]));
            #pragma unroll
            for (int mi = 0; mi < 2; mi++)
                #pragma unroll
                for (int g = 0; g < 4; g++)
                    #pragma unroll
                    for (int hh = 0; hh < 2; hh++)
                        mma16816(acc[mi][g * 2 + hh], aH[mi], &bR[g][hh * 2]);
        }
        if (kb + 1 < NKB)
            asm volatile("cp.async.wait_group 0;" ::: "memory");
        __syncthreads();
    }

    // epilogue: out += v
    const int rOff = lane >> 2, cOff = (lane & 3) * 2;
    #pragma unroll
    for (int mi = 0; mi < 2; mi++)
        #pragma unroll
        for (int nf = 0; nf < 8; nf++)
            #pragma unroll
            for (int hh = 0; hh < 2; hh++) {
                const int rr = rowA + wm * 32 + mi * 16 + rOff + hh * 8;
                const int cc = rowB + wn * 64 + nf * 8 + cOff;
                const size_t pos = (size_t)rr * NN + cc;
                float2 o = *(const float2*)(C + pos);
                o.x += acc[mi][nf][hh * 2 + 0];
                o.y += acc[mi][nf][hh * 2 + 1];
                *(float2*)(C + pos) = o;
            }
}

// ---------------------------------------------------------------------------
// Conversions
// ---------------------------------------------------------------------------
__global__ void conv_xh(const float* __restrict__ in,
                        __half* __restrict__ oh, __half* __restrict__ ol, size_t n4)
{
    size_t i = (size_t)blockIdx.x * blockDim.x + threadIdx.x;
    if (i >= n4) return;
    float4 v = *(const float4*)(in + i * 4);
    float f[4] = {v.x, v.y, v.z, v.w};
    __half h[4], l[4];
    #pragma unroll
    for (int q = 0; q < 4; q++) {
        h[q] = __float2half_rn(f[q]);
        l[q] = __float2half_rn(f[q] - __half2float(h[q]));
    }
    *(__half2*)(oh + i * 4)     = __halves2half2(h[0], h[1]);
    *(__half2*)(oh + i * 4 + 2) = __halves2half2(h[2], h[3]);
    *(__half2*)(ol + i * 4)     = __halves2half2(l[0], l[1]);
    *(__half2*)(ol + i * 4 + 2) = __halves2half2(l[2], l[3]);
}

__global__ void tconv_h(const float* __restrict__ in, __half* __restrict__ o,
                        int R, int C)
{
    __shared__ float t[32][33];
    const int c0 = blockIdx.x * 32, r0 = blockIdx.y * 32;
    const int tx = threadIdx.x, ty = threadIdx.y;
    #pragma unroll
    for (int i = 0; i < 4; i++)
        t[ty + i * 8][tx] = in[(size_t)(r0 + ty + i * 8) * C + c0 + tx];
    __syncthreads();
    #pragma unroll
    for (int i = 0; i < 4; i++)
        o[(size_t)(c0 + ty + i * 8) * R + r0 + tx] = __float2half_rn(t[tx][ty + i * 8]);
}

// ---------------------------------------------------------------------------
// f32x2 SGEMM for the Q projection (fp32 exact — routing is rank-sensitive)
// ---------------------------------------------------------------------------
__device__ __forceinline__ unsigned long long pack_dup(float a) {
    unsigned long long r;
    asm("mov.b64 %0, {%1, %1};" : "=l"(r) : "f"(a));
    return r;
}
__device__ __forceinline__ void ffma2(unsigned long long& d, unsigned long long a,
                                      unsigned long long b) {
    asm("fma.rn.f32x2 %0, %1, %2, %0;" : "+l"(d) : "l"(a), "l"(b));
}
__device__ __forceinline__ float2 unpack2(unsigned long long v) {
    float2 f;
    asm("mov.b64 {%0, %1}, %2;" : "=f"(f.x), "=f"(f.y) : "l"(v));
    return f;
}

__global__ __launch_bounds__(256, 2) void sgemm_q(
    const int M, const int N, const int K,
    const float* __restrict__ A, const float* __restrict__ B, float* __restrict__ C)
{
    constexpr int BK = 8;
    __shared__ __align__(16) float As[2][BK][128];
    __shared__ __align__(16) float Bs[2][BK][128];
    const int tid = threadIdx.x;
    const int tRow = tid >> 4, tCol = tid & 15;
    const int bRow = blockIdx.y, bCol = blockIdx.x;
    const int aRow = tid >> 1, aCol = (tid & 1) * 4;
    const int bRowi = tid >> 5, bColi = (tid & 31) * 4;

    const float* Ag = A + (size_t)(bRow * 128 + aRow) * K + aCol;
    const float* Bg = B + (size_t)bRowi * N + (size_t)bCol * 128 + bColi;

    unsigned long long acc[8][4];
    #pragma unroll
    for (int i = 0; i < 8; i++)
        #pragma unroll
        for (int j = 0; j < 4; j++) acc[i][j] = 0ull;

    {
        float4 a0 = *(const float4*)Ag;
        unsigned bdst = (unsigned)__cvta_generic_to_shared(&Bs[0][bRowi][bColi]);
        asm volatile("cp.async.cg.shared.global [%0], [%1], 16;" :: "r"(bdst), "l"(Bg));
        asm volatile("cp.async.commit_group;");
        As[0][aCol + 0][aRow] = a0.x; As[0][aCol + 1][aRow] = a0.y;
        As[0][aCol + 2][aRow] = a0.z; As[0][aCol + 3][aRow] = a0.w;
        asm volatile("cp.async.wait_group 0;");
    }
    __syncthreads();

    const int NKB = K / BK;
    for (int kb = 0; kb < NKB; kb++) {
        const int buf = kb & 1;
        float4 an;
        if (kb + 1 < NKB) {
            an = *(const float4*)(Ag + (size_t)(kb + 1) * BK);
            unsigned bdst = (unsigned)__cvta_generic_to_shared(&Bs[buf ^ 1][bRowi][bColi]);
            asm volatile("cp.async.cg.shared.global [%0], [%1], 16;"
                         :: "r"(bdst), "l"(Bg + (size_t)(kb + 1) * BK * N));
            asm volatile("cp.async.commit_group;");
        }
        #pragma unroll
        for (int k = 0; k < BK; k++) {
            ulonglong2 n01 = *(const ulonglong2*)(&Bs[buf][k][tCol * 8]);
            ulonglong2 n23 = *(const ulonglong2*)(&Bs[buf][k][tCol * 8 + 4]);
            float4 m0 = *(const float4*)(&As[buf][k][tRow * 8]);
            float4 m1 = *(const float4*)(&As[buf][k][tRow * 8 + 4]);
            float mr[8] = {m0.x, m0.y, m0.z, m0.w, m1.x, m1.y, m1.z, m1.w};
            #pragma unroll
            for (int i = 0; i < 8; i++) {
                unsigned long long mm = pack_dup(mr[i]);
                ffma2(acc[i][0], mm, n01.x);
                ffma2(acc[i][1], mm, n01.y);
                ffma2(acc[i][2], mm, n23.x);
                ffma2(acc[i][3], mm, n23.y);
            }
        }
        if (kb + 1 < NKB) {
            As[buf ^ 1][aCol + 0][aRow] = an.x; As[buf ^ 1][aCol + 1][aRow] = an.y;
            As[buf ^ 1][aCol + 2][aRow] = an.z; As[buf ^ 1][aCol + 3][aRow] = an.w;
            asm volatile("cp.async.wait_group 0;");
        }
        __syncthreads();
    }

    float* Cb = C + (size_t)bRow * 128 * N + (size_t)bCol * 128;
    #pragma unroll
    for (int i = 0; i < 8; i++) {
        size_t rowOff = (size_t)(tRow * 8 + i) * N + tCol * 8;
        #pragma unroll
        for (int j2 = 0; j2 < 4; j2++) {
            float2 p = unpack2(acc[i][j2]);
            *(float2*)(Cb + rowOff + 2 * j2) = p;
        }
    }
}

// ---------------------------------------------------------------------------
// Product-key routing + two-level top-k
// ---------------------------------------------------------------------------
__global__ void routing_topk_kernel(
    const float* __restrict__ Q, const float* __restrict__ keys,
    float* __restrict__ out_scores, int* __restrict__ out_idx)
{
    const int j = blockIdx.x;
    const int t = threadIdx.x;
    __shared__ float q0[64], q1[64];
    __shared__ float r0[64], r1[64];
    __shared__ float cs[64];
    __shared__ int   ci[64];

    const int half = j & 1;
    const int tokA = (j >> 1);
    const int tokB = 4096 + (j >> 1);
    q0[t] = Q[tokA * RET + half * 64 + t];
    q1[t] = Q[tokB * RET + half * 64 + t];
    __syncthreads();

    float s0 = 0.f, s1 = 0.f;
    #pragma unroll
    for (int d = 0; d < 64; d++) {
        s0 += q0[d] * keys[d * 64 + t];
        s1 += q1[d] * keys[4096 + d * 64 + t];
    }
    r0[t] = s0;
    r1[t] = s1;
    __syncthreads();

    if (t == 0) {
        float v0[TOPK], v1[TOPK];
        int   i0[TOPK], i1[TOPK];
        unsigned long long u0 = 0ull, u1 = 0ull;
        for (int p = 0; p < TOPK; p++) {
            float best = -INFINITY; int bi = 0;
            for (int k = 0; k < 64; k++)
                if (!((u0 >> k) & 1ull) && r0[k] > best) { best = r0[k]; bi = k; }
            v0[p] = best; i0[p] = bi; u0 |= 1ull << bi;
            best = -INFINITY; bi = 0;
            for (int k = 0; k < 64; k++)
                if (!((u1 >> k) & 1ull) && r1[k] > best) { best = r1[k]; bi = k; }
            v1[p] = best; i1[p] = bi; u1 |= 1ull << bi;
        }
        for (int a = 0; a < TOPK; a++)
            for (int b = 0; b < TOPK; b++) {
                cs[a * TOPK + b] = v0[a] + v1[b];
                ci[a * TOPK + b] = i0[a] * NKEY + i1[b];
            }
        unsigned long long uc = 0ull;
        for (int p = 0; p < TOPK; p++) {
            float best = -INFINITY; int bi = 0;
            for (int q = 0; q < 64; q++)
                if (!((uc >> q) & 1ull) && cs[q] > best) { best = cs[q]; bi = q; }
            out_scores[j * TOPK + p] = best;
            out_idx[j * TOPK + p]    = ci[bi];
            uc |= 1ull << bi;
        }
    }
}

// ---------------------------------------------------------------------------
// Expert branch
// ---------------------------------------------------------------------------
__global__ __launch_bounds__(256) void experts_kernel(
    const float* __restrict__ X, const float* __restrict__ down_e,
    const float* __restrict__ up_e, const float* __restrict__ scores,
    const int* __restrict__ idx, float* __restrict__ out)
{
    const int j = blockIdx.x;
    const int tid = threadIdx.x;
    const int wid = tid >> 5;
    const int lane = tid & 31;

    __shared__ float xs[HID];
    __shared__ float ew[TOPK];
    __shared__ float w[TOPK];

    for (int h4 = tid; h4 < HID / 4; h4 += 256)
        *(float4*)(&xs[h4 * 4]) = *(const float4*)(X + (size_t)j * HID + h4 * 4);
    __syncthreads();

    {
        const int e = idx[j * TOPK + wid];
        const float* de = down_e + (size_t)e * HID;
        float s = 0.f;
        for (int h = lane * 4; h < HID; h += 32 * 4) {
            float4 d = *(const float4*)(de + h);
            s += xs[h] * d.x + xs[h+1] * d.y + xs[h+2] * d.z + xs[h+3] * d.w;
        }
        #pragma unroll
        for (int o = 16; o; o >>= 1) s += __shfl_xor_sync(0xffffffffu, s, o);
        if (lane == 0) ew[wid] = s;
    }
    __syncthreads();

    if (tid == 0) {
        float sc[TOPK], m = -INFINITY;
        #pragma unroll
        for (int k = 0; k < TOPK; k++) { sc[k] = scores[j * TOPK + k]; m = fmaxf(m, sc[k]); }
        float den = 0.f;
        #pragma unroll
        for (int k = 0; k < TOPK; k++) { sc[k] = expf(sc[k] - m); den += sc[k]; }
        #pragma unroll
        for (int k = 0; k < TOPK; k++) {
            float e_ = ew[k];
            w[k] = (e_ / (1.f + expf(-e_))) * sc[k] / den;
        }
    }
    __syncthreads();

    int   eidx[TOPK];
    float wk[TOPK];
    #pragma unroll
    for (int k = 0; k < TOPK; k++) { eidx[k] = idx[j * TOPK + k]; wk[k] = w[k]; }

    for (int h = tid * 4; h < HID; h += 256 * 4) {
        float4 acc = make_float4(0.f, 0.f, 0.f, 0.f);
        #pragma unroll
        for (int k = 0; k < TOPK; k++) {
            float4 u = *(const float4*)(up_e + (size_t)eidx[k] * HID + h);
            acc.x += wk[k] * u.x; acc.y += wk[k] * u.y;
            acc.z += wk[k] * u.z; acc.w += wk[k] * u.w;
        }
        *(float4*)(out + (size_t)j * HID + h) = acc;
    }
}

// ---------------------------------------------------------------------------
// Launch
// ---------------------------------------------------------------------------
extern "C" void kernel_launch(void* const* d_in, const int* in_sizes, int n_in,
                              void* d_out, int out_size)
{
    const float* x      = (const float*)d_in[0];
    const float* wq     = (const float*)d_in[1];
    const float* keys   = (const float*)d_in[2];
    const float* down_e = (const float*)d_in[3];
    const float* up_e   = (const float*)d_in[4];
    const float* gate_w = (const float*)d_in[5];
    const float* up_w   = (const float*)d_in[6];
    const float* down_w = (const float*)d_in[7];
    float* out = (float*)d_out;

    float *q_ptr, *scr_ptr;
    int   *idx_ptr;
    __half *xh, *xl, *gw, *uw, *dw, *act;
    cudaGetSymbolAddress((void**)&q_ptr,   g_q);
    cudaGetSymbolAddress((void**)&scr_ptr, g_scores);
    cudaGetSymbolAddress((void**)&idx_ptr, g_idx);
    cudaGetSymbolAddress((void**)&xh,  g_xh);
    cudaGetSymbolAddress((void**)&xl,  g_xl);
    cudaGetSymbolAddress((void**)&gw,  g_gw);
    cudaGetSymbolAddress((void**)&uw,  g_uw);
    cudaGetSymbolAddress((void**)&dw,  g_dw);
    cudaGetSymbolAddress((void**)&act, g_act);

    cudaFuncSetAttribute(gemm_gu, cudaFuncAttributeMaxDynamicSharedMemorySize, 2 * STAGE_GU);
    cudaFuncSetAttribute(gemm_dn, cudaFuncAttributeMaxDynamicSharedMemorySize, 2 * STAGE_DN);

    // conversions
    conv_xh<<<(NTOK * HID / 4 + 255) / 256, 256>>>(x, xh, xl, (size_t)NTOK * HID / 4);
    tconv_h<<<dim3(INTER / 32, HID / 32), dim3(32, 8)>>>(gate_w, gw, HID, INTER);
    tconv_h<<<dim3(INTER / 32, HID / 32), dim3(32, 8)>>>(up_w,   uw, HID, INTER);
    tconv_h<<<dim3(HID / 32, INTER / 32), dim3(32, 8)>>>(down_w, dw, INTER, HID);

    // routing branch (fp32 exact)
    sgemm_q<<<dim3(RET / 128, NTOK / 128), 256>>>(NTOK, RET, HID, x, wq, q_ptr);
    routing_topk_kernel<<<NTOK, 64>>>(q_ptr, keys, scr_ptr, idx_ptr);
    experts_kernel<<<NTOK, 256>>>(x, down_e, up_e, scr_ptr, idx_ptr, out);

    // dense MLP: fused gate+up, then down (accumulates onto experts output)
    gemm_gu<<<dim3(INTER / 128, NTOK / 128), 512, 2 * STAGE_GU>>>(
        xh, xl, gw, uw, act);
    gemm_dn<<<dim3(HID / 256, NTOK / 128), 512, 2 * STAGE_DN>>>(
        act, dw, out);
}

// round 8
// speedup vs baseline: 7.2986x; 1.3664x over previous
#include <cuda_runtime.h>
#include <cuda_fp16.h>
#include <math.h>
#include <stdint.h>

// Problem constants
#define NTOK   8192
#define HID    2048
#define INTER  8192
#define RET    128
#define NKEY   64
#define TOPK   8
#define NEXP   4096

// ---------------------------------------------------------------------------
// Scratch (device globals — no allocation allowed)
// ---------------------------------------------------------------------------
__device__ float g_q[NTOK * RET];
__device__ float g_scores[NTOK * TOPK];
__device__ int   g_idx[NTOK * TOPK];
__device__ __half g_xh[(size_t)NTOK * HID];        // X fp16
__device__ __half g_gw[(size_t)INTER * HID];       // gate_w^T fp16 [8192,2048]
__device__ __half g_uw[(size_t)INTER * HID];       // up_w^T   fp16 [8192,2048]
__device__ __half g_dw[(size_t)HID * INTER];       // down_w^T fp16 [2048,8192]
__device__ __half g_act[(size_t)NTOK * INTER];     // act fp16

// ---------------------------------------------------------------------------
// PTX helpers
// ---------------------------------------------------------------------------
__device__ __forceinline__ void cpasync16(uint32_t dst, const void* src) {
    asm volatile("cp.async.cg.shared.global [%0], [%1], 16;" :: "r"(dst), "l"(src));
}
__device__ __forceinline__ void ldsm4(uint32_t* r, uint32_t addr) {
    asm volatile("ldmatrix.sync.aligned.m8n8.x4.shared.b16 {%0,%1,%2,%3}, [%4];"
                 : "=r"(r[0]), "=r"(r[1]), "=r"(r[2]), "=r"(r[3]) : "r"(addr));
}
__device__ __forceinline__ void mma16816(float* c, const uint32_t* a, const uint32_t* b) {
    asm volatile(
        "mma.sync.aligned.m16n8k16.row.col.f32.f16.f16.f32 "
        "{%0,%1,%2,%3}, {%4,%5,%6,%7}, {%8,%9}, {%0,%1,%2,%3};"
        : "+f"(c[0]), "+f"(c[1]), "+f"(c[2]), "+f"(c[3])
        : "r"(a[0]), "r"(a[1]), "r"(a[2]), "r"(a[3]), "r"(b[0]), "r"(b[1]));
}
__device__ __forceinline__ uint32_t smem_addr(const void* p) {
    uint32_t a;
    asm("{ .reg .u64 t; cvta.to.shared.u64 t, %1; cvt.u32.u64 %0, t; }" : "=r"(a) : "l"(p));
    return a;
}

#define STAGE_GU 49152    // A, Bg, Bu x 16KB
#define STAGE_DN 49152    // A 16KB + B 32KB

// ---------------------------------------------------------------------------
// Fused gate+up GEMM (plain fp16):
//   act = silu(X@gate_w) * (X@up_w) -> fp16
// 512 threads = 16 warps (4m x 4n), warp tile 32x32 per GEMM. BK=64.
// ---------------------------------------------------------------------------
__global__ __launch_bounds__(512, 1) void gemm_gu(
    const __half* __restrict__ A,
    const __half* __restrict__ Bg, const __half* __restrict__ Bu,
    __half* __restrict__ O)
{
    extern __shared__ __align__(128) char dynsmem[];
    const int K  = HID;
    const int NN = INTER;
    const int tid = threadIdx.x, lane = tid & 31, wid = tid >> 5;
    const int wm = wid & 3, wn = wid >> 2;
    const int rowA = blockIdx.y * 128, rowB = blockIdx.x * 128;
    const uint32_t sbase = smem_addr(dynsmem);

    auto load_stage = [&](uint32_t db0, int kk) {
        #pragma unroll
        for (int i = 0; i < 6; i++) {
            int ch = i * 512 + tid;
            int t = ch >> 10, local = ch & 1023;
            int r = local >> 3, c = local & 7;
            const __half* P = (t == 0 ? A : t == 1 ? Bg : Bu)
                              + (size_t)((t == 0 ? rowA : rowB) + r) * K + kk;
            uint32_t off = ((uint32_t)(r * 128 + c * 16)) ^ (uint32_t)((r & 7) << 4);
            cpasync16(db0 + t * 16384 + off, (const char*)P + c * 16);
        }
        asm volatile("cp.async.commit_group;" ::: "memory");
    };

    uint32_t rawA[2], xA[2];
    #pragma unroll
    for (int mi = 0; mi < 2; mi++) {
        uint32_t r = (uint32_t)(wm * 32 + mi * 16 + (lane & 15));
        rawA[mi] = r * 128 + ((lane >> 4) * 16);
        xA[mi]   = (rawA[mi] >> 3) & 0x70;
    }
    uint32_t rawB[2], xB[2];
    #pragma unroll
    for (int g = 0; g < 2; g++) {
        uint32_t r = (uint32_t)(wn * 32 + g * 16 + (lane & 7) + ((lane >> 4) << 3));
        rawB[g] = r * 128 + (((lane >> 3) & 1) * 16);
        xB[g]   = (rawB[g] >> 3) & 0x70;
    }

    float ag[2][4][4], au[2][4][4];
    #pragma unroll
    for (int i = 0; i < 2; i++)
        #pragma unroll
        for (int j = 0; j < 4; j++)
            #pragma unroll
            for (int q = 0; q < 4; q++) { ag[i][j][q] = 0.f; au[i][j][q] = 0.f; }

    load_stage(sbase, 0);
    asm volatile("cp.async.wait_group 0;" ::: "memory");
    __syncthreads();

    const int NKB = K / 64;
    for (int kb = 0; kb < NKB; kb++) {
        const uint32_t cur = sbase + (uint32_t)(kb & 1) * STAGE_GU;
        if (kb + 1 < NKB)
            load_stage(sbase + (uint32_t)((kb + 1) & 1) * STAGE_GU, (kb + 1) * 64);

        #pragma unroll
        for (int ks = 0; ks < 4; ks++) {
            uint32_t aF[2][4], bG[2][4], bU[2][4];
            #pragma unroll
            for (int mi = 0; mi < 2; mi++)
                ldsm4(aF[mi], cur + ((rawA[mi] + ks * 32) ^ xA[mi]));
            #pragma unroll
            for (int g = 0; g < 2; g++) {
                uint32_t o = (rawB[g] + ks * 32) ^ xB[g];
                ldsm4(bG[g], cur + 16384 + o);
                ldsm4(bU[g], cur + 32768 + o);
            }
            #pragma unroll
            for (int mi = 0; mi < 2; mi++)
                #pragma unroll
                for (int g = 0; g < 2; g++)
                    #pragma unroll
                    for (int hh = 0; hh < 2; hh++) {
                        mma16816(ag[mi][g * 2 + hh], aF[mi], &bG[g][hh * 2]);
                        mma16816(au[mi][g * 2 + hh], aF[mi], &bU[g][hh * 2]);
                    }
        }
        if (kb + 1 < NKB)
            asm volatile("cp.async.wait_group 0;" ::: "memory");
        __syncthreads();
    }

    // epilogue: act = silu(gate)*up -> fp16
    const int rOff = lane >> 2, cOff = (lane & 3) * 2;
    #pragma unroll
    for (int mi = 0; mi < 2; mi++)
        #pragma unroll
        for (int nf = 0; nf < 4; nf++)
            #pragma unroll
            for (int hh = 0; hh < 2; hh++) {
                const int rr = rowA + wm * 32 + mi * 16 + rOff + hh * 8;
                const int cc = rowB + wn * 32 + nf * 8 + cOff;
                const size_t pos = (size_t)rr * NN + cc;
                float g0 = ag[mi][nf][hh * 2 + 0], g1 = ag[mi][nf][hh * 2 + 1];
                float u0 = au[mi][nf][hh * 2 + 0], u1 = au[mi][nf][hh * 2 + 1];
                float y0 = (g0 / (1.f + expf(-g0))) * u0;
                float y1 = (g1 / (1.f + expf(-g1))) * u1;
                *(__half2*)(O + pos) =
                    __halves2half2(__float2half_rn(y0), __float2half_rn(y1));
            }
}

// ---------------------------------------------------------------------------
// Down GEMM (fp16): out += act @ down_w
// CTA tile 128(M) x 256(N), BK=64. 512 threads = 16 warps (4m x 4n),
// warp tile 32x64. Tiles/stage: A(16K) + B(32K) = 48KB.
// ---------------------------------------------------------------------------
__global__ __launch_bounds__(512, 1) void gemm_dn(
    const __half* __restrict__ A,
    const __half* __restrict__ B, float* __restrict__ C)
{
    extern __shared__ __align__(128) char dynsmem[];
    const int K  = INTER;
    const int NN = HID;
    const int tid = threadIdx.x, lane = tid & 31, wid = tid >> 5;
    const int wm = wid & 3, wn = wid >> 2;
    const int rowA = blockIdx.y * 128, rowB = blockIdx.x * 256;
    const uint32_t sbase = smem_addr(dynsmem);

    auto load_stage = [&](uint32_t db0, int kk) {
        #pragma unroll
        for (int i = 0; i < 6; i++) {
            int ch = i * 512 + tid;
            const __half* P;
            uint32_t dst;
            if (ch < 1024) {
                int r = ch >> 3, c = ch & 7;
                P = A + (size_t)(rowA + r) * K + kk + c * 8;
                uint32_t off = ((uint32_t)(r * 128 + c * 16)) ^ (uint32_t)((r & 7) << 4);
                dst = db0 + off;
            } else {
                int local = ch - 1024;
                int r = local >> 3, c = local & 7;
                P = B + (size_t)(rowB + r) * K + kk + c * 8;
                uint32_t off = ((uint32_t)(r * 128 + c * 16)) ^ (uint32_t)((r & 7) << 4);
                dst = db0 + 16384 + off;
            }
            cpasync16(dst, P);
        }
        asm volatile("cp.async.commit_group;" ::: "memory");
    };

    uint32_t rawA[2], xA[2];
    #pragma unroll
    for (int mi = 0; mi < 2; mi++) {
        uint32_t r = (uint32_t)(wm * 32 + mi * 16 + (lane & 15));
        rawA[mi] = r * 128 + ((lane >> 4) * 16);
        xA[mi]   = (rawA[mi] >> 3) & 0x70;
    }
    uint32_t rawB[4], xB[4];
    #pragma unroll
    for (int g = 0; g < 4; g++) {
        uint32_t r = (uint32_t)(wn * 64 + g * 16 + (lane & 7) + ((lane >> 4) << 3));
        rawB[g] = r * 128 + (((lane >> 3) & 1) * 16);
        xB[g]   = (rawB[g] >> 3) & 0x70;
    }

    float acc[2][8][4];
    #pragma unroll
    for (int i = 0; i < 2; i++)
        #pragma unroll
        for (int j = 0; j < 8; j++)
            #pragma unroll
            for (int q = 0; q < 4; q++) acc[i][j][q] = 0.f;

    load_stage(sbase, 0);
    asm volatile("cp.async.wait_group 0;" ::: "memory");
    __syncthreads();

    const int NKB = K / 64;
    for (int kb = 0; kb < NKB; kb++) {
        const uint32_t cur = sbase + (uint32_t)(kb & 1) * STAGE_DN;
        if (kb + 1 < NKB)
            load_stage(sbase + (uint32_t)((kb + 1) & 1) * STAGE_DN, (kb + 1) * 64);

        #pragma unroll
        for (int ks = 0; ks < 4; ks++) {
            uint32_t aH[2][4], bR[4][4];
            #pragma unroll
            for (int mi = 0; mi < 2; mi++)
                ldsm4(aH[mi], cur + ((rawA[mi] + ks * 32) ^ xA[mi]));
            #pragma unroll
            for (int g = 0; g < 4; g++)
                ldsm4(bR[g], cur + 16384 + ((rawB[g] + ks * 32) ^ xB[g]));
            #pragma unroll
            for (int mi = 0; mi < 2; mi++)
                #pragma unroll
                for (int g = 0; g < 4; g++)
                    #pragma unroll
                    for (int hh = 0; hh < 2; hh++)
                        mma16816(acc[mi][g * 2 + hh], aH[mi], &bR[g][hh * 2]);
        }
        if (kb + 1 < NKB)
            asm volatile("cp.async.wait_group 0;" ::: "memory");
        __syncthreads();
    }

    // epilogue: out += v
    const int rOff = lane >> 2, cOff = (lane & 3) * 2;
    #pragma unroll
    for (int mi = 0; mi < 2; mi++)
        #pragma unroll
        for (int nf = 0; nf < 8; nf++)
            #pragma unroll
            for (int hh = 0; hh < 2; hh++) {
                const int rr = rowA + wm * 32 + mi * 16 + rOff + hh * 8;
                const int cc = rowB + wn * 64 + nf * 8 + cOff;
                const size_t pos = (size_t)rr * NN + cc;
                float2 o = *(const float2*)(C + pos);
                o.x += acc[mi][nf][hh * 2 + 0];
                o.y += acc[mi][nf][hh * 2 + 1];
                *(float2*)(C + pos) = o;
            }
}

// ---------------------------------------------------------------------------
// Conversions
// ---------------------------------------------------------------------------
__global__ void conv_x(const float* __restrict__ in, __half* __restrict__ o, size_t n4)
{
    size_t i = (size_t)blockIdx.x * blockDim.x + threadIdx.x;
    if (i >= n4) return;
    float4 v = *(const float4*)(in + i * 4);
    *(__half2*)(o + i * 4)     = __halves2half2(__float2half_rn(v.x), __float2half_rn(v.y));
    *(__half2*)(o + i * 4 + 2) = __halves2half2(__float2half_rn(v.z), __float2half_rn(v.w));
}

__global__ void tconv_h(const float* __restrict__ in, __half* __restrict__ o,
                        int R, int C)
{
    __shared__ float t[32][33];
    const int c0 = blockIdx.x * 32, r0 = blockIdx.y * 32;
    const int tx = threadIdx.x, ty = threadIdx.y;
    #pragma unroll
    for (int i = 0; i < 4; i++)
        t[ty + i * 8][tx] = in[(size_t)(r0 + ty + i * 8) * C + c0 + tx];
    __syncthreads();
    #pragma unroll
    for (int i = 0; i < 4; i++)
        o[(size_t)(c0 + ty + i * 8) * R + r0 + tx] = __float2half_rn(t[tx][ty + i * 8]);
}

// ---------------------------------------------------------------------------
// f32x2 SGEMM for the Q projection (fp32 exact — routing is rank-sensitive)
// ---------------------------------------------------------------------------
__device__ __forceinline__ unsigned long long pack_dup(float a) {
    unsigned long long r;
    asm("mov.b64 %0, {%1, %1};" : "=l"(r) : "f"(a));
    return r;
}
__device__ __forceinline__ void ffma2(unsigned long long& d, unsigned long long a,
                                      unsigned long long b) {
    asm("fma.rn.f32x2 %0, %1, %2, %0;" : "+l"(d) : "l"(a), "l"(b));
}
__device__ __forceinline__ float2 unpack2(unsigned long long v) {
    float2 f;
    asm("mov.b64 {%0, %1}, %2;" : "=f"(f.x), "=f"(f.y) : "l"(v));
    return f;
}

__global__ __launch_bounds__(256, 2) void sgemm_q(
    const int M, const int N, const int K,
    const float* __restrict__ A, const float* __restrict__ B, float* __restrict__ C)
{
    constexpr int BK = 8;
    __shared__ __align__(16) float As[2][BK][128];
    __shared__ __align__(16) float Bs[2][BK][128];
    const int tid = threadIdx.x;
    const int tRow = tid >> 4, tCol = tid & 15;
    const int bRow = blockIdx.y, bCol = blockIdx.x;
    const int aRow = tid >> 1, aCol = (tid & 1) * 4;
    const int bRowi = tid >> 5, bColi = (tid & 31) * 4;

    const float* Ag = A + (size_t)(bRow * 128 + aRow) * K + aCol;
    const float* Bg = B + (size_t)bRowi * N + (size_t)bCol * 128 + bColi;

    unsigned long long acc[8][4];
    #pragma unroll
    for (int i = 0; i < 8; i++)
        #pragma unroll
        for (int j = 0; j < 4; j++) acc[i][j] = 0ull;

    {
        float4 a0 = *(const float4*)Ag;
        unsigned bdst = (unsigned)__cvta_generic_to_shared(&Bs[0][bRowi][bColi]);
        asm volatile("cp.async.cg.shared.global [%0], [%1], 16;" :: "r"(bdst), "l"(Bg));
        asm volatile("cp.async.commit_group;");
        As[0][aCol + 0][aRow] = a0.x; As[0][aCol + 1][aRow] = a0.y;
        As[0][aCol + 2][aRow] = a0.z; As[0][aCol + 3][aRow] = a0.w;
        asm volatile("cp.async.wait_group 0;");
    }
    __syncthreads();

    const int NKB = K / BK;
    for (int kb = 0; kb < NKB; kb++) {
        const int buf = kb & 1;
        float4 an;
        if (kb + 1 < NKB) {
            an = *(const float4*)(Ag + (size_t)(kb + 1) * BK);
            unsigned bdst = (unsigned)__cvta_generic_to_shared(&Bs[buf ^ 1][bRowi][bColi]);
            asm volatile("cp.async.cg.shared.global [%0], [%1], 16;"
                         :: "r"(bdst), "l"(Bg + (size_t)(kb + 1) * BK * N));
            asm volatile("cp.async.commit_group;");
        }
        #pragma unroll
        for (int k = 0; k < BK; k++) {
            ulonglong2 n01 = *(const ulonglong2*)(&Bs[buf][k][tCol * 8]);
            ulonglong2 n23 = *(const ulonglong2*)(&Bs[buf][k][tCol * 8 + 4]);
            float4 m0 = *(const float4*)(&As[buf][k][tRow * 8]);
            float4 m1 = *(const float4*)(&As[buf][k][tRow * 8 + 4]);
            float mr[8] = {m0.x, m0.y, m0.z, m0.w, m1.x, m1.y, m1.z, m1.w};
            #pragma unroll
            for (int i = 0; i < 8; i++) {
                unsigned long long mm = pack_dup(mr[i]);
                ffma2(acc[i][0], mm, n01.x);
                ffma2(acc[i][1], mm, n01.y);
                ffma2(acc[i][2], mm, n23.x);
                ffma2(acc[i][3], mm, n23.y);
            }
        }
        if (kb + 1 < NKB) {
            As[buf ^ 1][aCol + 0][aRow] = an.x; As[buf ^ 1][aCol + 1][aRow] = an.y;
            As[buf ^ 1][aCol + 2][aRow] = an.z; As[buf ^ 1][aCol + 3][aRow] = an.w;
            asm volatile("cp.async.wait_group 0;");
        }
        __syncthreads();
    }

    float* Cb = C + (size_t)bRow * 128 * N + (size_t)bCol * 128;
    #pragma unroll
    for (int i = 0; i < 8; i++) {
        size_t rowOff = (size_t)(tRow * 8 + i) * N + tCol * 8;
        #pragma unroll
        for (int j2 = 0; j2 < 4; j2++) {
            float2 p = unpack2(acc[i][j2]);
            *(float2*)(Cb + rowOff + 2 * j2) = p;
        }
    }
}

// ---------------------------------------------------------------------------
// Product-key routing + two-level top-k
// ---------------------------------------------------------------------------
__global__ void routing_topk_kernel(
    const float* __restrict__ Q, const float* __restrict__ keys,
    float* __restrict__ out_scores, int* __restrict__ out_idx)
{
    const int j = blockIdx.x;
    const int t = threadIdx.x;
    __shared__ float q0[64], q1[64];
    __shared__ float r0[64], r1[64];
    __shared__ float cs[64];
    __shared__ int   ci[64];

    const int half = j & 1;
    const int tokA = (j >> 1);
    const int tokB = 4096 + (j >> 1);
    q0[t] = Q[tokA * RET + half * 64 + t];
    q1[t] = Q[tokB * RET + half * 64 + t];
    __syncthreads();

    float s0 = 0.f, s1 = 0.f;
    #pragma unroll
    for (int d = 0; d < 64; d++) {
        s0 += q0[d] * keys[d * 64 + t];
        s1 += q1[d] * keys[4096 + d * 64 + t];
    }
    r0[t] = s0;
    r1[t] = s1;
    __syncthreads();

    if (t == 0) {
        float v0[TOPK], v1[TOPK];
        int   i0[TOPK], i1[TOPK];
        unsigned long long u0 = 0ull, u1 = 0ull;
        for (int p = 0; p < TOPK; p++) {
            float best = -INFINITY; int bi = 0;
            for (int k = 0; k < 64; k++)
                if (!((u0 >> k) & 1ull) && r0[k] > best) { best = r0[k]; bi = k; }
            v0[p] = best; i0[p] = bi; u0 |= 1ull << bi;
            best = -INFINITY; bi = 0;
            for (int k = 0; k < 64; k++)
                if (!((u1 >> k) & 1ull) && r1[k] > best) { best = r1[k]; bi = k; }
            v1[p] = best; i1[p] = bi; u1 |= 1ull << bi;
        }
        for (int a = 0; a < TOPK; a++)
            for (int b = 0; b < TOPK; b++) {
                cs[a * TOPK + b] = v0[a] + v1[b];
                ci[a * TOPK + b] = i0[a] * NKEY + i1[b];
            }
        unsigned long long uc = 0ull;
        for (int p = 0; p < TOPK; p++) {
            float best = -INFINITY; int bi = 0;
            for (int q = 0; q < 64; q++)
                if (!((uc >> q) & 1ull) && cs[q] > best) { best = cs[q]; bi = q; }
            out_scores[j * TOPK + p] = best;
            out_idx[j * TOPK + p]    = ci[bi];
            uc |= 1ull << bi;
        }
    }
}

// ---------------------------------------------------------------------------
// Expert branch
// ---------------------------------------------------------------------------
__global__ __launch_bounds__(256) void experts_kernel(
    const float* __restrict__ X, const float* __restrict__ down_e,
    const float* __restrict__ up_e, const float* __restrict__ scores,
    const int* __restrict__ idx, float* __restrict__ out)
{
    const int j = blockIdx.x;
    const int tid = threadIdx.x;
    const int wid = tid >> 5;
    const int lane = tid & 31;

    __shared__ float xs[HID];
    __shared__ float ew[TOPK];
    __shared__ float w[TOPK];

    for (int h4 = tid; h4 < HID / 4; h4 += 256)
        *(float4*)(&xs[h4 * 4]) = *(const float4*)(X + (size_t)j * HID + h4 * 4);
    __syncthreads();

    {
        const int e = idx[j * TOPK + wid];
        const float* de = down_e + (size_t)e * HID;
        float s = 0.f;
        for (int h = lane * 4; h < HID; h += 32 * 4) {
            float4 d = *(const float4*)(de + h);
            s += xs[h] * d.x + xs[h+1] * d.y + xs[h+2] * d.z + xs[h+3] * d.w;
        }
        #pragma unroll
        for (int o = 16; o; o >>= 1) s += __shfl_xor_sync(0xffffffffu, s, o);
        if (lane == 0) ew[wid] = s;
    }
    __syncthreads();

    if (tid == 0) {
        float sc[TOPK], m = -INFINITY;
        #pragma unroll
        for (int k = 0; k < TOPK; k++) { sc[k] = scores[j * TOPK + k]; m = fmaxf(m, sc[k]); }
        float den = 0.f;
        #pragma unroll
        for (int k = 0; k < TOPK; k++) { sc[k] = expf(sc[k] - m); den += sc[k]; }
        #pragma unroll
        for (int k = 0; k < TOPK; k++) {
            float e_ = ew[k];
            w[k] = (e_ / (1.f + expf(-e_))) * sc[k] / den;
        }
    }
    __syncthreads();

    int   eidx[TOPK];
    float wk[TOPK];
    #pragma unroll
    for (int k = 0; k < TOPK; k++) { eidx[k] = idx[j * TOPK + k]; wk[k] = w[k]; }

    for (int h = tid * 4; h < HID; h += 256 * 4) {
        float4 acc = make_float4(0.f, 0.f, 0.f, 0.f);
        #pragma unroll
        for (int k = 0; k < TOPK; k++) {
            float4 u = *(const float4*)(up_e + (size_t)eidx[k] * HID + h);
            acc.x += wk[k] * u.x; acc.y += wk[k] * u.y;
            acc.z += wk[k] * u.z; acc.w += wk[k] * u.w;
        }
        *(float4*)(out + (size_t)j * HID + h) = acc;
    }
}

// ---------------------------------------------------------------------------
// Launch
// ---------------------------------------------------------------------------
extern "C" void kernel_launch(void* const* d_in, const int* in_sizes, int n_in,
                              void* d_out, int out_size)
{
    const float* x      = (const float*)d_in[0];
    const float* wq     = (const float*)d_in[1];
    const float* keys   = (const float*)d_in[2];
    const float* down_e = (const float*)d_in[3];
    const float* up_e   = (const float*)d_in[4];
    const float* gate_w = (const float*)d_in[5];
    const float* up_w   = (const float*)d_in[6];
    const float* down_w = (const float*)d_in[7];
    float* out = (float*)d_out;

    float *q_ptr, *scr_ptr;
    int   *idx_ptr;
    __half *xh, *gw, *uw, *dw, *act;
    cudaGetSymbolAddress((void**)&q_ptr,   g_q);
    cudaGetSymbolAddress((void**)&scr_ptr, g_scores);
    cudaGetSymbolAddress((void**)&idx_ptr, g_idx);
    cudaGetSymbolAddress((void**)&xh,  g_xh);
    cudaGetSymbolAddress((void**)&gw,  g_gw);
    cudaGetSymbolAddress((void**)&uw,  g_uw);
    cudaGetSymbolAddress((void**)&dw,  g_dw);
    cudaGetSymbolAddress((void**)&act, g_act);

    cudaFuncSetAttribute(gemm_gu, cudaFuncAttributeMaxDynamicSharedMemorySize, 2 * STAGE_GU);
    cudaFuncSetAttribute(gemm_dn, cudaFuncAttributeMaxDynamicSharedMemorySize, 2 * STAGE_DN);

    // conversions
    conv_x<<<(NTOK * HID / 4 + 255) / 256, 256>>>(x, xh, (size_t)NTOK * HID / 4);
    tconv_h<<<dim3(INTER / 32, HID / 32), dim3(32, 8)>>>(gate_w, gw, HID, INTER);
    tconv_h<<<dim3(INTER / 32, HID / 32), dim3(32, 8)>>>(up_w,   uw, HID, INTER);
    tconv_h<<<dim3(HID / 32, INTER / 32), dim3(32, 8)>>>(down_w, dw, INTER, HID);

    // routing branch (fp32 exact)
    sgemm_q<<<dim3(RET / 128, NTOK / 128), 256>>>(NTOK, RET, HID, x, wq, q_ptr);
    routing_topk_kernel<<<NTOK, 64>>>(q_ptr, keys, scr_ptr, idx_ptr);
    experts_kernel<<<NTOK, 256>>>(x, down_e, up_e, scr_ptr, idx_ptr, out);

    // dense MLP: fused gate+up, then down (accumulates onto experts output)
    gemm_gu<<<dim3(INTER / 128, NTOK / 128), 512, 2 * STAGE_GU>>>(xh, gw, uw, act);
    gemm_dn<<<dim3(HID / 256, NTOK / 128), 512, 2 * STAGE_DN>>>(act, dw, out);
}

// round 9
// speedup vs baseline: 7.6552x; 1.0489x over previous
#include <cuda_runtime.h>
#include <cuda_fp16.h>
#include <math.h>
#include <stdint.h>

// Problem constants
#define NTOK   8192
#define HID    2048
#define INTER  8192
#define RET    128
#define NKEY   64
#define TOPK   8
#define NEXP   4096

// ---------------------------------------------------------------------------
// Scratch (device globals — no allocation allowed)
// ---------------------------------------------------------------------------
__device__ float g_q[NTOK * RET];
__device__ float g_scores[NTOK * TOPK];
__device__ int   g_idx[NTOK * TOPK];
__device__ __half g_xh[(size_t)NTOK * HID];        // X fp16
__device__ __half g_gw[(size_t)INTER * HID];       // gate_w^T fp16 [8192,2048]
__device__ __half g_uw[(size_t)INTER * HID];       // up_w^T   fp16 [8192,2048]
__device__ __half g_dw[(size_t)HID * INTER];       // down_w^T fp16 [2048,8192]
__device__ __half g_act[(size_t)NTOK * INTER];     // act fp16

// ---------------------------------------------------------------------------
// PTX helpers
// ---------------------------------------------------------------------------
__device__ __forceinline__ void cpasync16(uint32_t dst, const void* src) {
    asm volatile("cp.async.cg.shared.global [%0], [%1], 16;" :: "r"(dst), "l"(src));
}
__device__ __forceinline__ void ldsm4(uint32_t* r, uint32_t addr) {
    asm volatile("ldmatrix.sync.aligned.m8n8.x4.shared.b16 {%0,%1,%2,%3}, [%4];"
                 : "=r"(r[0]), "=r"(r[1]), "=r"(r[2]), "=r"(r[3]) : "r"(addr));
}
__device__ __forceinline__ void mma16816(float* c, const uint32_t* a, const uint32_t* b) {
    asm volatile(
        "mma.sync.aligned.m16n8k16.row.col.f32.f16.f16.f32 "
        "{%0,%1,%2,%3}, {%4,%5,%6,%7}, {%8,%9}, {%0,%1,%2,%3};"
        : "+f"(c[0]), "+f"(c[1]), "+f"(c[2]), "+f"(c[3])
        : "r"(a[0]), "r"(a[1]), "r"(a[2]), "r"(a[3]), "r"(b[0]), "r"(b[1]));
}
__device__ __forceinline__ uint32_t smem_addr(const void* p) {
    uint32_t a;
    asm("{ .reg .u64 t; cvta.to.shared.u64 t, %1; cvt.u32.u64 %0, t; }" : "=r"(a) : "l"(p));
    return a;
}

#define STAGE_GU 49152    // A, Bg, Bu x 16KB
#define STAGE_DN 49152    // A 16KB + B 32KB
#define WAIT_G1() asm volatile("cp.async.wait_group 1;" ::: "memory")
#define WAIT_G0() asm volatile("cp.async.wait_group 0;" ::: "memory")

// ---------------------------------------------------------------------------
// Fused gate+up GEMM (fp16): act = silu(X@gate_w) * (X@up_w) -> fp16
// 512 threads = 16 warps (4m x 4n), warp tile 32x32 per GEMM. BK=64.
// 3-stage cp.async pipeline.
// ---------------------------------------------------------------------------
__global__ __launch_bounds__(512, 1) void gemm_gu(
    const __half* __restrict__ A,
    const __half* __restrict__ Bg, const __half* __restrict__ Bu,
    __half* __restrict__ O)
{
    extern __shared__ __align__(128) char dynsmem[];
    const int K  = HID;
    const int NN = INTER;
    const int tid = threadIdx.x, lane = tid & 31, wid = tid >> 5;
    const int wm = wid & 3, wn = wid >> 2;
    const int rowA = blockIdx.y * 128, rowB = blockIdx.x * 128;
    const uint32_t sbase = smem_addr(dynsmem);

    auto load_stage = [&](uint32_t db0, int kk) {
        #pragma unroll
        for (int i = 0; i < 6; i++) {
            int ch = i * 512 + tid;
            int t = ch >> 10, local = ch & 1023;
            int r = local >> 3, c = local & 7;
            const __half* P = (t == 0 ? A : t == 1 ? Bg : Bu)
                              + (size_t)((t == 0 ? rowA : rowB) + r) * K + kk;
            uint32_t off = ((uint32_t)(r * 128 + c * 16)) ^ (uint32_t)((r & 7) << 4);
            cpasync16(db0 + t * 16384 + off, (const char*)P + c * 16);
        }
        asm volatile("cp.async.commit_group;" ::: "memory");
    };

    uint32_t rawA[2], xA[2];
    #pragma unroll
    for (int mi = 0; mi < 2; mi++) {
        uint32_t r = (uint32_t)(wm * 32 + mi * 16 + (lane & 15));
        rawA[mi] = r * 128 + ((lane >> 4) * 16);
        xA[mi]   = (rawA[mi] >> 3) & 0x70;
    }
    uint32_t rawB[2], xB[2];
    #pragma unroll
    for (int g = 0; g < 2; g++) {
        uint32_t r = (uint32_t)(wn * 32 + g * 16 + (lane & 7) + ((lane >> 4) << 3));
        rawB[g] = r * 128 + (((lane >> 3) & 1) * 16);
        xB[g]   = (rawB[g] >> 3) & 0x70;
    }

    float ag[2][4][4], au[2][4][4];
    #pragma unroll
    for (int i = 0; i < 2; i++)
        #pragma unroll
        for (int j = 0; j < 4; j++)
            #pragma unroll
            for (int q = 0; q < 4; q++) { ag[i][j][q] = 0.f; au[i][j][q] = 0.f; }

    const int NKB = K / 64;   // 32
    load_stage(sbase, 0);
    load_stage(sbase + STAGE_GU, 64);
    WAIT_G1();
    __syncthreads();

    for (int kb = 0; kb < NKB; kb++) {
        const uint32_t cur = sbase + (uint32_t)(kb % 3) * STAGE_GU;
        if (kb + 2 < NKB)
            load_stage(sbase + (uint32_t)((kb + 2) % 3) * STAGE_GU, (kb + 2) * 64);

        #pragma unroll
        for (int ks = 0; ks < 4; ks++) {
            uint32_t aF[2][4], bG[2][4], bU[2][4];
            #pragma unroll
            for (int mi = 0; mi < 2; mi++)
                ldsm4(aF[mi], cur + ((rawA[mi] + ks * 32) ^ xA[mi]));
            #pragma unroll
            for (int g = 0; g < 2; g++) {
                uint32_t o = (rawB[g] + ks * 32) ^ xB[g];
                ldsm4(bG[g], cur + 16384 + o);
                ldsm4(bU[g], cur + 32768 + o);
            }
            #pragma unroll
            for (int mi = 0; mi < 2; mi++)
                #pragma unroll
                for (int g = 0; g < 2; g++)
                    #pragma unroll
                    for (int hh = 0; hh < 2; hh++) {
                        mma16816(ag[mi][g * 2 + hh], aF[mi], &bG[g][hh * 2]);
                        mma16816(au[mi][g * 2 + hh], aF[mi], &bU[g][hh * 2]);
                    }
        }
        if (kb + 1 < NKB) {
            if (kb + 2 < NKB) WAIT_G1(); else WAIT_G0();
        }
        __syncthreads();
    }

    // epilogue: act = silu(gate)*up -> fp16
    const int rOff = lane >> 2, cOff = (lane & 3) * 2;
    #pragma unroll
    for (int mi = 0; mi < 2; mi++)
        #pragma unroll
        for (int nf = 0; nf < 4; nf++)
            #pragma unroll
            for (int hh = 0; hh < 2; hh++) {
                const int rr = rowA + wm * 32 + mi * 16 + rOff + hh * 8;
                const int cc = rowB + wn * 32 + nf * 8 + cOff;
                const size_t pos = (size_t)rr * NN + cc;
                float g0 = ag[mi][nf][hh * 2 + 0], g1 = ag[mi][nf][hh * 2 + 1];
                float u0 = au[mi][nf][hh * 2 + 0], u1 = au[mi][nf][hh * 2 + 1];
                float y0 = (g0 / (1.f + expf(-g0))) * u0;
                float y1 = (g1 / (1.f + expf(-g1))) * u1;
                *(__half2*)(O + pos) =
                    __halves2half2(__float2half_rn(y0), __float2half_rn(y1));
            }
}

// ---------------------------------------------------------------------------
// Down GEMM (fp16): out += act @ down_w
// CTA tile 128(M) x 256(N), BK=64. 512 threads = 16 warps (4m x 4n),
// warp tile 32x64. 3-stage pipeline.
// ---------------------------------------------------------------------------
__global__ __launch_bounds__(512, 1) void gemm_dn(
    const __half* __restrict__ A,
    const __half* __restrict__ B, float* __restrict__ C)
{
    extern __shared__ __align__(128) char dynsmem[];
    const int K  = INTER;
    const int NN = HID;
    const int tid = threadIdx.x, lane = tid & 31, wid = tid >> 5;
    const int wm = wid & 3, wn = wid >> 2;
    const int rowA = blockIdx.y * 128, rowB = blockIdx.x * 256;
    const uint32_t sbase = smem_addr(dynsmem);

    auto load_stage = [&](uint32_t db0, int kk) {
        #pragma unroll
        for (int i = 0; i < 6; i++) {
            int ch = i * 512 + tid;
            const __half* P;
            uint32_t dst;
            if (ch < 1024) {
                int r = ch >> 3, c = ch & 7;
                P = A + (size_t)(rowA + r) * K + kk + c * 8;
                uint32_t off = ((uint32_t)(r * 128 + c * 16)) ^ (uint32_t)((r & 7) << 4);
                dst = db0 + off;
            } else {
                int local = ch - 1024;
                int r = local >> 3, c = local & 7;
                P = B + (size_t)(rowB + r) * K + kk + c * 8;
                uint32_t off = ((uint32_t)(r * 128 + c * 16)) ^ (uint32_t)((r & 7) << 4);
                dst = db0 + 16384 + off;
            }
            cpasync16(dst, P);
        }
        asm volatile("cp.async.commit_group;" ::: "memory");
    };

    uint32_t rawA[2], xA[2];
    #pragma unroll
    for (int mi = 0; mi < 2; mi++) {
        uint32_t r = (uint32_t)(wm * 32 + mi * 16 + (lane & 15));
        rawA[mi] = r * 128 + ((lane >> 4) * 16);
        xA[mi]   = (rawA[mi] >> 3) & 0x70;
    }
    uint32_t rawB[4], xB[4];
    #pragma unroll
    for (int g = 0; g < 4; g++) {
        uint32_t r = (uint32_t)(wn * 64 + g * 16 + (lane & 7) + ((lane >> 4) << 3));
        rawB[g] = r * 128 + (((lane >> 3) & 1) * 16);
        xB[g]   = (rawB[g] >> 3) & 0x70;
    }

    float acc[2][8][4];
    #pragma unroll
    for (int i = 0; i < 2; i++)
        #pragma unroll
        for (int j = 0; j < 8; j++)
            #pragma unroll
            for (int q = 0; q < 4; q++) acc[i][j][q] = 0.f;

    const int NKB = K / 64;   // 128
    load_stage(sbase, 0);
    load_stage(sbase + STAGE_DN, 64);
    WAIT_G1();
    __syncthreads();

    for (int kb = 0; kb < NKB; kb++) {
        const uint32_t cur = sbase + (uint32_t)(kb % 3) * STAGE_DN;
        if (kb + 2 < NKB)
            load_stage(sbase + (uint32_t)((kb + 2) % 3) * STAGE_DN, (kb + 2) * 64);

        #pragma unroll
        for (int ks = 0; ks < 4; ks++) {
            uint32_t aH[2][4], bR[4][4];
            #pragma unroll
            for (int mi = 0; mi < 2; mi++)
                ldsm4(aH[mi], cur + ((rawA[mi] + ks * 32) ^ xA[mi]));
            #pragma unroll
            for (int g = 0; g < 4; g++)
                ldsm4(bR[g], cur + 16384 + ((rawB[g] + ks * 32) ^ xB[g]));
            #pragma unroll
            for (int mi = 0; mi < 2; mi++)
                #pragma unroll
                for (int g = 0; g < 4; g++)
                    #pragma unroll
                    for (int hh = 0; hh < 2; hh++)
                        mma16816(acc[mi][g * 2 + hh], aH[mi], &bR[g][hh * 2]);
        }
        if (kb + 1 < NKB) {
            if (kb + 2 < NKB) WAIT_G1(); else WAIT_G0();
        }
        __syncthreads();
    }

    // epilogue: out += v
    const int rOff = lane >> 2, cOff = (lane & 3) * 2;
    #pragma unroll
    for (int mi = 0; mi < 2; mi++)
        #pragma unroll
        for (int nf = 0; nf < 8; nf++)
            #pragma unroll
            for (int hh = 0; hh < 2; hh++) {
                const int rr = rowA + wm * 32 + mi * 16 + rOff + hh * 8;
                const int cc = rowB + wn * 64 + nf * 8 + cOff;
                const size_t pos = (size_t)rr * NN + cc;
                float2 o = *(const float2*)(C + pos);
                o.x += acc[mi][nf][hh * 2 + 0];
                o.y += acc[mi][nf][hh * 2 + 1];
                *(float2*)(C + pos) = o;
            }
}

// ---------------------------------------------------------------------------
// Conversions
// ---------------------------------------------------------------------------
__global__ void conv_x(const float* __restrict__ in, __half* __restrict__ o, size_t n4)
{
    size_t i = (size_t)blockIdx.x * blockDim.x + threadIdx.x;
    if (i >= n4) return;
    float4 v = *(const float4*)(in + i * 4);
    *(__half2*)(o + i * 4)     = __halves2half2(__float2half_rn(v.x), __float2half_rn(v.y));
    *(__half2*)(o + i * 4 + 2) = __halves2half2(__float2half_rn(v.z), __float2half_rn(v.w));
}

__global__ void tconv_h(const float* __restrict__ in, __half* __restrict__ o,
                        int R, int C)
{
    __shared__ float t[32][33];
    const int c0 = blockIdx.x * 32, r0 = blockIdx.y * 32;
    const int tx = threadIdx.x, ty = threadIdx.y;
    #pragma unroll
    for (int i = 0; i < 4; i++)
        t[ty + i * 8][tx] = in[(size_t)(r0 + ty + i * 8) * C + c0 + tx];
    __syncthreads();
    #pragma unroll
    for (int i = 0; i < 4; i++)
        o[(size_t)(c0 + ty + i * 8) * R + r0 + tx] = __float2half_rn(t[tx][ty + i * 8]);
}

// ---------------------------------------------------------------------------
// f32x2 SGEMM for the Q projection (fp32 exact — routing is rank-sensitive)
// ---------------------------------------------------------------------------
__device__ __forceinline__ unsigned long long pack_dup(float a) {
    unsigned long long r;
    asm("mov.b64 %0, {%1, %1};" : "=l"(r) : "f"(a));
    return r;
}
__device__ __forceinline__ void ffma2(unsigned long long& d, unsigned long long a,
                                      unsigned long long b) {
    asm("fma.rn.f32x2 %0, %1, %2, %0;" : "+l"(d) : "l"(a), "l"(b));
}
__device__ __forceinline__ float2 unpack2(unsigned long long v) {
    float2 f;
    asm("mov.b64 {%0, %1}, %2;" : "=f"(f.x), "=f"(f.y) : "l"(v));
    return f;
}

__global__ __launch_bounds__(256, 2) void sgemm_q(
    const int M, const int N, const int K,
    const float* __restrict__ A, const float* __restrict__ B, float* __restrict__ C)
{
    constexpr int BK = 8;
    __shared__ __align__(16) float As[2][BK][128];
    __shared__ __align__(16) float Bs[2][BK][128];
    const int tid = threadIdx.x;
    const int tRow = tid >> 4, tCol = tid & 15;
    const int bRow = blockIdx.y, bCol = blockIdx.x;
    const int aRow = tid >> 1, aCol = (tid & 1) * 4;
    const int bRowi = tid >> 5, bColi = (tid & 31) * 4;

    const float* Ag = A + (size_t)(bRow * 128 + aRow) * K + aCol;
    const float* Bg = B + (size_t)bRowi * N + (size_t)bCol * 128 + bColi;

    unsigned long long acc[8][4];
    #pragma unroll
    for (int i = 0; i < 8; i++)
        #pragma unroll
        for (int j = 0; j < 4; j++) acc[i][j] = 0ull;

    {
        float4 a0 = *(const float4*)Ag;
        unsigned bdst = (unsigned)__cvta_generic_to_shared(&Bs[0][bRowi][bColi]);
        asm volatile("cp.async.cg.shared.global [%0], [%1], 16;" :: "r"(bdst), "l"(Bg));
        asm volatile("cp.async.commit_group;");
        As[0][aCol + 0][aRow] = a0.x; As[0][aCol + 1][aRow] = a0.y;
        As[0][aCol + 2][aRow] = a0.z; As[0][aCol + 3][aRow] = a0.w;
        asm volatile("cp.async.wait_group 0;");
    }
    __syncthreads();

    const int NKB = K / BK;
    for (int kb = 0; kb < NKB; kb++) {
        const int buf = kb & 1;
        float4 an;
        if (kb + 1 < NKB) {
            an = *(const float4*)(Ag + (size_t)(kb + 1) * BK);
            unsigned bdst = (unsigned)__cvta_generic_to_shared(&Bs[buf ^ 1][bRowi][bColi]);
            asm volatile("cp.async.cg.shared.global [%0], [%1], 16;"
                         :: "r"(bdst), "l"(Bg + (size_t)(kb + 1) * BK * N));
            asm volatile("cp.async.commit_group;");
        }
        #pragma unroll
        for (int k = 0; k < BK; k++) {
            ulonglong2 n01 = *(const ulonglong2*)(&Bs[buf][k][tCol * 8]);
            ulonglong2 n23 = *(const ulonglong2*)(&Bs[buf][k][tCol * 8 + 4]);
            float4 m0 = *(const float4*)(&As[buf][k][tRow * 8]);
            float4 m1 = *(const float4*)(&As[buf][k][tRow * 8 + 4]);
            float mr[8] = {m0.x, m0.y, m0.z, m0.w, m1.x, m1.y, m1.z, m1.w};
            #pragma unroll
            for (int i = 0; i < 8; i++) {
                unsigned long long mm = pack_dup(mr[i]);
                ffma2(acc[i][0], mm, n01.x);
                ffma2(acc[i][1], mm, n01.y);
                ffma2(acc[i][2], mm, n23.x);
                ffma2(acc[i][3], mm, n23.y);
            }
        }
        if (kb + 1 < NKB) {
            As[buf ^ 1][aCol + 0][aRow] = an.x; As[buf ^ 1][aCol + 1][aRow] = an.y;
            As[buf ^ 1][aCol + 2][aRow] = an.z; As[buf ^ 1][aCol + 3][aRow] = an.w;
            asm volatile("cp.async.wait_group 0;");
        }
        __syncthreads();
    }

    float* Cb = C + (size_t)bRow * 128 * N + (size_t)bCol * 128;
    #pragma unroll
    for (int i = 0; i < 8; i++) {
        size_t rowOff = (size_t)(tRow * 8 + i) * N + tCol * 8;
        #pragma unroll
        for (int j2 = 0; j2 < 4; j2++) {
            float2 p = unpack2(acc[i][j2]);
            *(float2*)(Cb + rowOff + 2 * j2) = p;
        }
    }
}

// ---------------------------------------------------------------------------
// Product-key routing + two-level top-k
// ---------------------------------------------------------------------------
__global__ void routing_topk_kernel(
    const float* __restrict__ Q, const float* __restrict__ keys,
    float* __restrict__ out_scores, int* __restrict__ out_idx)
{
    const int j = blockIdx.x;
    const int t = threadIdx.x;
    __shared__ float q0[64], q1[64];
    __shared__ float r0[64], r1[64];
    __shared__ float cs[64];
    __shared__ int   ci[64];

    const int half = j & 1;
    const int tokA = (j >> 1);
    const int tokB = 4096 + (j >> 1);
    q0[t] = Q[tokA * RET + half * 64 + t];
    q1[t] = Q[tokB * RET + half * 64 + t];
    __syncthreads();

    float s0 = 0.f, s1 = 0.f;
    #pragma unroll
    for (int d = 0; d < 64; d++) {
        s0 += q0[d] * keys[d * 64 + t];
        s1 += q1[d] * keys[4096 + d * 64 + t];
    }
    r0[t] = s0;
    r1[t] = s1;
    __syncthreads();

    if (t == 0) {
        float v0[TOPK], v1[TOPK];
        int   i0[TOPK], i1[TOPK];
        unsigned long long u0 = 0ull, u1 = 0ull;
        for (int p = 0; p < TOPK; p++) {
            float best = -INFINITY; int bi = 0;
            for (int k = 0; k < 64; k++)
                if (!((u0 >> k) & 1ull) && r0[k] > best) { best = r0[k]; bi = k; }
            v0[p] = best; i0[p] = bi; u0 |= 1ull << bi;
            best = -INFINITY; bi = 0;
            for (int k = 0; k < 64; k++)
                if (!((u1 >> k) & 1ull) && r1[k] > best) { best = r1[k]; bi = k; }
            v1[p] = best; i1[p] = bi; u1 |= 1ull << bi;
        }
        for (int a = 0; a < TOPK; a++)
            for (int b = 0; b < TOPK; b++) {
                cs[a * TOPK + b] = v0[a] + v1[b];
                ci[a * TOPK + b] = i0[a] * NKEY + i1[b];
            }
        unsigned long long uc = 0ull;
        for (int p = 0; p < TOPK; p++) {
            float best = -INFINITY; int bi = 0;
            for (int q = 0; q < 64; q++)
                if (!((uc >> q) & 1ull) && cs[q] > best) { best = cs[q]; bi = q; }
            out_scores[j * TOPK + p] = best;
            out_idx[j * TOPK + p]    = ci[bi];
            uc |= 1ull << bi;
        }
    }
}

// ---------------------------------------------------------------------------
// Expert branch
// ---------------------------------------------------------------------------
__global__ __launch_bounds__(256) void experts_kernel(
    const float* __restrict__ X, const float* __restrict__ down_e,
    const float* __restrict__ up_e, const float* __restrict__ scores,
    const int* __restrict__ idx, float* __restrict__ out)
{
    const int j = blockIdx.x;
    const int tid = threadIdx.x;
    const int wid = tid >> 5;
    const int lane = tid & 31;

    __shared__ float xs[HID];
    __shared__ float ew[TOPK];
    __shared__ float w[TOPK];

    for (int h4 = tid; h4 < HID / 4; h4 += 256)
        *(float4*)(&xs[h4 * 4]) = *(const float4*)(X + (size_t)j * HID + h4 * 4);
    __syncthreads();

    {
        const int e = idx[j * TOPK + wid];
        const float* de = down_e + (size_t)e * HID;
        float s = 0.f;
        for (int h = lane * 4; h < HID; h += 32 * 4) {
            float4 d = *(const float4*)(de + h);
            s += xs[h] * d.x + xs[h+1] * d.y + xs[h+2] * d.z + xs[h+3] * d.w;
        }
        #pragma unroll
        for (int o = 16; o; o >>= 1) s += __shfl_xor_sync(0xffffffffu, s, o);
        if (lane == 0) ew[wid] = s;
    }
    __syncthreads();

    if (tid == 0) {
        float sc[TOPK], m = -INFINITY;
        #pragma unroll
        for (int k = 0; k < TOPK; k++) { sc[k] = scores[j * TOPK + k]; m = fmaxf(m, sc[k]); }
        float den = 0.f;
        #pragma unroll
        for (int k = 0; k < TOPK; k++) { sc[k] = expf(sc[k] - m); den += sc[k]; }
        #pragma unroll
        for (int k = 0; k < TOPK; k++) {
            float e_ = ew[k];
            w[k] = (e_ / (1.f + expf(-e_))) * sc[k] / den;
        }
    }
    __syncthreads();

    int   eidx[TOPK];
    float wk[TOPK];
    #pragma unroll
    for (int k = 0; k < TOPK; k++) { eidx[k] = idx[j * TOPK + k]; wk[k] = w[k]; }

    for (int h = tid * 4; h < HID; h += 256 * 4) {
        float4 acc = make_float4(0.f, 0.f, 0.f, 0.f);
        #pragma unroll
        for (int k = 0; k < TOPK; k++) {
            float4 u = *(const float4*)(up_e + (size_t)eidx[k] * HID + h);
            acc.x += wk[k] * u.x; acc.y += wk[k] * u.y;
            acc.z += wk[k] * u.z; acc.w += wk[k] * u.w;
        }
        *(float4*)(out + (size_t)j * HID + h) = acc;
    }
}

// ---------------------------------------------------------------------------
// Launch: fork a second stream for the independent routing/experts branch.
//   Stream A (caller's): conv_x -> tconv gw -> tconv uw -> gemm_gu -> [join] -> gemm_dn
//   Stream B:            sgemm_q -> routing -> experts(out) -> tconv dw
// ---------------------------------------------------------------------------
extern "C" void kernel_launch(void* const* d_in, const int* in_sizes, int n_in,
                              void* d_out, int out_size)
{
    const float* x      = (const float*)d_in[0];
    const float* wq     = (const float*)d_in[1];
    const float* keys   = (const float*)d_in[2];
    const float* down_e = (const float*)d_in[3];
    const float* up_e   = (const float*)d_in[4];
    const float* gate_w = (const float*)d_in[5];
    const float* up_w   = (const float*)d_in[6];
    const float* down_w = (const float*)d_in[7];
    float* out = (float*)d_out;

    float *q_ptr, *scr_ptr;
    int   *idx_ptr;
    __half *xh, *gw, *uw, *dw, *act;
    cudaGetSymbolAddress((void**)&q_ptr,   g_q);
    cudaGetSymbolAddress((void**)&scr_ptr, g_scores);
    cudaGetSymbolAddress((void**)&idx_ptr, g_idx);
    cudaGetSymbolAddress((void**)&xh,  g_xh);
    cudaGetSymbolAddress((void**)&gw,  g_gw);
    cudaGetSymbolAddress((void**)&uw,  g_uw);
    cudaGetSymbolAddress((void**)&dw,  g_dw);
    cudaGetSymbolAddress((void**)&act, g_act);

    cudaFuncSetAttribute(gemm_gu, cudaFuncAttributeMaxDynamicSharedMemorySize, 3 * STAGE_GU);
    cudaFuncSetAttribute(gemm_dn, cudaFuncAttributeMaxDynamicSharedMemorySize, 3 * STAGE_DN);

    static cudaStream_t sB = nullptr;
    static cudaEvent_t evF = nullptr, evJ = nullptr;
    if (sB == nullptr) {
        cudaStreamCreateWithFlags(&sB, cudaStreamNonBlocking);
        cudaEventCreateWithFlags(&evF, cudaEventDisableTiming);
        cudaEventCreateWithFlags(&evJ, cudaEventDisableTiming);
    }

    // fork
    cudaEventRecord(evF, 0);
    cudaStreamWaitEvent(sB, evF, 0);

    // ---- stream B: routing branch + dw conversion ----
    sgemm_q<<<dim3(RET / 128, NTOK / 128), 256, 0, sB>>>(NTOK, RET, HID, x, wq, q_ptr);
    routing_topk_kernel<<<NTOK, 64, 0, sB>>>(q_ptr, keys, scr_ptr, idx_ptr);
    experts_kernel<<<NTOK, 256, 0, sB>>>(x, down_e, up_e, scr_ptr, idx_ptr, out);
    tconv_h<<<dim3(HID / 32, INTER / 32), dim3(32, 8), 0, sB>>>(down_w, dw, INTER, HID);
    cudaEventRecord(evJ, sB);

    // ---- stream A: dense MLP path ----
    conv_x<<<(NTOK * HID / 4 + 255) / 256, 256>>>(x, xh, (size_t)NTOK * HID / 4);
    tconv_h<<<dim3(INTER / 32, HID / 32), dim3(32, 8)>>>(gate_w, gw, HID, INTER);
    tconv_h<<<dim3(INTER / 32, HID / 32), dim3(32, 8)>>>(up_w,   uw, HID, INTER);
    gemm_gu<<<dim3(INTER / 128, NTOK / 128), 512, 3 * STAGE_GU>>>(xh, gw, uw, act);

    // join: dn needs act (A), dw (B) and experts' out (B)
    cudaStreamWaitEvent(0, evJ, 0);
    gemm_dn<<<dim3(HID / 256, NTOK / 128), 512, 3 * STAGE_DN>>>(act, dw, out);
}

// round 10
// speedup vs baseline: 7.6650x; 1.0013x over previous
#include <cuda_runtime.h>
#include <cuda_fp16.h>
#include <math.h>
#include <stdint.h>

// Problem constants
#define NTOK   8192
#define HID    2048
#define INTER  8192
#define RET    128
#define NKEY   64
#define TOPK   8
#define NEXP   4096

// ---------------------------------------------------------------------------
// Scratch (device globals — no allocation allowed)
// ---------------------------------------------------------------------------
__device__ float g_q[NTOK * RET];
__device__ float g_scores[NTOK * TOPK];
__device__ int   g_idx[NTOK * TOPK];
__device__ __half g_xh[(size_t)NTOK * HID];        // X fp16
__device__ __half g_gw[(size_t)INTER * HID];       // gate_w^T fp16 [8192,2048]
__device__ __half g_uw[(size_t)INTER * HID];       // up_w^T   fp16 [8192,2048]
__device__ __half g_dw[(size_t)HID * INTER];       // down_w^T fp16 [2048,8192]
__device__ __half g_act[(size_t)NTOK * INTER];     // act fp16

// ---------------------------------------------------------------------------
// PTX helpers
// ---------------------------------------------------------------------------
__device__ __forceinline__ void cpasync16(uint32_t dst, const void* src) {
    asm volatile("cp.async.cg.shared.global [%0], [%1], 16;" :: "r"(dst), "l"(src));
}
__device__ __forceinline__ void ldsm4(uint32_t* r, uint32_t addr) {
    asm volatile("ldmatrix.sync.aligned.m8n8.x4.shared.b16 {%0,%1,%2,%3}, [%4];"
                 : "=r"(r[0]), "=r"(r[1]), "=r"(r[2]), "=r"(r[3]) : "r"(addr));
}
__device__ __forceinline__ void mma16816(float* c, const uint32_t* a, const uint32_t* b) {
    asm volatile(
        "mma.sync.aligned.m16n8k16.row.col.f32.f16.f16.f32 "
        "{%0,%1,%2,%3}, {%4,%5,%6,%7}, {%8,%9}, {%0,%1,%2,%3};"
        : "+f"(c[0]), "+f"(c[1]), "+f"(c[2]), "+f"(c[3])
        : "r"(a[0]), "r"(a[1]), "r"(a[2]), "r"(a[3]), "r"(b[0]), "r"(b[1]));
}
__device__ __forceinline__ uint32_t smem_addr(const void* p) {
    uint32_t a;
    asm("{ .reg .u64 t; cvta.to.shared.u64 t, %1; cvt.u32.u64 %0, t; }" : "=r"(a) : "l"(p));
    return a;
}

#define STAGE_GU 49152    // A, Bg, Bu x 16KB
#define STAGE_DN 49152    // A 16KB + B 32KB
#define WAIT_G1() asm volatile("cp.async.wait_group 1;" ::: "memory")
#define WAIT_G0() asm volatile("cp.async.wait_group 0;" ::: "memory")

// ---------------------------------------------------------------------------
// Fused gate+up GEMM (fp16): act = silu(X@gate_w) * (X@up_w) -> fp16
// 512 threads = 16 warps (4m x 4n), warp tile 32x32 per GEMM. BK=64.
// 3-stage cp.async pipeline.
// ---------------------------------------------------------------------------
__global__ __launch_bounds__(512, 1) void gemm_gu(
    const __half* __restrict__ A,
    const __half* __restrict__ Bg, const __half* __restrict__ Bu,
    __half* __restrict__ O)
{
    extern __shared__ __align__(128) char dynsmem[];
    const int K  = HID;
    const int NN = INTER;
    const int tid = threadIdx.x, lane = tid & 31, wid = tid >> 5;
    const int wm = wid & 3, wn = wid >> 2;
    const int rowA = blockIdx.y * 128, rowB = blockIdx.x * 128;
    const uint32_t sbase = smem_addr(dynsmem);

    auto load_stage = [&](uint32_t db0, int kk) {
        #pragma unroll
        for (int i = 0; i < 6; i++) {
            int ch = i * 512 + tid;
            int t = ch >> 10, local = ch & 1023;
            int r = local >> 3, c = local & 7;
            const __half* P = (t == 0 ? A : t == 1 ? Bg : Bu)
                              + (size_t)((t == 0 ? rowA : rowB) + r) * K + kk;
            uint32_t off = ((uint32_t)(r * 128 + c * 16)) ^ (uint32_t)((r & 7) << 4);
            cpasync16(db0 + t * 16384 + off, (const char*)P + c * 16);
        }
        asm volatile("cp.async.commit_group;" ::: "memory");
    };

    uint32_t rawA[2], xA[2];
    #pragma unroll
    for (int mi = 0; mi < 2; mi++) {
        uint32_t r = (uint32_t)(wm * 32 + mi * 16 + (lane & 15));
        rawA[mi] = r * 128 + ((lane >> 4) * 16);
        xA[mi]   = (rawA[mi] >> 3) & 0x70;
    }
    uint32_t rawB[2], xB[2];
    #pragma unroll
    for (int g = 0; g < 2; g++) {
        uint32_t r = (uint32_t)(wn * 32 + g * 16 + (lane & 7) + ((lane >> 4) << 3));
        rawB[g] = r * 128 + (((lane >> 3) & 1) * 16);
        xB[g]   = (rawB[g] >> 3) & 0x70;
    }

    float ag[2][4][4], au[2][4][4];
    #pragma unroll
    for (int i = 0; i < 2; i++)
        #pragma unroll
        for (int j = 0; j < 4; j++)
            #pragma unroll
            for (int q = 0; q < 4; q++) { ag[i][j][q] = 0.f; au[i][j][q] = 0.f; }

    const int NKB = K / 64;   // 32
    load_stage(sbase, 0);
    load_stage(sbase + STAGE_GU, 64);
    WAIT_G1();
    __syncthreads();

    for (int kb = 0; kb < NKB; kb++) {
        const uint32_t cur = sbase + (uint32_t)(kb % 3) * STAGE_GU;
        if (kb + 2 < NKB)
            load_stage(sbase + (uint32_t)((kb + 2) % 3) * STAGE_GU, (kb + 2) * 64);

        #pragma unroll
        for (int ks = 0; ks < 4; ks++) {
            uint32_t aF[2][4], bG[2][4], bU[2][4];
            #pragma unroll
            for (int mi = 0; mi < 2; mi++)
                ldsm4(aF[mi], cur + ((rawA[mi] + ks * 32) ^ xA[mi]));
            #pragma unroll
            for (int g = 0; g < 2; g++) {
                uint32_t o = (rawB[g] + ks * 32) ^ xB[g];
                ldsm4(bG[g], cur + 16384 + o);
                ldsm4(bU[g], cur + 32768 + o);
            }
            #pragma unroll
            for (int mi = 0; mi < 2; mi++)
                #pragma unroll
                for (int g = 0; g < 2; g++)
                    #pragma unroll
                    for (int hh = 0; hh < 2; hh++) {
                        mma16816(ag[mi][g * 2 + hh], aF[mi], &bG[g][hh * 2]);
                        mma16816(au[mi][g * 2 + hh], aF[mi], &bU[g][hh * 2]);
                    }
        }
        if (kb + 1 < NKB) {
            if (kb + 2 < NKB) WAIT_G1(); else WAIT_G0();
        }
        __syncthreads();
    }

    // epilogue: act = silu(gate)*up -> fp16
    const int rOff = lane >> 2, cOff = (lane & 3) * 2;
    #pragma unroll
    for (int mi = 0; mi < 2; mi++)
        #pragma unroll
        for (int nf = 0; nf < 4; nf++)
            #pragma unroll
            for (int hh = 0; hh < 2; hh++) {
                const int rr = rowA + wm * 32 + mi * 16 + rOff + hh * 8;
                const int cc = rowB + wn * 32 + nf * 8 + cOff;
                const size_t pos = (size_t)rr * NN + cc;
                float g0 = ag[mi][nf][hh * 2 + 0], g1 = ag[mi][nf][hh * 2 + 1];
                float u0 = au[mi][nf][hh * 2 + 0], u1 = au[mi][nf][hh * 2 + 1];
                float y0 = (g0 / (1.f + expf(-g0))) * u0;
                float y1 = (g1 / (1.f + expf(-g1))) * u1;
                *(__half2*)(O + pos) =
                    __halves2half2(__float2half_rn(y0), __float2half_rn(y1));
            }
}

// ---------------------------------------------------------------------------
// Down GEMM (fp16): out += act @ down_w
// CTA tile 128(M) x 256(N), BK=64. 512 threads = 16 warps (4m x 4n),
// warp tile 32x64. 3-stage pipeline.
// ---------------------------------------------------------------------------
__global__ __launch_bounds__(512, 1) void gemm_dn(
    const __half* __restrict__ A,
    const __half* __restrict__ B, float* __restrict__ C)
{
    extern __shared__ __align__(128) char dynsmem[];
    const int K  = INTER;
    const int NN = HID;
    const int tid = threadIdx.x, lane = tid & 31, wid = tid >> 5;
    const int wm = wid & 3, wn = wid >> 2;
    const int rowA = blockIdx.y * 128, rowB = blockIdx.x * 256;
    const uint32_t sbase = smem_addr(dynsmem);

    auto load_stage = [&](uint32_t db0, int kk) {
        #pragma unroll
        for (int i = 0; i < 6; i++) {
            int ch = i * 512 + tid;
            const __half* P;
            uint32_t dst;
            if (ch < 1024) {
                int r = ch >> 3, c = ch & 7;
                P = A + (size_t)(rowA + r) * K + kk + c * 8;
                uint32_t off = ((uint32_t)(r * 128 + c * 16)) ^ (uint32_t)((r & 7) << 4);
                dst = db0 + off;
            } else {
                int local = ch - 1024;
                int r = local >> 3, c = local & 7;
                P = B + (size_t)(rowB + r) * K + kk + c * 8;
                uint32_t off = ((uint32_t)(r * 128 + c * 16)) ^ (uint32_t)((r & 7) << 4);
                dst = db0 + 16384 + off;
            }
            cpasync16(dst, P);
        }
        asm volatile("cp.async.commit_group;" ::: "memory");
    };

    uint32_t rawA[2], xA[2];
    #pragma unroll
    for (int mi = 0; mi < 2; mi++) {
        uint32_t r = (uint32_t)(wm * 32 + mi * 16 + (lane & 15));
        rawA[mi] = r * 128 + ((lane >> 4) * 16);
        xA[mi]   = (rawA[mi] >> 3) & 0x70;
    }
    uint32_t rawB[4], xB[4];
    #pragma unroll
    for (int g = 0; g < 4; g++) {
        uint32_t r = (uint32_t)(wn * 64 + g * 16 + (lane & 7) + ((lane >> 4) << 3));
        rawB[g] = r * 128 + (((lane >> 3) & 1) * 16);
        xB[g]   = (rawB[g] >> 3) & 0x70;
    }

    float acc[2][8][4];
    #pragma unroll
    for (int i = 0; i < 2; i++)
        #pragma unroll
        for (int j = 0; j < 8; j++)
            #pragma unroll
            for (int q = 0; q < 4; q++) acc[i][j][q] = 0.f;

    const int NKB = K / 64;   // 128
    load_stage(sbase, 0);
    load_stage(sbase + STAGE_DN, 64);
    WAIT_G1();
    __syncthreads();

    for (int kb = 0; kb < NKB; kb++) {
        const uint32_t cur = sbase + (uint32_t)(kb % 3) * STAGE_DN;
        if (kb + 2 < NKB)
            load_stage(sbase + (uint32_t)((kb + 2) % 3) * STAGE_DN, (kb + 2) * 64);

        #pragma unroll
        for (int ks = 0; ks < 4; ks++) {
            uint32_t aH[2][4], bR[4][4];
            #pragma unroll
            for (int mi = 0; mi < 2; mi++)
                ldsm4(aH[mi], cur + ((rawA[mi] + ks * 32) ^ xA[mi]));
            #pragma unroll
            for (int g = 0; g < 4; g++)
                ldsm4(bR[g], cur + 16384 + ((rawB[g] + ks * 32) ^ xB[g]));
            #pragma unroll
            for (int mi = 0; mi < 2; mi++)
                #pragma unroll
                for (int g = 0; g < 4; g++)
                    #pragma unroll
                    for (int hh = 0; hh < 2; hh++)
                        mma16816(acc[mi][g * 2 + hh], aH[mi], &bR[g][hh * 2]);
        }
        if (kb + 1 < NKB) {
            if (kb + 2 < NKB) WAIT_G1(); else WAIT_G0();
        }
        __syncthreads();
    }

    // epilogue: out += v
    const int rOff = lane >> 2, cOff = (lane & 3) * 2;
    #pragma unroll
    for (int mi = 0; mi < 2; mi++)
        #pragma unroll
        for (int nf = 0; nf < 8; nf++)
            #pragma unroll
            for (int hh = 0; hh < 2; hh++) {
                const int rr = rowA + wm * 32 + mi * 16 + rOff + hh * 8;
                const int cc = rowB + wn * 64 + nf * 8 + cOff;
                const size_t pos = (size_t)rr * NN + cc;
                float2 o = *(const float2*)(C + pos);
                o.x += acc[mi][nf][hh * 2 + 0];
                o.y += acc[mi][nf][hh * 2 + 1];
                *(float2*)(C + pos) = o;
            }
}

// ---------------------------------------------------------------------------
// Conversions
// ---------------------------------------------------------------------------
__global__ void conv_x(const float* __restrict__ in, __half* __restrict__ o, size_t n4)
{
    size_t i = (size_t)blockIdx.x * blockDim.x + threadIdx.x;
    if (i >= n4) return;
    float4 v = *(const float4*)(in + i * 4);
    *(__half2*)(o + i * 4)     = __halves2half2(__float2half_rn(v.x), __float2half_rn(v.y));
    *(__half2*)(o + i * 4 + 2) = __halves2half2(__float2half_rn(v.z), __float2half_rn(v.w));
}

__global__ void tconv_h(const float* __restrict__ in, __half* __restrict__ o,
                        int R, int C)
{
    __shared__ float t[32][33];
    const int c0 = blockIdx.x * 32, r0 = blockIdx.y * 32;
    const int tx = threadIdx.x, ty = threadIdx.y;
    #pragma unroll
    for (int i = 0; i < 4; i++)
        t[ty + i * 8][tx] = in[(size_t)(r0 + ty + i * 8) * C + c0 + tx];
    __syncthreads();
    #pragma unroll
    for (int i = 0; i < 4; i++)
        o[(size_t)(c0 + ty + i * 8) * R + r0 + tx] = __float2half_rn(t[tx][ty + i * 8]);
}

// ---------------------------------------------------------------------------
// f32x2 SGEMM for the Q projection (fp32 exact — routing is rank-sensitive)
// ---------------------------------------------------------------------------
__device__ __forceinline__ unsigned long long pack_dup(float a) {
    unsigned long long r;
    asm("mov.b64 %0, {%1, %1};" : "=l"(r) : "f"(a));
    return r;
}
__device__ __forceinline__ void ffma2(unsigned long long& d, unsigned long long a,
                                      unsigned long long b) {
    asm("fma.rn.f32x2 %0, %1, %2, %0;" : "+l"(d) : "l"(a), "l"(b));
}
__device__ __forceinline__ float2 unpack2(unsigned long long v) {
    float2 f;
    asm("mov.b64 {%0, %1}, %2;" : "=f"(f.x), "=f"(f.y) : "l"(v));
    return f;
}

__global__ __launch_bounds__(256, 2) void sgemm_q(
    const int M, const int N, const int K,
    const float* __restrict__ A, const float* __restrict__ B, float* __restrict__ C)
{
    constexpr int BK = 8;
    __shared__ __align__(16) float As[2][BK][128];
    __shared__ __align__(16) float Bs[2][BK][128];
    const int tid = threadIdx.x;
    const int tRow = tid >> 4, tCol = tid & 15;
    const int bRow = blockIdx.y, bCol = blockIdx.x;
    const int aRow = tid >> 1, aCol = (tid & 1) * 4;
    const int bRowi = tid >> 5, bColi = (tid & 31) * 4;

    const float* Ag = A + (size_t)(bRow * 128 + aRow) * K + aCol;
    const float* Bg = B + (size_t)bRowi * N + (size_t)bCol * 128 + bColi;

    unsigned long long acc[8][4];
    #pragma unroll
    for (int i = 0; i < 8; i++)
        #pragma unroll
        for (int j = 0; j < 4; j++) acc[i][j] = 0ull;

    {
        float4 a0 = *(const float4*)Ag;
        unsigned bdst = (unsigned)__cvta_generic_to_shared(&Bs[0][bRowi][bColi]);
        asm volatile("cp.async.cg.shared.global [%0], [%1], 16;" :: "r"(bdst), "l"(Bg));
        asm volatile("cp.async.commit_group;");
        As[0][aCol + 0][aRow] = a0.x; As[0][aCol + 1][aRow] = a0.y;
        As[0][aCol + 2][aRow] = a0.z; As[0][aCol + 3][aRow] = a0.w;
        asm volatile("cp.async.wait_group 0;");
    }
    __syncthreads();

    const int NKB = K / BK;
    for (int kb = 0; kb < NKB; kb++) {
        const int buf = kb & 1;
        float4 an;
        if (kb + 1 < NKB) {
            an = *(const float4*)(Ag + (size_t)(kb + 1) * BK);
            unsigned bdst = (unsigned)__cvta_generic_to_shared(&Bs[buf ^ 1][bRowi][bColi]);
            asm volatile("cp.async.cg.shared.global [%0], [%1], 16;"
                         :: "r"(bdst), "l"(Bg + (size_t)(kb + 1) * BK * N));
            asm volatile("cp.async.commit_group;");
        }
        #pragma unroll
        for (int k = 0; k < BK; k++) {
            ulonglong2 n01 = *(const ulonglong2*)(&Bs[buf][k][tCol * 8]);
            ulonglong2 n23 = *(const ulonglong2*)(&Bs[buf][k][tCol * 8 + 4]);
            float4 m0 = *(const float4*)(&As[buf][k][tRow * 8]);
            float4 m1 = *(const float4*)(&As[buf][k][tRow * 8 + 4]);
            float mr[8] = {m0.x, m0.y, m0.z, m0.w, m1.x, m1.y, m1.z, m1.w};
            #pragma unroll
            for (int i = 0; i < 8; i++) {
                unsigned long long mm = pack_dup(mr[i]);
                ffma2(acc[i][0], mm, n01.x);
                ffma2(acc[i][1], mm, n01.y);
                ffma2(acc[i][2], mm, n23.x);
                ffma2(acc[i][3], mm, n23.y);
            }
        }
        if (kb + 1 < NKB) {
            As[buf ^ 1][aCol + 0][aRow] = an.x; As[buf ^ 1][aCol + 1][aRow] = an.y;
            As[buf ^ 1][aCol + 2][aRow] = an.z; As[buf ^ 1][aCol + 3][aRow] = an.w;
            asm volatile("cp.async.wait_group 0;");
        }
        __syncthreads();
    }

    float* Cb = C + (size_t)bRow * 128 * N + (size_t)bCol * 128;
    #pragma unroll
    for (int i = 0; i < 8; i++) {
        size_t rowOff = (size_t)(tRow * 8 + i) * N + tCol * 8;
        #pragma unroll
        for (int j2 = 0; j2 < 4; j2++) {
            float2 p = unpack2(acc[i][j2]);
            *(float2*)(Cb + rowOff + 2 * j2) = p;
        }
    }
}

// ---------------------------------------------------------------------------
// Product-key routing + two-level top-k
// ---------------------------------------------------------------------------
__global__ void routing_topk_kernel(
    const float* __restrict__ Q, const float* __restrict__ keys,
    float* __restrict__ out_scores, int* __restrict__ out_idx)
{
    const int j = blockIdx.x;
    const int t = threadIdx.x;
    __shared__ float q0[64], q1[64];
    __shared__ float r0[64], r1[64];
    __shared__ float cs[64];
    __shared__ int   ci[64];

    const int half = j & 1;
    const int tokA = (j >> 1);
    const int tokB = 4096 + (j >> 1);
    q0[t] = Q[tokA * RET + half * 64 + t];
    q1[t] = Q[tokB * RET + half * 64 + t];
    __syncthreads();

    float s0 = 0.f, s1 = 0.f;
    #pragma unroll
    for (int d = 0; d < 64; d++) {
        s0 += q0[d] * keys[d * 64 + t];
        s1 += q1[d] * keys[4096 + d * 64 + t];
    }
    r0[t] = s0;
    r1[t] = s1;
    __syncthreads();

    if (t == 0) {
        float v0[TOPK], v1[TOPK];
        int   i0[TOPK], i1[TOPK];
        unsigned long long u0 = 0ull, u1 = 0ull;
        for (int p = 0; p < TOPK; p++) {
            float best = -INFINITY; int bi = 0;
            for (int k = 0; k < 64; k++)
                if (!((u0 >> k) & 1ull) && r0[k] > best) { best = r0[k]; bi = k; }
            v0[p] = best; i0[p] = bi; u0 |= 1ull << bi;
            best = -INFINITY; bi = 0;
            for (int k = 0; k < 64; k++)
                if (!((u1 >> k) & 1ull) && r1[k] > best) { best = r1[k]; bi = k; }
            v1[p] = best; i1[p] = bi; u1 |= 1ull << bi;
        }
        for (int a = 0; a < TOPK; a++)
            for (int b = 0; b < TOPK; b++) {
                cs[a * TOPK + b] = v0[a] + v1[b];
                ci[a * TOPK + b] = i0[a] * NKEY + i1[b];
            }
        unsigned long long uc = 0ull;
        for (int p = 0; p < TOPK; p++) {
            float best = -INFINITY; int bi = 0;
            for (int q = 0; q < 64; q++)
                if (!((uc >> q) & 1ull) && cs[q] > best) { best = cs[q]; bi = q; }
            out_scores[j * TOPK + p] = best;
            out_idx[j * TOPK + p]    = ci[bi];
            uc |= 1ull << bi;
        }
    }
}

// ---------------------------------------------------------------------------
// Expert branch
// ---------------------------------------------------------------------------
__global__ __launch_bounds__(256) void experts_kernel(
    const float* __restrict__ X, const float* __restrict__ down_e,
    const float* __restrict__ up_e, const float* __restrict__ scores,
    const int* __restrict__ idx, float* __restrict__ out)
{
    const int j = blockIdx.x;
    const int tid = threadIdx.x;
    const int wid = tid >> 5;
    const int lane = tid & 31;

    __shared__ float xs[HID];
    __shared__ float ew[TOPK];
    __shared__ float w[TOPK];

    for (int h4 = tid; h4 < HID / 4; h4 += 256)
        *(float4*)(&xs[h4 * 4]) = *(const float4*)(X + (size_t)j * HID + h4 * 4);
    __syncthreads();

    {
        const int e = idx[j * TOPK + wid];
        const float* de = down_e + (size_t)e * HID;
        float s = 0.f;
        for (int h = lane * 4; h < HID; h += 32 * 4) {
            float4 d = *(const float4*)(de + h);
            s += xs[h] * d.x + xs[h+1] * d.y + xs[h+2] * d.z + xs[h+3] * d.w;
        }
        #pragma unroll
        for (int o = 16; o; o >>= 1) s += __shfl_xor_sync(0xffffffffu, s, o);
        if (lane == 0) ew[wid] = s;
    }
    __syncthreads();

    if (tid == 0) {
        float sc[TOPK], m = -INFINITY;
        #pragma unroll
        for (int k = 0; k < TOPK; k++) { sc[k] = scores[j * TOPK + k]; m = fmaxf(m, sc[k]); }
        float den = 0.f;
        #pragma unroll
        for (int k = 0; k < TOPK; k++) { sc[k] = expf(sc[k] - m); den += sc[k]; }
        #pragma unroll
        for (int k = 0; k < TOPK; k++) {
            float e_ = ew[k];
            w[k] = (e_ / (1.f + expf(-e_))) * sc[k] / den;
        }
    }
    __syncthreads();

    int   eidx[TOPK];
    float wk[TOPK];
    #pragma unroll
    for (int k = 0; k < TOPK; k++) { eidx[k] = idx[j * TOPK + k]; wk[k] = w[k]; }

    for (int h = tid * 4; h < HID; h += 256 * 4) {
        float4 acc = make_float4(0.f, 0.f, 0.f, 0.f);
        #pragma unroll
        for (int k = 0; k < TOPK; k++) {
            float4 u = *(const float4*)(up_e + (size_t)eidx[k] * HID + h);
            acc.x += wk[k] * u.x; acc.y += wk[k] * u.y;
            acc.z += wk[k] * u.z; acc.w += wk[k] * u.w;
        }
        *(float4*)(out + (size_t)j * HID + h) = acc;
    }
}

// ---------------------------------------------------------------------------
// Launch: fork a second stream for the independent routing/experts branch.
//   Stream A (caller's): conv_x -> tconv gw -> tconv uw -> gemm_gu -> [join] -> gemm_dn
//   Stream B:            sgemm_q -> routing -> experts(out) -> tconv dw
// ---------------------------------------------------------------------------
extern "C" void kernel_launch(void* const* d_in, const int* in_sizes, int n_in,
                              void* d_out, int out_size)
{
    const float* x      = (const float*)d_in[0];
    const float* wq     = (const float*)d_in[1];
    const float* keys   = (const float*)d_in[2];
    const float* down_e = (const float*)d_in[3];
    const float* up_e   = (const float*)d_in[4];
    const float* gate_w = (const float*)d_in[5];
    const float* up_w   = (const float*)d_in[6];
    const float* down_w = (const float*)d_in[7];
    float* out = (float*)d_out;

    float *q_ptr, *scr_ptr;
    int   *idx_ptr;
    __half *xh, *gw, *uw, *dw, *act;
    cudaGetSymbolAddress((void**)&q_ptr,   g_q);
    cudaGetSymbolAddress((void**)&scr_ptr, g_scores);
    cudaGetSymbolAddress((void**)&idx_ptr, g_idx);
    cudaGetSymbolAddress((void**)&xh,  g_xh);
    cudaGetSymbolAddress((void**)&gw,  g_gw);
    cudaGetSymbolAddress((void**)&uw,  g_uw);
    cudaGetSymbolAddress((void**)&dw,  g_dw);
    cudaGetSymbolAddress((void**)&act, g_act);

    cudaFuncSetAttribute(gemm_gu, cudaFuncAttributeMaxDynamicSharedMemorySize, 3 * STAGE_GU);
    cudaFuncSetAttribute(gemm_dn, cudaFuncAttributeMaxDynamicSharedMemorySize, 3 * STAGE_DN);

    static cudaStream_t sB = nullptr;
    static cudaEvent_t evF = nullptr, evJ = nullptr;
    if (sB == nullptr) {
        cudaStreamCreateWithFlags(&sB, cudaStreamNonBlocking);
        cudaEventCreateWithFlags(&evF, cudaEventDisableTiming);
        cudaEventCreateWithFlags(&evJ, cudaEventDisableTiming);
    }

    // fork
    cudaEventRecord(evF, 0);
    cudaStreamWaitEvent(sB, evF, 0);

    // ---- stream B: routing branch + dw conversion ----
    sgemm_q<<<dim3(RET / 128, NTOK / 128), 256, 0, sB>>>(NTOK, RET, HID, x, wq, q_ptr);
    routing_topk_kernel<<<NTOK, 64, 0, sB>>>(q_ptr, keys, scr_ptr, idx_ptr);
    experts_kernel<<<NTOK, 256, 0, sB>>>(x, down_e, up_e, scr_ptr, idx_ptr, out);
    tconv_h<<<dim3(HID / 32, INTER / 32), dim3(32, 8), 0, sB>>>(down_w, dw, INTER, HID);
    cudaEventRecord(evJ, sB);

    // ---- stream A: dense MLP path ----
    conv_x<<<(NTOK * HID / 4 + 255) / 256, 256>>>(x, xh, (size_t)NTOK * HID / 4);
    tconv_h<<<dim3(INTER / 32, HID / 32), dim3(32, 8)>>>(gate_w, gw, HID, INTER);
    tconv_h<<<dim3(INTER / 32, HID / 32), dim3(32, 8)>>>(up_w,   uw, HID, INTER);
    gemm_gu<<<dim3(INTER / 128, NTOK / 128), 512, 3 * STAGE_GU>>>(xh, gw, uw, act);

    // join: dn needs act (A), dw (B) and experts' out (B)
    cudaStreamWaitEvent(0, evJ, 0);
    gemm_dn<<<dim3(HID / 256, NTOK / 128), 512, 3 * STAGE_DN>>>(act, dw, out);
}

// round 11
// speedup vs baseline: 7.6737x; 1.0011x over previous
#include <cuda_runtime.h>
#include <cuda_fp16.h>
#include <math.h>
#include <stdint.h>

// Problem constants
#define NTOK   8192
#define HID    2048
#define INTER  8192
#define RET    128
#define NKEY   64
#define TOPK   8
#define NEXP   4096

// ---------------------------------------------------------------------------
// Scratch (device globals — no allocation allowed)
// ---------------------------------------------------------------------------
__device__ float g_q[NTOK * RET];
__device__ float g_scores[NTOK * TOPK];
__device__ int   g_idx[NTOK * TOPK];
__device__ __half g_xh[(size_t)NTOK * HID];        // X fp16
__device__ __half g_gw[(size_t)INTER * HID];       // gate_w^T fp16 [8192,2048]
__device__ __half g_uw[(size_t)INTER * HID];       // up_w^T   fp16 [8192,2048]
__device__ __half g_dw[(size_t)HID * INTER];       // down_w^T fp16 [2048,8192]
__device__ __half g_act[(size_t)NTOK * INTER];     // act fp16

// ---------------------------------------------------------------------------
// PTX helpers
// ---------------------------------------------------------------------------
__device__ __forceinline__ void cpasync16(uint32_t dst, const void* src) {
    asm volatile("cp.async.cg.shared.global [%0], [%1], 16;" :: "r"(dst), "l"(src));
}
__device__ __forceinline__ void ldsm4(uint32_t* r, uint32_t addr) {
    asm volatile("ldmatrix.sync.aligned.m8n8.x4.shared.b16 {%0,%1,%2,%3}, [%4];"
                 : "=r"(r[0]), "=r"(r[1]), "=r"(r[2]), "=r"(r[3]) : "r"(addr));
}
__device__ __forceinline__ void mma16816(float* c, const uint32_t* a, const uint32_t* b) {
    asm volatile(
        "mma.sync.aligned.m16n8k16.row.col.f32.f16.f16.f32 "
        "{%0,%1,%2,%3}, {%4,%5,%6,%7}, {%8,%9}, {%0,%1,%2,%3};"
        : "+f"(c[0]), "+f"(c[1]), "+f"(c[2]), "+f"(c[3])
        : "r"(a[0]), "r"(a[1]), "r"(a[2]), "r"(a[3]), "r"(b[0]), "r"(b[1]));
}
__device__ __forceinline__ uint32_t smem_addr(const void* p) {
    uint32_t a;
    asm("{ .reg .u64 t; cvta.to.shared.u64 t, %1; cvt.u32.u64 %0, t; }" : "=r"(a) : "l"(p));
    return a;
}

#define STAGE_GU 49152    // A, Bg, Bu x 16KB
#define STAGE_DN 49152    // A 16KB + B 32KB
#define WAIT_G1() asm volatile("cp.async.wait_group 1;" ::: "memory")
#define WAIT_G0() asm volatile("cp.async.wait_group 0;" ::: "memory")

// ---------------------------------------------------------------------------
// Fused gate+up GEMM (fp16): act = silu(X@gate_w) * (X@up_w) -> fp16
// 512 threads = 16 warps (4m x 4n), warp tile 32x32 per GEMM. BK=64.
// 3-stage cp.async pipeline.
// ---------------------------------------------------------------------------
__global__ __launch_bounds__(512, 1) void gemm_gu(
    const __half* __restrict__ A,
    const __half* __restrict__ Bg, const __half* __restrict__ Bu,
    __half* __restrict__ O)
{
    extern __shared__ __align__(128) char dynsmem[];
    const int K  = HID;
    const int NN = INTER;
    const int tid = threadIdx.x, lane = tid & 31, wid = tid >> 5;
    const int wm = wid & 3, wn = wid >> 2;
    const int rowA = blockIdx.y * 128, rowB = blockIdx.x * 128;
    const uint32_t sbase = smem_addr(dynsmem);

    auto load_stage = [&](uint32_t db0, int kk) {
        #pragma unroll
        for (int i = 0; i < 6; i++) {
            int ch = i * 512 + tid;
            int t = ch >> 10, local = ch & 1023;
            int r = local >> 3, c = local & 7;
            const __half* P = (t == 0 ? A : t == 1 ? Bg : Bu)
                              + (size_t)((t == 0 ? rowA : rowB) + r) * K + kk;
            uint32_t off = ((uint32_t)(r * 128 + c * 16)) ^ (uint32_t)((r & 7) << 4);
            cpasync16(db0 + t * 16384 + off, (const char*)P + c * 16);
        }
        asm volatile("cp.async.commit_group;" ::: "memory");
    };

    uint32_t rawA[2], xA[2];
    #pragma unroll
    for (int mi = 0; mi < 2; mi++) {
        uint32_t r = (uint32_t)(wm * 32 + mi * 16 + (lane & 15));
        rawA[mi] = r * 128 + ((lane >> 4) * 16);
        xA[mi]   = (rawA[mi] >> 3) & 0x70;
    }
    uint32_t rawB[2], xB[2];
    #pragma unroll
    for (int g = 0; g < 2; g++) {
        uint32_t r = (uint32_t)(wn * 32 + g * 16 + (lane & 7) + ((lane >> 4) << 3));
        rawB[g] = r * 128 + (((lane >> 3) & 1) * 16);
        xB[g]   = (rawB[g] >> 3) & 0x70;
    }

    float ag[2][4][4], au[2][4][4];
    #pragma unroll
    for (int i = 0; i < 2; i++)
        #pragma unroll
        for (int j = 0; j < 4; j++)
            #pragma unroll
            for (int q = 0; q < 4; q++) { ag[i][j][q] = 0.f; au[i][j][q] = 0.f; }

    const int NKB = K / 64;   // 32
    load_stage(sbase, 0);
    load_stage(sbase + STAGE_GU, 64);
    WAIT_G1();
    __syncthreads();

    for (int kb = 0; kb < NKB; kb++) {
        const uint32_t cur = sbase + (uint32_t)(kb % 3) * STAGE_GU;
        if (kb + 2 < NKB)
            load_stage(sbase + (uint32_t)((kb + 2) % 3) * STAGE_GU, (kb + 2) * 64);

        #pragma unroll
        for (int ks = 0; ks < 4; ks++) {
            uint32_t aF[2][4], bG[2][4], bU[2][4];
            #pragma unroll
            for (int mi = 0; mi < 2; mi++)
                ldsm4(aF[mi], cur + ((rawA[mi] + ks * 32) ^ xA[mi]));
            #pragma unroll
            for (int g = 0; g < 2; g++) {
                uint32_t o = (rawB[g] + ks * 32) ^ xB[g];
                ldsm4(bG[g], cur + 16384 + o);
                ldsm4(bU[g], cur + 32768 + o);
            }
            #pragma unroll
            for (int mi = 0; mi < 2; mi++)
                #pragma unroll
                for (int g = 0; g < 2; g++)
                    #pragma unroll
                    for (int hh = 0; hh < 2; hh++) {
                        mma16816(ag[mi][g * 2 + hh], aF[mi], &bG[g][hh * 2]);
                        mma16816(au[mi][g * 2 + hh], aF[mi], &bU[g][hh * 2]);
                    }
        }
        if (kb + 1 < NKB) {
            if (kb + 2 < NKB) WAIT_G1(); else WAIT_G0();
        }
        __syncthreads();
    }

    // epilogue: act = silu(gate)*up -> fp16
    const int rOff = lane >> 2, cOff = (lane & 3) * 2;
    #pragma unroll
    for (int mi = 0; mi < 2; mi++)
        #pragma unroll
        for (int nf = 0; nf < 4; nf++)
            #pragma unroll
            for (int hh = 0; hh < 2; hh++) {
                const int rr = rowA + wm * 32 + mi * 16 + rOff + hh * 8;
                const int cc = rowB + wn * 32 + nf * 8 + cOff;
                const size_t pos = (size_t)rr * NN + cc;
                float g0 = ag[mi][nf][hh * 2 + 0], g1 = ag[mi][nf][hh * 2 + 1];
                float u0 = au[mi][nf][hh * 2 + 0], u1 = au[mi][nf][hh * 2 + 1];
                float y0 = (g0 / (1.f + expf(-g0))) * u0;
                float y1 = (g1 / (1.f + expf(-g1))) * u1;
                *(__half2*)(O + pos) =
                    __halves2half2(__float2half_rn(y0), __float2half_rn(y1));
            }
}

// ---------------------------------------------------------------------------
// Down GEMM (fp16): out += act @ down_w
// CTA tile 128(M) x 256(N), BK=64. 512 threads = 16 warps (4m x 4n),
// warp tile 32x64. 3-stage pipeline.
// ---------------------------------------------------------------------------
__global__ __launch_bounds__(512, 1) void gemm_dn(
    const __half* __restrict__ A,
    const __half* __restrict__ B, float* __restrict__ C)
{
    extern __shared__ __align__(128) char dynsmem[];
    const int K  = INTER;
    const int NN = HID;
    const int tid = threadIdx.x, lane = tid & 31, wid = tid >> 5;
    const int wm = wid & 3, wn = wid >> 2;
    const int rowA = blockIdx.y * 128, rowB = blockIdx.x * 256;
    const uint32_t sbase = smem_addr(dynsmem);

    auto load_stage = [&](uint32_t db0, int kk) {
        #pragma unroll
        for (int i = 0; i < 6; i++) {
            int ch = i * 512 + tid;
            const __half* P;
            uint32_t dst;
            if (ch < 1024) {
                int r = ch >> 3, c = ch & 7;
                P = A + (size_t)(rowA + r) * K + kk + c * 8;
                uint32_t off = ((uint32_t)(r * 128 + c * 16)) ^ (uint32_t)((r & 7) << 4);
                dst = db0 + off;
            } else {
                int local = ch - 1024;
                int r = local >> 3, c = local & 7;
                P = B + (size_t)(rowB + r) * K + kk + c * 8;
                uint32_t off = ((uint32_t)(r * 128 + c * 16)) ^ (uint32_t)((r & 7) << 4);
                dst = db0 + 16384 + off;
            }
            cpasync16(dst, P);
        }
        asm volatile("cp.async.commit_group;" ::: "memory");
    };

    uint32_t rawA[2], xA[2];
    #pragma unroll
    for (int mi = 0; mi < 2; mi++) {
        uint32_t r = (uint32_t)(wm * 32 + mi * 16 + (lane & 15));
        rawA[mi] = r * 128 + ((lane >> 4) * 16);
        xA[mi]   = (rawA[mi] >> 3) & 0x70;
    }
    uint32_t rawB[4], xB[4];
    #pragma unroll
    for (int g = 0; g < 4; g++) {
        uint32_t r = (uint32_t)(wn * 64 + g * 16 + (lane & 7) + ((lane >> 4) << 3));
        rawB[g] = r * 128 + (((lane >> 3) & 1) * 16);
        xB[g]   = (rawB[g] >> 3) & 0x70;
    }

    float acc[2][8][4];
    #pragma unroll
    for (int i = 0; i < 2; i++)
        #pragma unroll
        for (int j = 0; j < 8; j++)
            #pragma unroll
            for (int q = 0; q < 4; q++) acc[i][j][q] = 0.f;

    const int NKB = K / 64;   // 128
    load_stage(sbase, 0);
    load_stage(sbase + STAGE_DN, 64);
    WAIT_G1();
    __syncthreads();

    for (int kb = 0; kb < NKB; kb++) {
        const uint32_t cur = sbase + (uint32_t)(kb % 3) * STAGE_DN;
        if (kb + 2 < NKB)
            load_stage(sbase + (uint32_t)((kb + 2) % 3) * STAGE_DN, (kb + 2) * 64);

        #pragma unroll
        for (int ks = 0; ks < 4; ks++) {
            uint32_t aH[2][4], bR[4][4];
            #pragma unroll
            for (int mi = 0; mi < 2; mi++)
                ldsm4(aH[mi], cur + ((rawA[mi] + ks * 32) ^ xA[mi]));
            #pragma unroll
            for (int g = 0; g < 4; g++)
                ldsm4(bR[g], cur + 16384 + ((rawB[g] + ks * 32) ^ xB[g]));
            #pragma unroll
            for (int mi = 0; mi < 2; mi++)
                #pragma unroll
                for (int g = 0; g < 4; g++)
                    #pragma unroll
                    for (int hh = 0; hh < 2; hh++)
                        mma16816(acc[mi][g * 2 + hh], aH[mi], &bR[g][hh * 2]);
        }
        if (kb + 1 < NKB) {
            if (kb + 2 < NKB) WAIT_G1(); else WAIT_G0();
        }
        __syncthreads();
    }

    // epilogue: out += v
    const int rOff = lane >> 2, cOff = (lane & 3) * 2;
    #pragma unroll
    for (int mi = 0; mi < 2; mi++)
        #pragma unroll
        for (int nf = 0; nf < 8; nf++)
            #pragma unroll
            for (int hh = 0; hh < 2; hh++) {
                const int rr = rowA + wm * 32 + mi * 16 + rOff + hh * 8;
                const int cc = rowB + wn * 64 + nf * 8 + cOff;
                const size_t pos = (size_t)rr * NN + cc;
                float2 o = *(const float2*)(C + pos);
                o.x += acc[mi][nf][hh * 2 + 0];
                o.y += acc[mi][nf][hh * 2 + 1];
                *(float2*)(C + pos) = o;
            }
}

// ---------------------------------------------------------------------------
// Conversions
// ---------------------------------------------------------------------------
__global__ void conv_x(const float* __restrict__ in, __half* __restrict__ o, size_t n4)
{
    size_t i = (size_t)blockIdx.x * blockDim.x + threadIdx.x;
    if (i >= n4) return;
    float4 v = *(const float4*)(in + i * 4);
    *(__half2*)(o + i * 4)     = __halves2half2(__float2half_rn(v.x), __float2half_rn(v.y));
    *(__half2*)(o + i * 4 + 2) = __halves2half2(__float2half_rn(v.z), __float2half_rn(v.w));
}

__global__ void tconv_h(const float* __restrict__ in, __half* __restrict__ o,
                        int R, int C)
{
    __shared__ float t[32][33];
    const int c0 = blockIdx.x * 32, r0 = blockIdx.y * 32;
    const int tx = threadIdx.x, ty = threadIdx.y;
    #pragma unroll
    for (int i = 0; i < 4; i++)
        t[ty + i * 8][tx] = in[(size_t)(r0 + ty + i * 8) * C + c0 + tx];
    __syncthreads();
    #pragma unroll
    for (int i = 0; i < 4; i++)
        o[(size_t)(c0 + ty + i * 8) * R + r0 + tx] = __float2half_rn(t[tx][ty + i * 8]);
}

// ---------------------------------------------------------------------------
// f32x2 SGEMM for the Q projection (fp32 exact — routing is rank-sensitive)
// ---------------------------------------------------------------------------
__device__ __forceinline__ unsigned long long pack_dup(float a) {
    unsigned long long r;
    asm("mov.b64 %0, {%1, %1};" : "=l"(r) : "f"(a));
    return r;
}
__device__ __forceinline__ void ffma2(unsigned long long& d, unsigned long long a,
                                      unsigned long long b) {
    asm("fma.rn.f32x2 %0, %1, %2, %0;" : "+l"(d) : "l"(a), "l"(b));
}
__device__ __forceinline__ float2 unpack2(unsigned long long v) {
    float2 f;
    asm("mov.b64 {%0, %1}, %2;" : "=f"(f.x), "=f"(f.y) : "l"(v));
    return f;
}

__global__ __launch_bounds__(256, 2) void sgemm_q(
    const int M, const int N, const int K,
    const float* __restrict__ A, const float* __restrict__ B, float* __restrict__ C)
{
    constexpr int BK = 8;
    __shared__ __align__(16) float As[2][BK][128];
    __shared__ __align__(16) float Bs[2][BK][128];
    const int tid = threadIdx.x;
    const int tRow = tid >> 4, tCol = tid & 15;
    const int bRow = blockIdx.y, bCol = blockIdx.x;
    const int aRow = tid >> 1, aCol = (tid & 1) * 4;
    const int bRowi = tid >> 5, bColi = (tid & 31) * 4;

    const float* Ag = A + (size_t)(bRow * 128 + aRow) * K + aCol;
    const float* Bg = B + (size_t)bRowi * N + (size_t)bCol * 128 + bColi;

    unsigned long long acc[8][4];
    #pragma unroll
    for (int i = 0; i < 8; i++)
        #pragma unroll
        for (int j = 0; j < 4; j++) acc[i][j] = 0ull;

    {
        float4 a0 = *(const float4*)Ag;
        unsigned bdst = (unsigned)__cvta_generic_to_shared(&Bs[0][bRowi][bColi]);
        asm volatile("cp.async.cg.shared.global [%0], [%1], 16;" :: "r"(bdst), "l"(Bg));
        asm volatile("cp.async.commit_group;");
        As[0][aCol + 0][aRow] = a0.x; As[0][aCol + 1][aRow] = a0.y;
        As[0][aCol + 2][aRow] = a0.z; As[0][aCol + 3][aRow] = a0.w;
        asm volatile("cp.async.wait_group 0;");
    }
    __syncthreads();

    const int NKB = K / BK;
    for (int kb = 0; kb < NKB; kb++) {
        const int buf = kb & 1;
        float4 an;
        if (kb + 1 < NKB) {
            an = *(const float4*)(Ag + (size_t)(kb + 1) * BK);
            unsigned bdst = (unsigned)__cvta_generic_to_shared(&Bs[buf ^ 1][bRowi][bColi]);
            asm volatile("cp.async.cg.shared.global [%0], [%1], 16;"
                         :: "r"(bdst), "l"(Bg + (size_t)(kb + 1) * BK * N));
            asm volatile("cp.async.commit_group;");
        }
        #pragma unroll
        for (int k = 0; k < BK; k++) {
            ulonglong2 n01 = *(const ulonglong2*)(&Bs[buf][k][tCol * 8]);
            ulonglong2 n23 = *(const ulonglong2*)(&Bs[buf][k][tCol * 8 + 4]);
            float4 m0 = *(const float4*)(&As[buf][k][tRow * 8]);
            float4 m1 = *(const float4*)(&As[buf][k][tRow * 8 + 4]);
            float mr[8] = {m0.x, m0.y, m0.z, m0.w, m1.x, m1.y, m1.z, m1.w};
            #pragma unroll
            for (int i = 0; i < 8; i++) {
                unsigned long long mm = pack_dup(mr[i]);
                ffma2(acc[i][0], mm, n01.x);
                ffma2(acc[i][1], mm, n01.y);
                ffma2(acc[i][2], mm, n23.x);
                ffma2(acc[i][3], mm, n23.y);
            }
        }
        if (kb + 1 < NKB) {
            As[buf ^ 1][aCol + 0][aRow] = an.x; As[buf ^ 1][aCol + 1][aRow] = an.y;
            As[buf ^ 1][aCol + 2][aRow] = an.z; As[buf ^ 1][aCol + 3][aRow] = an.w;
            asm volatile("cp.async.wait_group 0;");
        }
        __syncthreads();
    }

    float* Cb = C + (size_t)bRow * 128 * N + (size_t)bCol * 128;
    #pragma unroll
    for (int i = 0; i < 8; i++) {
        size_t rowOff = (size_t)(tRow * 8 + i) * N + tCol * 8;
        #pragma unroll
        for (int j2 = 0; j2 < 4; j2++) {
            float2 p = unpack2(acc[i][j2]);
            *(float2*)(Cb + rowOff + 2 * j2) = p;
        }
    }
}

// ---------------------------------------------------------------------------
// Product-key routing + two-level top-k
// ---------------------------------------------------------------------------
__global__ void routing_topk_kernel(
    const float* __restrict__ Q, const float* __restrict__ keys,
    float* __restrict__ out_scores, int* __restrict__ out_idx)
{
    const int j = blockIdx.x;
    const int t = threadIdx.x;
    __shared__ float q0[64], q1[64];
    __shared__ float r0[64], r1[64];
    __shared__ float cs[64];
    __shared__ int   ci[64];

    const int half = j & 1;
    const int tokA = (j >> 1);
    const int tokB = 4096 + (j >> 1);
    q0[t] = Q[tokA * RET + half * 64 + t];
    q1[t] = Q[tokB * RET + half * 64 + t];
    __syncthreads();

    float s0 = 0.f, s1 = 0.f;
    #pragma unroll
    for (int d = 0; d < 64; d++) {
        s0 += q0[d] * keys[d * 64 + t];
        s1 += q1[d] * keys[4096 + d * 64 + t];
    }
    r0[t] = s0;
    r1[t] = s1;
    __syncthreads();

    if (t == 0) {
        float v0[TOPK], v1[TOPK];
        int   i0[TOPK], i1[TOPK];
        unsigned long long u0 = 0ull, u1 = 0ull;
        for (int p = 0; p < TOPK; p++) {
            float best = -INFINITY; int bi = 0;
            for (int k = 0; k < 64; k++)
                if (!((u0 >> k) & 1ull) && r0[k] > best) { best = r0[k]; bi = k; }
            v0[p] = best; i0[p] = bi; u0 |= 1ull << bi;
            best = -INFINITY; bi = 0;
            for (int k = 0; k < 64; k++)
                if (!((u1 >> k) & 1ull) && r1[k] > best) { best = r1[k]; bi = k; }
            v1[p] = best; i1[p] = bi; u1 |= 1ull << bi;
        }
        for (int a = 0; a < TOPK; a++)
            for (int b = 0; b < TOPK; b++) {
                cs[a * TOPK + b] = v0[a] + v1[b];
                ci[a * TOPK + b] = i0[a] * NKEY + i1[b];
            }
        unsigned long long uc = 0ull;
        for (int p = 0; p < TOPK; p++) {
            float best = -INFINITY; int bi = 0;
            for (int q = 0; q < 64; q++)
                if (!((uc >> q) & 1ull) && cs[q] > best) { best = cs[q]; bi = q; }
            out_scores[j * TOPK + p] = best;
            out_idx[j * TOPK + p]    = ci[bi];
            uc |= 1ull << bi;
        }
    }
}

// ---------------------------------------------------------------------------
// Expert branch
// ---------------------------------------------------------------------------
__global__ __launch_bounds__(256) void experts_kernel(
    const float* __restrict__ X, const float* __restrict__ down_e,
    const float* __restrict__ up_e, const float* __restrict__ scores,
    const int* __restrict__ idx, float* __restrict__ out)
{
    const int j = blockIdx.x;
    const int tid = threadIdx.x;
    const int wid = tid >> 5;
    const int lane = tid & 31;

    __shared__ float xs[HID];
    __shared__ float ew[TOPK];
    __shared__ float w[TOPK];

    for (int h4 = tid; h4 < HID / 4; h4 += 256)
        *(float4*)(&xs[h4 * 4]) = *(const float4*)(X + (size_t)j * HID + h4 * 4);
    __syncthreads();

    {
        const int e = idx[j * TOPK + wid];
        const float* de = down_e + (size_t)e * HID;
        float s = 0.f;
        for (int h = lane * 4; h < HID; h += 32 * 4) {
            float4 d = *(const float4*)(de + h);
            s += xs[h] * d.x + xs[h+1] * d.y + xs[h+2] * d.z + xs[h+3] * d.w;
        }
        #pragma unroll
        for (int o = 16; o; o >>= 1) s += __shfl_xor_sync(0xffffffffu, s, o);
        if (lane == 0) ew[wid] = s;
    }
    __syncthreads();

    if (tid == 0) {
        float sc[TOPK], m = -INFINITY;
        #pragma unroll
        for (int k = 0; k < TOPK; k++) { sc[k] = scores[j * TOPK + k]; m = fmaxf(m, sc[k]); }
        float den = 0.f;
        #pragma unroll
        for (int k = 0; k < TOPK; k++) { sc[k] = expf(sc[k] - m); den += sc[k]; }
        #pragma unroll
        for (int k = 0; k < TOPK; k++) {
            float e_ = ew[k];
            w[k] = (e_ / (1.f + expf(-e_))) * sc[k] / den;
        }
    }
    __syncthreads();

    int   eidx[TOPK];
    float wk[TOPK];
    #pragma unroll
    for (int k = 0; k < TOPK; k++) { eidx[k] = idx[j * TOPK + k]; wk[k] = w[k]; }

    for (int h = tid * 4; h < HID; h += 256 * 4) {
        float4 acc = make_float4(0.f, 0.f, 0.f, 0.f);
        #pragma unroll
        for (int k = 0; k < TOPK; k++) {
            float4 u = *(const float4*)(up_e + (size_t)eidx[k] * HID + h);
            acc.x += wk[k] * u.x; acc.y += wk[k] * u.y;
            acc.z += wk[k] * u.z; acc.w += wk[k] * u.w;
        }
        *(float4*)(out + (size_t)j * HID + h) = acc;
    }
}

// ---------------------------------------------------------------------------
// Launch: fork a second stream for the independent routing/experts branch.
//   Stream A (caller's): conv_x -> tconv gw -> tconv uw -> gemm_gu -> [join] -> gemm_dn
//   Stream B:            sgemm_q -> routing -> experts(out) -> tconv dw
// ---------------------------------------------------------------------------
extern "C" void kernel_launch(void* const* d_in, const int* in_sizes, int n_in,
                              void* d_out, int out_size)
{
    const float* x      = (const float*)d_in[0];
    const float* wq     = (const float*)d_in[1];
    const float* keys   = (const float*)d_in[2];
    const float* down_e = (const float*)d_in[3];
    const float* up_e   = (const float*)d_in[4];
    const float* gate_w = (const float*)d_in[5];
    const float* up_w   = (const float*)d_in[6];
    const float* down_w = (const float*)d_in[7];
    float* out = (float*)d_out;

    float *q_ptr, *scr_ptr;
    int   *idx_ptr;
    __half *xh, *gw, *uw, *dw, *act;
    cudaGetSymbolAddress((void**)&q_ptr,   g_q);
    cudaGetSymbolAddress((void**)&scr_ptr, g_scores);
    cudaGetSymbolAddress((void**)&idx_ptr, g_idx);
    cudaGetSymbolAddress((void**)&xh,  g_xh);
    cudaGetSymbolAddress((void**)&gw,  g_gw);
    cudaGetSymbolAddress((void**)&uw,  g_uw);
    cudaGetSymbolAddress((void**)&dw,  g_dw);
    cudaGetSymbolAddress((void**)&act, g_act);

    cudaFuncSetAttribute(gemm_gu, cudaFuncAttributeMaxDynamicSharedMemorySize, 3 * STAGE_GU);
    cudaFuncSetAttribute(gemm_dn, cudaFuncAttributeMaxDynamicSharedMemorySize, 3 * STAGE_DN);

    static cudaStream_t sB = nullptr;
    static cudaEvent_t evF = nullptr, evJ = nullptr;
    if (sB == nullptr) {
        cudaStreamCreateWithFlags(&sB, cudaStreamNonBlocking);
        cudaEventCreateWithFlags(&evF, cudaEventDisableTiming);
        cudaEventCreateWithFlags(&evJ, cudaEventDisableTiming);
    }

    // fork
    cudaEventRecord(evF, 0);
    cudaStreamWaitEvent(sB, evF, 0);

    // ---- stream B: routing branch + dw conversion ----
    sgemm_q<<<dim3(RET / 128, NTOK / 128), 256, 0, sB>>>(NTOK, RET, HID, x, wq, q_ptr);
    routing_topk_kernel<<<NTOK, 64, 0, sB>>>(q_ptr, keys, scr_ptr, idx_ptr);
    experts_kernel<<<NTOK, 256, 0, sB>>>(x, down_e, up_e, scr_ptr, idx_ptr, out);
    tconv_h<<<dim3(HID / 32, INTER / 32), dim3(32, 8), 0, sB>>>(down_w, dw, INTER, HID);
    cudaEventRecord(evJ, sB);

    // ---- stream A: dense MLP path ----
    conv_x<<<(NTOK * HID / 4 + 255) / 256, 256>>>(x, xh, (size_t)NTOK * HID / 4);
    tconv_h<<<dim3(INTER / 32, HID / 32), dim3(32, 8)>>>(gate_w, gw, HID, INTER);
    tconv_h<<<dim3(INTER / 32, HID / 32), dim3(32, 8)>>>(up_w,   uw, HID, INTER);
    gemm_gu<<<dim3(INTER / 128, NTOK / 128), 512, 3 * STAGE_GU>>>(xh, gw, uw, act);

    // join: dn needs act (A), dw (B) and experts' out (B)
    cudaStreamWaitEvent(0, evJ, 0);
    gemm_dn<<<dim3(HID / 256, NTOK / 128), 512, 3 * STAGE_DN>>>(act, dw, out);
}